// round 5
// baseline (speedup 1.0000x reference)
#include <cuda_runtime.h>
#include <cuda_bf16.h>
#include <math.h>
#include <stdint.h>

#define SEQ 1024
#define DM  1024
#define NH  16
#define HD  64
#define NB  2
#define GK  1024

// Scratch (device globals: no allocations allowed)
__device__ float g_qproj[NB*SEQ*DM];
__device__ float g_vproj[NB*SEQ*DM];
__device__ float g_x[NB*SEQ*DM];
__device__ float g_posT[HD*2*SEQ + 16];   // [64][2048] transposed pos, +pad
__device__ float g_vbrel[NH*2*SEQ + 16];  // [16][2048] v_bias . pos, +pad

// ---------------------------------------------------------------------------
// helpers (generic sm_80+ PTX only: ldmatrix + mma.sync — NO tcgen05!)
// ---------------------------------------------------------------------------
__device__ __forceinline__ uint32_t smem_u32(const void* p) {
    uint32_t a;
    asm("{ .reg .u64 t; cvta.to.shared.u64 t, %1; cvt.u32.u64 %0, t; }" : "=r"(a) : "l"(p));
    return a;
}

__device__ __forceinline__ void ldsm_x4(uint32_t (&r)[4], uint32_t addr) {
    asm volatile("ldmatrix.sync.aligned.m8n8.x4.shared.b16 {%0,%1,%2,%3}, [%4];"
        : "=r"(r[0]), "=r"(r[1]), "=r"(r[2]), "=r"(r[3]) : "r"(addr));
}

__device__ __forceinline__ void mma_bf16(float (&d)[4], const uint32_t (&a)[4],
                                         uint32_t b0, uint32_t b1) {
    asm volatile("mma.sync.aligned.m16n8k16.row.col.f32.bf16.bf16.f32 "
        "{%0,%1,%2,%3}, {%4,%5,%6,%7}, {%8,%9}, {%0,%1,%2,%3};"
        : "+f"(d[0]), "+f"(d[1]), "+f"(d[2]), "+f"(d[3])
        : "r"(a[0]), "r"(a[1]), "r"(a[2]), "r"(a[3]), "r"(b0), "r"(b1));
}

// split fp32 float4 -> bf16 hi + bf16 lo, store 8B each to smem
__device__ __forceinline__ void split_sts(float4 v, char* hi, char* lo, int byteoff) {
    __nv_bfloat162 h01 = __floats2bfloat162_rn(v.x, v.y);
    __nv_bfloat162 h23 = __floats2bfloat162_rn(v.z, v.w);
    float2 f01 = __bfloat1622float2(h01);
    float2 f23 = __bfloat1622float2(h23);
    __nv_bfloat162 l01 = __floats2bfloat162_rn(v.x - f01.x, v.y - f01.y);
    __nv_bfloat162 l23 = __floats2bfloat162_rn(v.z - f23.x, v.w - f23.y);
    *(uint2*)(hi + byteoff) = make_uint2(*(uint32_t*)&h01, *(uint32_t*)&h23);
    *(uint2*)(lo + byteoff) = make_uint2(*(uint32_t*)&l01, *(uint32_t*)&l23);
}

// ---------------------------------------------------------------------------
// Positional embeddings, stored transposed: g_posT[d][l] = pos[l][d]
// ---------------------------------------------------------------------------
__global__ void pos_kernel() {
    int l = blockIdx.x * blockDim.x + threadIdx.x;
    if (l >= 2*SEQ) return;
    float p = (float)(l - SEQ);
    const double negc = -log(10000.0) / 31.0;   // half-1 = 31
    for (int j = 0; j < 32; j++) {
        float div = (float)exp((double)j * negc);
        float ang = p * div;                    // fp32 angle (matches jnp fp32)
        double a = (double)ang;
        g_posT[j*2048 + l]        = (float)sin(a);
        g_posT[(j+32)*2048 + l]   = (float)cos(a);
    }
}

// vbrel[h][l] = sum_d v_bias[h][d] * pos[l][d]
__global__ void vbrel_kernel(const float* __restrict__ vb) {
    int l = blockIdx.x * blockDim.x + threadIdx.x;
    if (l >= 2*SEQ) return;
    for (int h = 0; h < NH; h++) {
        float s = 0.f;
        #pragma unroll 8
        for (int d = 0; d < HD; d++)
            s = fmaf(vb[h*HD + d], g_posT[d*2048 + l], s);
        g_vbrel[h*2048 + l] = s;
    }
}

// ---------------------------------------------------------------------------
// bf16x2-split tensor-core GEMM (NT): C[m][n] = sum_k A[m][k]*B[n][k] + bias[n]
// 128x128 CTA tile, 8 warps (2x4) of 64x32, K-step 32, double-buffered smem.
// smem tiles: [128 rows][stride 40 bf16] = 10240 B each (80B rows: 8 distinct
// banks per ldmatrix phase). Per buf: Ahi Alo Bhi Blo = 40960 B; x2 = 80 KB
// dynamic smem.
// ---------------------------------------------------------------------------
#define TSTRIDE 40
#define TILE_B  (128 * TSTRIDE * 2)      // 10240
#define BUF_B   (4 * TILE_B)             // 40960
#define HG_SMEM (2 * BUF_B)              // 81920

__global__ __launch_bounds__(256) void hgemm_nt_bias(
    const float* __restrict__ A, const float* __restrict__ B,
    const float* __restrict__ bias, float* __restrict__ C,
    int M, int N)
{
    extern __shared__ __align__(16) char smraw[];
    const int tid = threadIdx.x, lane = tid & 31, wid = tid >> 5;
    const int wm = wid & 1, wn = wid >> 1;
    const int row0 = blockIdx.y * 128, col0 = blockIdx.x * 128;

    // loader: thread handles row lr, 16 floats starting at col lc of each k32 chunk
    const int lr = tid >> 1, lc = (tid & 1) * 16;
    const float* Ap = A + (size_t)(row0 + lr) * GK + lc;
    const float* Bp = B + (size_t)(col0 + lr) * GK + lc;

    const uint32_t sbase = smem_u32(smraw);

    // ldmatrix lane addressing (x4, non-trans, canonical 16x16 tiles)
    const int a_r = lane & 15;              // row within 16-row group
    const int a_c = (lane >> 4) << 3;       // k-offset 0 or 8
    const int b_r = (lane & 7) + ((lane & 16) >> 1);  // n within 16
    const int b_c = lane & 8;               // k-offset 0 or 8

    float acc[4][4][4];
    #pragma unroll
    for (int i = 0; i < 4; i++)
        #pragma unroll
        for (int j = 0; j < 4; j++)
            #pragma unroll
            for (int c = 0; c < 4; c++) acc[i][j][c] = 0.f;

    float4 av[4], bv[4];
    // prologue: load + stage k-chunk 0 into buf 0
    #pragma unroll
    for (int q = 0; q < 4; q++) {
        av[q] = *(const float4*)(Ap + 4*q);
        bv[q] = *(const float4*)(Bp + 4*q);
    }
    {
        char* hA = smraw;
        const int bo = (lr*TSTRIDE + lc) * 2;
        #pragma unroll
        for (int q = 0; q < 4; q++) {
            split_sts(av[q], hA,            hA + TILE_B,   bo + 8*q);
            split_sts(bv[q], hA + 2*TILE_B, hA + 3*TILE_B, bo + 8*q);
        }
    }
    __syncthreads();

    for (int kt = 0; kt < 32; kt++) {
        // prefetch next chunk from global
        if (kt < 31) {
            #pragma unroll
            for (int q = 0; q < 4; q++) {
                av[q] = *(const float4*)(Ap + (kt+1)*32 + 4*q);
                bv[q] = *(const float4*)(Bp + (kt+1)*32 + 4*q);
            }
        }

        // compute on buffer kt&1
        const uint32_t base = sbase + (kt & 1) * BUF_B;
        const uint32_t aHi = base,              aLo = base + TILE_B;
        const uint32_t bHi = base + 2*TILE_B,   bLo = base + 3*TILE_B;

        #pragma unroll
        for (int kk = 0; kk < 2; kk++) {
            const int koff = kk * 16;
            uint32_t ah[4][4], al[4][4];
            #pragma unroll
            for (int i = 0; i < 4; i++) {
                const uint32_t off = (uint32_t)(((wm*64 + i*16 + a_r)*TSTRIDE + koff + a_c) * 2);
                ldsm_x4(ah[i], aHi + off);
                ldsm_x4(al[i], aLo + off);
            }
            uint32_t bh[2][4], bl[2][4];
            #pragma unroll
            for (int p = 0; p < 2; p++) {
                const uint32_t off = (uint32_t)(((wn*32 + p*16 + b_r)*TSTRIDE + koff + b_c) * 2);
                ldsm_x4(bh[p], bHi + off);
                ldsm_x4(bl[p], bLo + off);
            }
            #pragma unroll
            for (int i = 0; i < 4; i++)
                #pragma unroll
                for (int j = 0; j < 4; j++) {
                    const int p = j >> 1, s = (j & 1) * 2;
                    mma_bf16(acc[i][j], ah[i], bh[p][s], bh[p][s+1]);  // hi*hi
                    mma_bf16(acc[i][j], ah[i], bl[p][s], bl[p][s+1]);  // hi*lo
                    mma_bf16(acc[i][j], al[i], bh[p][s], bh[p][s+1]);  // lo*hi
                }
        }

        // stage next chunk into buffer (kt+1)&1
        if (kt < 31) {
            char* hA = smraw + ((kt+1) & 1) * BUF_B;
            const int bo = (lr*TSTRIDE + lc) * 2;
            #pragma unroll
            for (int q = 0; q < 4; q++) {
                split_sts(av[q], hA,            hA + TILE_B,   bo + 8*q);
                split_sts(bv[q], hA + 2*TILE_B, hA + 3*TILE_B, bo + 8*q);
            }
            __syncthreads();
        }
    }

    // epilogue: mma C layout -> global, add bias
    const int grp = lane >> 2, qid = lane & 3;
    #pragma unroll
    for (int j = 0; j < 4; j++) {
        const int col = col0 + wn*32 + j*8 + qid*2;
        const float2 bj = *(const float2*)(bias + col);
        #pragma unroll
        for (int i = 0; i < 4; i++) {
            const int row = row0 + wm*64 + i*16 + grp;
            float2 o0 = make_float2(acc[i][j][0] + bj.x, acc[i][j][1] + bj.y);
            float2 o1 = make_float2(acc[i][j][2] + bj.x, acc[i][j][3] + bj.y);
            *(float2*)(C + (size_t)row * N + col)       = o0;
            *(float2*)(C + (size_t)(row + 8) * N + col) = o1;
        }
    }
}

// ---------------------------------------------------------------------------
// Fused attention (fp32, proven round-1 version): per CTA a 128-query tile.
// ---------------------------------------------------------------------------
#define ATT_SMEM_FLOATS 50944
#define ATT_SMEM_BYTES  (ATT_SMEM_FLOATS * 4)

__global__ __launch_bounds__(256, 1) void attn_kernel(const float* __restrict__ key)
{
    extern __shared__ float smf[];
    float* Qs  = smf;
    float* KV  = smf + 8704;
    float* Ps  = smf + 17408;
    float* Pt  = smf + 33792;
    float* vbs = smf + 50688;

    int tid = threadIdx.x;
    int tx = tid & 15, ty = tid >> 4;
    int q0 = blockIdx.x * 128;
    int h  = blockIdx.y;
    int b  = blockIdx.z;

    const float* qbase = g_qproj + ((size_t)(b*SEQ + q0))*DM + h*HD;
    #pragma unroll
    for (int r = 0; r < 8; r++) {
        int it = tid + r*256;
        int u = it >> 4, dq = it & 15;
        float4 v = *(const float4*)(qbase + (size_t)u*DM + 4*dq);
        *(float4*)&Qs[u*68 + 4*dq] = v;
    }

    float O[8][4];
    float m_run[8], l_run[8];
    #pragma unroll
    for (int i = 0; i < 8; i++) {
        m_run[i] = -INFINITY; l_run[i] = 0.f;
        #pragma unroll
        for (int c = 0; c < 4; c++) O[i][c] = 0.f;
    }

    int u0 = ty*8, w0 = tx*8;
    int mbase = 127 + w0 - u0;

    const float* kbase = key     + ((size_t)(b*SEQ))*DM + h*HD;
    const float* vbase = g_vproj + ((size_t)(b*SEQ))*DM + h*HD;

    for (int kt = 0; kt < 8; kt++) {
        int k0 = kt*128;
        int lmin = SEQ + k0 - q0 - 127;
        __syncthreads();

        #pragma unroll
        for (int r = 0; r < 8; r++) {
            int it = tid + r*256;
            int w = it >> 4, dq = it & 15;
            float4 v = *(const float4*)(kbase + (size_t)(k0+w)*DM + 4*dq);
            KV[(4*dq+0)*132 + w] = v.x;
            KV[(4*dq+1)*132 + w] = v.y;
            KV[(4*dq+2)*132 + w] = v.z;
            KV[(4*dq+3)*132 + w] = v.w;
        }
        for (int it = tid; it < 64*256; it += 256) {
            int d = it >> 8, m = it & 255;
            Ps[it] = g_posT[d*2048 + lmin + m];
        }
        vbs[tid] = g_vbrel[h*2048 + lmin + tid];
        __syncthreads();

        float acc[8][8];
        #pragma unroll
        for (int i = 0; i < 8; i++)
            #pragma unroll
            for (int j = 0; j < 8; j++) acc[i][j] = 0.f;

        #pragma unroll 4
        for (int d = 0; d < 64; d++) {
            float qv[8], kv[8], pv[16];
            #pragma unroll
            for (int i = 0; i < 8; i++) qv[i] = Qs[(u0+i)*68 + d];
            *(float4*)&kv[0] = *(const float4*)&KV[d*132 + w0];
            *(float4*)&kv[4] = *(const float4*)&KV[d*132 + w0 + 4];
            const float* pr = &Ps[d*256 + mbase - 7];
            *(float4*)&pv[0]  = *(const float4*)&pr[0];
            *(float4*)&pv[4]  = *(const float4*)&pr[4];
            *(float4*)&pv[8]  = *(const float4*)&pr[8];
            *(float4*)&pv[12] = *(const float4*)&pr[12];
            #pragma unroll
            for (int i = 0; i < 8; i++)
                #pragma unroll
                for (int j = 0; j < 8; j++)
                    acc[i][j] = fmaf(qv[i], kv[j] + pv[7 + j - i], acc[i][j]);
        }

        float mt[8];
        #pragma unroll
        for (int i = 0; i < 8; i++) {
            float mm = -INFINITY;
            #pragma unroll
            for (int j = 0; j < 8; j++) {
                acc[i][j] += vbs[mbase + j - i];
                mm = fmaxf(mm, acc[i][j]);
            }
            mt[i] = mm;
        }
        #pragma unroll
        for (int o = 1; o < 16; o <<= 1)
            #pragma unroll
            for (int i = 0; i < 8; i++)
                mt[i] = fmaxf(mt[i], __shfl_xor_sync(0xffffffffu, mt[i], o));

        float scl[8], ls[8];
        #pragma unroll
        for (int i = 0; i < 8; i++) {
            float mn = fmaxf(m_run[i], mt[i]);
            scl[i] = __expf(m_run[i] - mn);
            m_run[i] = mn;
            float p0 = __expf(acc[i][0]-mn), p1 = __expf(acc[i][1]-mn);
            float p2 = __expf(acc[i][2]-mn), p3 = __expf(acc[i][3]-mn);
            float p4 = __expf(acc[i][4]-mn), p5 = __expf(acc[i][5]-mn);
            float p6 = __expf(acc[i][6]-mn), p7 = __expf(acc[i][7]-mn);
            *(float4*)&Pt[(u0+i)*132 + w0]     = make_float4(p0,p1,p2,p3);
            *(float4*)&Pt[(u0+i)*132 + w0 + 4] = make_float4(p4,p5,p6,p7);
            ls[i] = ((p0+p1)+(p2+p3)) + ((p4+p5)+(p6+p7));
        }
        #pragma unroll
        for (int o = 1; o < 16; o <<= 1)
            #pragma unroll
            for (int i = 0; i < 8; i++)
                ls[i] += __shfl_xor_sync(0xffffffffu, ls[i], o);
        #pragma unroll
        for (int i = 0; i < 8; i++)
            l_run[i] = l_run[i]*scl[i] + ls[i];

        __syncthreads();
        #pragma unroll
        for (int r = 0; r < 8; r++) {
            int it = tid + r*256;
            int w = it >> 4, dq = it & 15;
            float4 v = *(const float4*)(vbase + (size_t)(k0+w)*DM + 4*dq);
            *(float4*)&KV[w*68 + 4*dq] = v;
        }
        __syncthreads();

        #pragma unroll
        for (int i = 0; i < 8; i++) {
            O[i][0] *= scl[i]; O[i][1] *= scl[i];
            O[i][2] *= scl[i]; O[i][3] *= scl[i];
        }
        #pragma unroll 4
        for (int w = 0; w < 128; w++) {
            float4 vv = *(const float4*)&KV[w*68 + 4*tx];
            #pragma unroll
            for (int i = 0; i < 8; i++) {
                float p = Pt[(u0+i)*132 + w];
                O[i][0] = fmaf(p, vv.x, O[i][0]);
                O[i][1] = fmaf(p, vv.y, O[i][1]);
                O[i][2] = fmaf(p, vv.z, O[i][2]);
                O[i][3] = fmaf(p, vv.w, O[i][3]);
            }
        }
    }

    float* xbase = g_x + ((size_t)(b*SEQ + q0))*DM + h*HD;
    #pragma unroll
    for (int i = 0; i < 8; i++) {
        float inv = 1.f / l_run[i];
        float4 o = make_float4(O[i][0]*inv, O[i][1]*inv, O[i][2]*inv, O[i][3]*inv);
        *(float4*)(xbase + (size_t)(u0+i)*DM + 4*tx) = o;
    }
}

// ---------------------------------------------------------------------------
extern "C" void kernel_launch(void* const* d_in, const int* in_sizes, int n_in,
                              void* d_out, int out_size) {
    const float* query  = (const float*)d_in[0];
    const float* key    = (const float*)d_in[1];
    const float* value  = (const float*)d_in[2];
    /* d_in[3] = mask: unused by reference */
    const float* Wq     = (const float*)d_in[4];
    const float* bq     = (const float*)d_in[5];
    const float* Wv     = (const float*)d_in[6];
    const float* bv     = (const float*)d_in[7];
    const float* Wo     = (const float*)d_in[8];
    const float* bo     = (const float*)d_in[9];
    const float* v_bias = (const float*)d_in[10];
    float* out = (float*)d_out;

    void *qp, *vp, *xp;
    cudaGetSymbolAddress(&qp, g_qproj);
    cudaGetSymbolAddress(&vp, g_vproj);
    cudaGetSymbolAddress(&xp, g_x);

    cudaFuncSetAttribute(attn_kernel,
                         cudaFuncAttributeMaxDynamicSharedMemorySize,
                         ATT_SMEM_BYTES);
    cudaFuncSetAttribute(hgemm_nt_bias,
                         cudaFuncAttributeMaxDynamicSharedMemorySize,
                         HG_SMEM);

    pos_kernel<<<8, 256>>>();
    vbrel_kernel<<<8, 256>>>(v_bias);

    dim3 ggrid(DM/128, (NB*SEQ)/128);  // (8, 16)
    hgemm_nt_bias<<<ggrid, 256, HG_SMEM>>>(query, Wq, bq, (float*)qp, NB*SEQ, DM);
    hgemm_nt_bias<<<ggrid, 256, HG_SMEM>>>(value, Wv, bv, (float*)vp, NB*SEQ, DM);

    dim3 agrid(SEQ/128, NH, NB);       // (8, 16, 2)
    attn_kernel<<<agrid, 256, ATT_SMEM_BYTES>>>(key);

    hgemm_nt_bias<<<ggrid, 256, HG_SMEM>>>((const float*)xp, Wo, bo, out, NB*SEQ, DM);
}

// round 6
// speedup vs baseline: 1.3529x; 1.3529x over previous
#include <cuda_runtime.h>
#include <cuda_bf16.h>
#include <math.h>
#include <stdint.h>

#define SEQ 1024
#define DM  1024
#define NH  16
#define HD  64
#define NB  2
#define GK  1024

__device__ float g_qproj[NB*SEQ*DM];
__device__ float g_vproj[NB*SEQ*DM];
__device__ float g_x[NB*SEQ*DM];
__device__ float g_vbrel[NH*2*SEQ + 32];
__device__ __nv_bfloat16 g_qhi[NB*NH*SEQ*HD], g_qlo[NB*NH*SEQ*HD];
__device__ __nv_bfloat16 g_khi[NB*NH*SEQ*HD], g_klo[NB*NH*SEQ*HD];
__device__ __nv_bfloat16 g_vthi[NB*NH*HD*SEQ], g_vtlo[NB*NH*HD*SEQ];
__device__ __nv_bfloat16 g_poshi[(2*SEQ+1)*HD], g_poslo[(2*SEQ+1)*HD];

__device__ __forceinline__ uint32_t smem_u32(const void* p) {
    uint32_t a;
    asm("{ .reg .u64 t; cvta.to.shared.u64 t, %1; cvt.u32.u64 %0, t; }" : "=r"(a) : "l"(p));
    return a;
}
__device__ __forceinline__ void ldsm_x4(uint32_t (&r)[4], uint32_t addr) {
    asm volatile("ldmatrix.sync.aligned.m8n8.x4.shared.b16 {%0,%1,%2,%3}, [%4];"
        : "=r"(r[0]), "=r"(r[1]), "=r"(r[2]), "=r"(r[3]) : "r"(addr));
}
__device__ __forceinline__ void mma_bf16(float (&d)[4], const uint32_t (&a)[4],
                                         uint32_t b0, uint32_t b1) {
    asm volatile("mma.sync.aligned.m16n8k16.row.col.f32.bf16.bf16.f32 "
        "{%0,%1,%2,%3}, {%4,%5,%6,%7}, {%8,%9}, {%0,%1,%2,%3};"
        : "+f"(d[0]), "+f"(d[1]), "+f"(d[2]), "+f"(d[3])
        : "r"(a[0]), "r"(a[1]), "r"(a[2]), "r"(a[3]), "r"(b0), "r"(b1));
}
__device__ __forceinline__ void split_sts(float4 v, char* hi, char* lo, int byteoff) {
    __nv_bfloat162 h01 = __floats2bfloat162_rn(v.x, v.y);
    __nv_bfloat162 h23 = __floats2bfloat162_rn(v.z, v.w);
    float2 f01 = __bfloat1622float2(h01);
    float2 f23 = __bfloat1622float2(h23);
    __nv_bfloat162 l01 = __floats2bfloat162_rn(v.x - f01.x, v.y - f01.y);
    __nv_bfloat162 l23 = __floats2bfloat162_rn(v.z - f23.x, v.w - f23.y);
    *(uint2*)(hi + byteoff) = make_uint2(*(uint32_t*)&h01, *(uint32_t*)&h23);
    *(uint2*)(lo + byteoff) = make_uint2(*(uint32_t*)&l01, *(uint32_t*)&l23);
}

// pos split (bf16 hi/lo, [l][d]) + vbrel[h][l]
__global__ void pos_kernel2(const float* __restrict__ vb) {
    int l = blockIdx.x * blockDim.x + threadIdx.x;
    if (l >= 2*SEQ) return;
    float pv[64];
    float p = (float)(l - SEQ);
    const double negc = -log(10000.0) / 31.0;
    for (int j = 0; j < 32; j++) {
        float ang = p * (float)exp((double)j * negc);
        pv[j] = (float)sin((double)ang);
        pv[j+32] = (float)cos((double)ang);
    }
    for (int d = 0; d < 64; d++) {
        __nv_bfloat16 hi = __float2bfloat16_rn(pv[d]);
        g_poshi[l*64+d] = hi;
        g_poslo[l*64+d] = __float2bfloat16_rn(pv[d] - __bfloat162float(hi));
    }
    for (int h = 0; h < NH; h++) {
        float s = 0.f;
        #pragma unroll 8
        for (int d = 0; d < HD; d++) s = fmaf(__ldg(vb + h*HD + d), pv[d], s);
        g_vbrel[h*2048 + l] = s;
    }
}

// (b,s,h*64+d) fp32 -> (b,h,s,d) bf16 hi/lo
__global__ void split_bhsd(const float* __restrict__ src,
                           __nv_bfloat16* __restrict__ hi, __nv_bfloat16* __restrict__ lo) {
    int idx = blockIdx.x * 256 + threadIdx.x;
    float4 v = ((const float4*)src)[idx];
    int c = idx & 255, s = (idx >> 8) & 1023, b = idx >> 18;
    int hh = c >> 4, dq = c & 15;
    size_t o = ((size_t)(b*NH + hh)*SEQ + s)*HD + dq*4;
    split_sts(v, (char*)(hi + o) - 0, (char*)(lo + o) - 0, 0);
}

// g_vproj (b,s,h*64+d) -> (b,h,d,s) bf16 hi/lo (smem transpose)
__global__ void vtsplit(const float* __restrict__ src,
                        __nv_bfloat16* __restrict__ hi, __nv_bfloat16* __restrict__ lo) {
    __shared__ float t[64*65];
    int w0 = (blockIdx.x & 15) * 64, bh = blockIdx.x >> 4;
    int b = bh >> 4, h = bh & 15, tid = threadIdx.x;
    #pragma unroll
    for (int it = 0; it < 4; it++) {
        int idx = tid + it*256, w = idx >> 4, dq = idx & 15;
        float4 v = *(const float4*)(src + ((size_t)(b*SEQ + w0 + w))*DM + h*HD + dq*4);
        t[w*65+dq*4+0] = v.x; t[w*65+dq*4+1] = v.y;
        t[w*65+dq*4+2] = v.z; t[w*65+dq*4+3] = v.w;
    }
    __syncthreads();
    #pragma unroll
    for (int it = 0; it < 4; it++) {
        int idx = tid + it*256, d = idx >> 4, wq = idx & 15;
        float4 v = make_float4(t[(wq*4+0)*65+d], t[(wq*4+1)*65+d],
                               t[(wq*4+2)*65+d], t[(wq*4+3)*65+d]);
        size_t o = ((size_t)bh*HD + d)*SEQ + w0 + wq*4;
        split_sts(v, (char*)(hi + o), (char*)(lo + o), 0);
    }
}

// --------- bf16x2-split GEMM (NT) — unchanged (proven 52us) ---------
#define TSTRIDE 40
#define TILE_B  (128 * TSTRIDE * 2)
#define BUF_B   (4 * TILE_B)
#define HG_SMEM (2 * BUF_B)

__global__ __launch_bounds__(256) void hgemm_nt_bias(
    const float* __restrict__ A, const float* __restrict__ B,
    const float* __restrict__ bias, float* __restrict__ C, int M, int N)
{
    extern __shared__ __align__(16) char smraw[];
    const int tid = threadIdx.x, lane = tid & 31, wid = tid >> 5;
    const int wm = wid & 1, wn = wid >> 1;
    const int row0 = blockIdx.y * 128, col0 = blockIdx.x * 128;
    const int lr = tid >> 1, lc = (tid & 1) * 16;
    const float* Ap = A + (size_t)(row0 + lr) * GK + lc;
    const float* Bp = B + (size_t)(col0 + lr) * GK + lc;
    const uint32_t sbase = smem_u32(smraw);
    const int a_r = lane & 15, a_c = (lane >> 4) << 3;
    const int b_r = (lane & 7) + ((lane & 16) >> 1), b_c = lane & 8;

    float acc[4][4][4];
    #pragma unroll
    for (int i = 0; i < 4; i++)
        #pragma unroll
        for (int j = 0; j < 4; j++)
            #pragma unroll
            for (int c = 0; c < 4; c++) acc[i][j][c] = 0.f;

    float4 av[4], bv[4];
    #pragma unroll
    for (int q = 0; q < 4; q++) { av[q] = *(const float4*)(Ap+4*q); bv[q] = *(const float4*)(Bp+4*q); }
    {
        char* hA = smraw;
        const int bo = (lr*TSTRIDE + lc) * 2;
        #pragma unroll
        for (int q = 0; q < 4; q++) {
            split_sts(av[q], hA,            hA + TILE_B,   bo + 8*q);
            split_sts(bv[q], hA + 2*TILE_B, hA + 3*TILE_B, bo + 8*q);
        }
    }
    __syncthreads();

    for (int kt = 0; kt < 32; kt++) {
        if (kt < 31) {
            #pragma unroll
            for (int q = 0; q < 4; q++) {
                av[q] = *(const float4*)(Ap + (kt+1)*32 + 4*q);
                bv[q] = *(const float4*)(Bp + (kt+1)*32 + 4*q);
            }
        }
        const uint32_t base = sbase + (kt & 1) * BUF_B;
        #pragma unroll
        for (int kk = 0; kk < 2; kk++) {
            const int koff = kk * 16;
            uint32_t ah[4][4], al[4][4];
            #pragma unroll
            for (int i = 0; i < 4; i++) {
                const uint32_t off = (uint32_t)(((wm*64 + i*16 + a_r)*TSTRIDE + koff + a_c) * 2);
                ldsm_x4(ah[i], base + off);
                ldsm_x4(al[i], base + TILE_B + off);
            }
            uint32_t bh[2][4], bl[2][4];
            #pragma unroll
            for (int p = 0; p < 2; p++) {
                const uint32_t off = (uint32_t)(((wn*32 + p*16 + b_r)*TSTRIDE + koff + b_c) * 2);
                ldsm_x4(bh[p], base + 2*TILE_B + off);
                ldsm_x4(bl[p], base + 3*TILE_B + off);
            }
            #pragma unroll
            for (int i = 0; i < 4; i++)
                #pragma unroll
                for (int j = 0; j < 4; j++) {
                    const int p = j >> 1, s = (j & 1) * 2;
                    mma_bf16(acc[i][j], ah[i], bh[p][s], bh[p][s+1]);
                    mma_bf16(acc[i][j], ah[i], bl[p][s], bl[p][s+1]);
                    mma_bf16(acc[i][j], al[i], bh[p][s], bh[p][s+1]);
                }
        }
        if (kt < 31) {
            char* hA = smraw + ((kt+1) & 1) * BUF_B;
            const int bo = (lr*TSTRIDE + lc) * 2;
            #pragma unroll
            for (int q = 0; q < 4; q++) {
                split_sts(av[q], hA,            hA + TILE_B,   bo + 8*q);
                split_sts(bv[q], hA + 2*TILE_B, hA + 3*TILE_B, bo + 8*q);
            }
            __syncthreads();
        }
    }
    const int grp = lane >> 2, qid = lane & 3;
    #pragma unroll
    for (int j = 0; j < 4; j++) {
        const int col = col0 + wn*32 + j*8 + qid*2;
        const float2 bj = *(const float2*)(bias + col);
        #pragma unroll
        for (int i = 0; i < 4; i++) {
            const int row = row0 + wm*64 + i*16 + grp;
            *(float2*)(C + (size_t)row*N + col)     = make_float2(acc[i][j][0]+bj.x, acc[i][j][1]+bj.y);
            *(float2*)(C + (size_t)(row+8)*N + col) = make_float2(acc[i][j][2]+bj.x, acc[i][j][3]+bj.y);
        }
    }
}

// --------- tensor-core fused attention ---------
// smem: Qhi 0 | Qlo 16384 | S(hi) 32768 | S(lo) 49152 | R fp32 [128][260] @65536 | vbs @198656
#define RSTR 260
#define A_SMEM 199680

__global__ __launch_bounds__(256, 1) void attn_mma()
{
    extern __shared__ __align__(16) char sm[];
    float* R   = (float*)(sm + 65536);
    float* vbs = (float*)(sm + 198656);
    const int tid = threadIdx.x, lane = tid & 31, wid = tid >> 5;
    const int grp = lane >> 2, qid = lane & 3;
    const int q0 = blockIdx.x*128, h = blockIdx.y, b = blockIdx.z, bh = b*NH + h;
    const uint32_t sbQ = smem_u32(sm), sbS = sbQ + 32768;
    const int wm = wid & 1, wn = wid >> 1;
    const int u0w = wid*16, r0 = u0w + grp;

    {   // Q stage
        const uint4* sh = (const uint4*)(g_qhi + ((size_t)bh*SEQ + q0)*HD);
        const uint4* sl = (const uint4*)(g_qlo + ((size_t)bh*SEQ + q0)*HD);
        #pragma unroll
        for (int r = 0; r < 4; r++) {
            int idx = tid + r*256, row = idx >> 3, c = idx & 7;
            int off = row*128 + ((c ^ (row & 7)) << 4);
            *(uint4*)(sm + off) = sh[idx];
            *(uint4*)(sm + 16384 + off) = sl[idx];
        }
    }
    float O[8][4];
    #pragma unroll
    for (int j = 0; j < 8; j++) { O[j][0]=0;O[j][1]=0;O[j][2]=0;O[j][3]=0; }
    float mr0 = -INFINITY, mr1 = -INFINITY, lr0 = 0.f, lr1 = 0.f;

    for (int kt = 0; kt < 8; kt++) {
        const int k0 = kt*128, lmin = SEQ + k0 - q0 - 127;
        __syncthreads();
        vbs[tid] = g_vbrel[h*2048 + lmin + tid];

        // ---- R = Q @ pos_band^T (+vbrel), two halves ----
        for (int hf = 0; hf < 2; hf++) {
            if (hf) __syncthreads();
            {
                const uint4* sh = (const uint4*)(g_poshi + (size_t)(lmin + hf*128)*HD);
                const uint4* sl = (const uint4*)(g_poslo + (size_t)(lmin + hf*128)*HD);
                #pragma unroll
                for (int r = 0; r < 4; r++) {
                    int idx = tid + r*256, row = idx >> 3, c = idx & 7;
                    int off = 32768 + row*128 + ((c ^ (row & 7)) << 4);
                    *(uint4*)(sm + off) = sh[idx];
                    *(uint4*)(sm + 16384 + off) = sl[idx];
                }
            }
            __syncthreads();
            float rc[4][4][4];
            #pragma unroll
            for (int i = 0; i < 4; i++)
                #pragma unroll
                for (int j = 0; j < 4; j++) { rc[i][j][0]=0;rc[i][j][1]=0;rc[i][j][2]=0;rc[i][j][3]=0; }
            #pragma unroll
            for (int kb = 0; kb < 4; kb++) {
                uint32_t ah[4][4], al[4][4];
                #pragma unroll
                for (int i = 0; i < 4; i++) {
                    uint32_t ao = (uint32_t)((wm*64 + i*16 + (lane&15))*128
                                 + (((kb*2 + (lane>>4)) ^ (lane&7)) << 4));
                    ldsm_x4(ah[i], sbQ + ao);
                    ldsm_x4(al[i], sbQ + 16384 + ao);
                }
                uint32_t bh2[2][4], bl2[2][4];
                #pragma unroll
                for (int jp = 0; jp < 2; jp++) {
                    uint32_t bo = (uint32_t)((wn*32 + jp*16 + (lane&7) + ((lane&16)>>1))*128
                                 + (((kb*2 + ((lane&8)>>3)) ^ (lane&7)) << 4));
                    ldsm_x4(bh2[jp], sbS + bo);
                    ldsm_x4(bl2[jp], sbS + 16384 + bo);
                }
                #pragma unroll
                for (int i = 0; i < 4; i++)
                    #pragma unroll
                    for (int j = 0; j < 4; j++) {
                        const int jp = j >> 1, s = (j & 1)*2;
                        mma_bf16(rc[i][j], ah[i], bh2[jp][s], bh2[jp][s+1]);
                        mma_bf16(rc[i][j], ah[i], bl2[jp][s], bl2[jp][s+1]);
                        mma_bf16(rc[i][j], al[i], bh2[jp][s], bh2[jp][s+1]);
                    }
            }
            #pragma unroll
            for (int i = 0; i < 4; i++) {
                const int u = wm*64 + i*16 + grp;
                #pragma unroll
                for (int j = 0; j < 4; j++) {
                    const int l = hf*128 + wn*32 + j*8 + qid*2;
                    float v0 = vbs[l], v1 = vbs[l+1];
                    *(float2*)&R[u*RSTR + l]     = make_float2(rc[i][j][0]+v0, rc[i][j][1]+v1);
                    *(float2*)&R[(u+8)*RSTR + l] = make_float2(rc[i][j][2]+v0, rc[i][j][3]+v1);
                }
            }
        }

        __syncthreads();
        {   // K stage
            const uint4* sh = (const uint4*)(g_khi + ((size_t)bh*SEQ + k0)*HD);
            const uint4* sl = (const uint4*)(g_klo + ((size_t)bh*SEQ + k0)*HD);
            #pragma unroll
            for (int r = 0; r < 4; r++) {
                int idx = tid + r*256, row = idx >> 3, c = idx & 7;
                int off = 32768 + row*128 + ((c ^ (row & 7)) << 4);
                *(uint4*)(sm + off) = sh[idx];
                *(uint4*)(sm + 16384 + off) = sl[idx];
            }
        }
        __syncthreads();

        // ---- QK: warp rows [u0w,u0w+16) x 128 cols ----
        float aq[16][4];
        #pragma unroll
        for (int j = 0; j < 16; j++) { aq[j][0]=0;aq[j][1]=0;aq[j][2]=0;aq[j][3]=0; }
        #pragma unroll
        for (int kb = 0; kb < 4; kb++) {
            uint32_t ah[4], al[4];
            uint32_t ao = (uint32_t)((u0w + (lane&15))*128
                         + (((kb*2 + (lane>>4)) ^ (lane&7)) << 4));
            ldsm_x4(ah, sbQ + ao);
            ldsm_x4(al, sbQ + 16384 + ao);
            #pragma unroll
            for (int jp = 0; jp < 8; jp++) {
                uint32_t bh4[4], bl4[4];
                uint32_t bo = (uint32_t)((jp*16 + (lane&7) + ((lane&16)>>1))*128
                             + (((kb*2 + ((lane&8)>>3)) ^ (lane&7)) << 4));
                ldsm_x4(bh4, sbS + bo);
                ldsm_x4(bl4, sbS + 16384 + bo);
                #pragma unroll
                for (int jj = 0; jj < 2; jj++) {
                    const int j = jp*2 + jj, s = jj*2;
                    mma_bf16(aq[j], ah, bh4[s], bh4[s+1]);
                    mma_bf16(aq[j], ah, bl4[s], bl4[s+1]);
                    mma_bf16(aq[j], al, bh4[s], bh4[s+1]);
                }
            }
        }

        // ---- rel gather + online softmax + pack P frags ----
        float m0 = -INFINITY, m1 = -INFINITY;
        #pragma unroll
        for (int j = 0; j < 16; j++) {
            const int w = j*8 + qid*2;
            aq[j][0] += R[r0*RSTR + 127 + w - r0];
            aq[j][1] += R[r0*RSTR + 128 + w - r0];
            aq[j][2] += R[(r0+8)*RSTR + 119 + w - r0];
            aq[j][3] += R[(r0+8)*RSTR + 120 + w - r0];
            m0 = fmaxf(m0, fmaxf(aq[j][0], aq[j][1]));
            m1 = fmaxf(m1, fmaxf(aq[j][2], aq[j][3]));
        }
        m0 = fmaxf(m0, __shfl_xor_sync(~0u, m0, 1));
        m0 = fmaxf(m0, __shfl_xor_sync(~0u, m0, 2));
        m1 = fmaxf(m1, __shfl_xor_sync(~0u, m1, 1));
        m1 = fmaxf(m1, __shfl_xor_sync(~0u, m1, 2));
        const float mn0 = fmaxf(mr0, m0), mn1 = fmaxf(mr1, m1);
        const float scl0 = __expf(mr0 - mn0), scl1 = __expf(mr1 - mn1);
        mr0 = mn0; mr1 = mn1;

        uint32_t phi[8][4], plo[8][4];
        float s0 = 0.f, s1 = 0.f;
        #pragma unroll
        for (int j = 0; j < 16; j++) {
            float p0 = __expf(aq[j][0]-mn0), p1 = __expf(aq[j][1]-mn0);
            float p2 = __expf(aq[j][2]-mn1), p3 = __expf(aq[j][3]-mn1);
            s0 += p0 + p1; s1 += p2 + p3;
            const int kk = j >> 1, bs = (j & 1)*2;
            __nv_bfloat162 h01 = __floats2bfloat162_rn(p0, p1);
            __nv_bfloat162 h23 = __floats2bfloat162_rn(p2, p3);
            float2 f01 = __bfloat1622float2(h01);
            float2 f23 = __bfloat1622float2(h23);
            __nv_bfloat162 l01 = __floats2bfloat162_rn(p0-f01.x, p1-f01.y);
            __nv_bfloat162 l23 = __floats2bfloat162_rn(p2-f23.x, p3-f23.y);
            phi[kk][bs]   = *(uint32_t*)&h01;  phi[kk][bs+1] = *(uint32_t*)&h23;
            plo[kk][bs]   = *(uint32_t*)&l01;  plo[kk][bs+1] = *(uint32_t*)&l23;
        }
        s0 += __shfl_xor_sync(~0u, s0, 1); s0 += __shfl_xor_sync(~0u, s0, 2);
        s1 += __shfl_xor_sync(~0u, s1, 1); s1 += __shfl_xor_sync(~0u, s1, 2);
        lr0 = lr0*scl0 + s0; lr1 = lr1*scl1 + s1;
        #pragma unroll
        for (int j = 0; j < 8; j++) {
            O[j][0] *= scl0; O[j][1] *= scl0; O[j][2] *= scl1; O[j][3] *= scl1;
        }

        __syncthreads();
        {   // Vt stage: 64 rows(d) x 128 bf16 (16 chunks)
            #pragma unroll
            for (int r = 0; r < 4; r++) {
                int idx = tid + r*256, d = idx >> 4, c = idx & 15;
                const uint4* sh = (const uint4*)(g_vthi + ((size_t)bh*HD + d)*SEQ + k0);
                const uint4* sl = (const uint4*)(g_vtlo + ((size_t)bh*HD + d)*SEQ + k0);
                int off = 32768 + d*256 + ((c ^ (d & 7)) << 4);
                *(uint4*)(sm + off) = sh[c];
                *(uint4*)(sm + 16384 + off) = sl[c];
            }
        }
        __syncthreads();

        // ---- PV: O += P @ Vt^T ----
        #pragma unroll
        for (int kk = 0; kk < 8; kk++) {
            #pragma unroll
            for (int jp = 0; jp < 4; jp++) {
                uint32_t bh4[4], bl4[4];
                uint32_t bo = (uint32_t)((jp*16 + (lane&7) + ((lane&16)>>1))*256
                             + (((kk*2 + ((lane&8)>>3)) ^ (lane&7)) << 4));
                ldsm_x4(bh4, sbS + bo);
                ldsm_x4(bl4, sbS + 16384 + bo);
                #pragma unroll
                for (int jj = 0; jj < 2; jj++) {
                    const int j = jp*2 + jj, s = jj*2;
                    mma_bf16(O[j], phi[kk], bh4[s], bh4[s+1]);
                    mma_bf16(O[j], phi[kk], bl4[s], bl4[s+1]);
                    mma_bf16(O[j], plo[kk], bh4[s], bh4[s+1]);
                }
            }
        }
    }

    // epilogue
    const float i0 = 1.f/lr0, i1 = 1.f/lr1;
    float* x0 = g_x + ((size_t)(b*SEQ + q0 + r0))*DM + h*HD;
    float* x1 = g_x + ((size_t)(b*SEQ + q0 + r0 + 8))*DM + h*HD;
    #pragma unroll
    for (int j = 0; j < 8; j++) {
        const int col = j*8 + qid*2;
        *(float2*)(x0 + col) = make_float2(O[j][0]*i0, O[j][1]*i0);
        *(float2*)(x1 + col) = make_float2(O[j][2]*i1, O[j][3]*i1);
    }
}

// ---------------------------------------------------------------------------
extern "C" void kernel_launch(void* const* d_in, const int* in_sizes, int n_in,
                              void* d_out, int out_size) {
    const float* query  = (const float*)d_in[0];
    const float* key    = (const float*)d_in[1];
    const float* value  = (const float*)d_in[2];
    const float* Wq     = (const float*)d_in[4];
    const float* bq     = (const float*)d_in[5];
    const float* Wv     = (const float*)d_in[6];
    const float* bv     = (const float*)d_in[7];
    const float* Wo     = (const float*)d_in[8];
    const float* bo     = (const float*)d_in[9];
    const float* v_bias = (const float*)d_in[10];
    float* out = (float*)d_out;

    void *qp, *vp, *xp, *qh, *ql, *kh, *kl, *vh, *vl;
    cudaGetSymbolAddress(&qp, g_qproj);
    cudaGetSymbolAddress(&vp, g_vproj);
    cudaGetSymbolAddress(&xp, g_x);
    cudaGetSymbolAddress(&qh, g_qhi); cudaGetSymbolAddress(&ql, g_qlo);
    cudaGetSymbolAddress(&kh, g_khi); cudaGetSymbolAddress(&kl, g_klo);
    cudaGetSymbolAddress(&vh, g_vthi); cudaGetSymbolAddress(&vl, g_vtlo);

    cudaFuncSetAttribute(hgemm_nt_bias, cudaFuncAttributeMaxDynamicSharedMemorySize, HG_SMEM);
    cudaFuncSetAttribute(attn_mma, cudaFuncAttributeMaxDynamicSharedMemorySize, A_SMEM);

    pos_kernel2<<<8, 256>>>(v_bias);
    split_bhsd<<<2048, 256>>>(key, (__nv_bfloat16*)kh, (__nv_bfloat16*)kl);

    dim3 ggrid(DM/128, (NB*SEQ)/128);
    hgemm_nt_bias<<<ggrid, 256, HG_SMEM>>>(query, Wq, bq, (float*)qp, NB*SEQ, DM);
    hgemm_nt_bias<<<ggrid, 256, HG_SMEM>>>(value, Wv, bv, (float*)vp, NB*SEQ, DM);

    split_bhsd<<<2048, 256>>>((const float*)qp, (__nv_bfloat16*)qh, (__nv_bfloat16*)ql);
    vtsplit<<<512, 256>>>((const float*)vp, (__nv_bfloat16*)vh, (__nv_bfloat16*)vl);

    dim3 agrid(SEQ/128, NH, NB);
    attn_mma<<<agrid, 256, A_SMEM>>>();

    hgemm_nt_bias<<<ggrid, 256, HG_SMEM>>>((const float*)xp, Wo, bo, out, NB*SEQ, DM);
}

// round 7
// speedup vs baseline: 2.1976x; 1.6243x over previous
#include <cuda_runtime.h>
#include <cuda_bf16.h>
#include <math.h>
#include <stdint.h>

#define SEQ 1024
#define DM  1024
#define NH  16
#define HD  64
#define NB  2
#define GK  1024

__device__ float g_vproj[NB*SEQ*DM];
__device__ float g_x[NB*SEQ*DM];
__device__ float g_posf[2*SEQ*HD];
__device__ float g_vbrel[NH*2*SEQ + 32];
__device__ __nv_bfloat16 g_qhi[NB*NH*SEQ*HD], g_qlo[NB*NH*SEQ*HD];
__device__ __nv_bfloat16 g_khi[NB*NH*SEQ*HD], g_klo[NB*NH*SEQ*HD];
__device__ __nv_bfloat16 g_vthi[NB*NH*HD*SEQ], g_vtlo[NB*NH*HD*SEQ];
__device__ __nv_bfloat16 g_poshi[(2*SEQ+1)*HD], g_poslo[(2*SEQ+1)*HD];

__device__ __forceinline__ uint32_t smem_u32(const void* p) {
    uint32_t a;
    asm("{ .reg .u64 t; cvta.to.shared.u64 t, %1; cvt.u32.u64 %0, t; }" : "=r"(a) : "l"(p));
    return a;
}
__device__ __forceinline__ void ldsm_x4(uint32_t (&r)[4], uint32_t addr) {
    asm volatile("ldmatrix.sync.aligned.m8n8.x4.shared.b16 {%0,%1,%2,%3}, [%4];"
        : "=r"(r[0]), "=r"(r[1]), "=r"(r[2]), "=r"(r[3]) : "r"(addr));
}
__device__ __forceinline__ void mma_bf16(float (&d)[4], const uint32_t (&a)[4],
                                         uint32_t b0, uint32_t b1) {
    asm volatile("mma.sync.aligned.m16n8k16.row.col.f32.bf16.bf16.f32 "
        "{%0,%1,%2,%3}, {%4,%5,%6,%7}, {%8,%9}, {%0,%1,%2,%3};"
        : "+f"(d[0]), "+f"(d[1]), "+f"(d[2]), "+f"(d[3])
        : "r"(a[0]), "r"(a[1]), "r"(a[2]), "r"(a[3]), "r"(b0), "r"(b1));
}
__device__ __forceinline__ void split_sts(float4 v, char* hi, char* lo, int byteoff) {
    __nv_bfloat162 h01 = __floats2bfloat162_rn(v.x, v.y);
    __nv_bfloat162 h23 = __floats2bfloat162_rn(v.z, v.w);
    float2 f01 = __bfloat1622float2(h01);
    float2 f23 = __bfloat1622float2(h23);
    __nv_bfloat162 l01 = __floats2bfloat162_rn(v.x - f01.x, v.y - f01.y);
    __nv_bfloat162 l23 = __floats2bfloat162_rn(v.z - f23.x, v.w - f23.y);
    *(uint2*)(hi + byteoff) = make_uint2(*(uint32_t*)&h01, *(uint32_t*)&h23);
    *(uint2*)(lo + byteoff) = make_uint2(*(uint32_t*)&l01, *(uint32_t*)&l23);
}
__device__ __forceinline__ uint32_t packsplit(float a, float b, uint32_t& lo) {
    __nv_bfloat162 hh = __floats2bfloat162_rn(a, b);
    float2 ff = __bfloat1622float2(hh);
    __nv_bfloat162 ll = __floats2bfloat162_rn(a - ff.x, b - ff.y);
    lo = *(uint32_t*)&ll;
    return *(uint32_t*)&hh;
}

// pos: one thread per (l, j<32): double-precision trig, fp32 + bf16 split out
__global__ void pos_split() {
    int idx = blockIdx.x * 256 + threadIdx.x;   // 65536
    int l = idx >> 5, j = idx & 31;
    float p = (float)(l - SEQ);
    const double negc = -log(10000.0) / 31.0;
    float ang = p * (float)exp((double)j * negc);
    float s = (float)sin((double)ang), c = (float)cos((double)ang);
    g_posf[l*64 + j]      = s;
    g_posf[l*64 + j + 32] = c;
    __nv_bfloat16 sh = __float2bfloat16_rn(s), ch = __float2bfloat16_rn(c);
    g_poshi[l*64 + j]      = sh;
    g_poshi[l*64 + j + 32] = ch;
    g_poslo[l*64 + j]      = __float2bfloat16_rn(s - __bfloat162float(sh));
    g_poslo[l*64 + j + 32] = __float2bfloat16_rn(c - __bfloat162float(ch));
}
// vbrel[h][l]: one thread per (l,h)
__global__ void vbrel_k(const float* __restrict__ vb) {
    int idx = blockIdx.x * 256 + threadIdx.x;   // 32768
    int l = idx >> 4, h = idx & 15;
    float s = 0.f;
    #pragma unroll 8
    for (int d = 0; d < HD; d++) s = fmaf(__ldg(vb + h*HD + d), g_posf[l*64 + d], s);
    g_vbrel[h*2048 + l] = s;
}
// (b,s,h*64+d) fp32 -> (b,h,s,d) bf16 hi/lo
__global__ void split_bhsd(const float* __restrict__ src,
                           __nv_bfloat16* __restrict__ hi, __nv_bfloat16* __restrict__ lo) {
    int idx = blockIdx.x * 256 + threadIdx.x;
    float4 v = ((const float4*)src)[idx];
    int c = idx & 255, s = (idx >> 8) & 1023, b = idx >> 18;
    size_t o = ((size_t)(b*NH + (c >> 4))*SEQ + s)*HD + (c & 15)*4;
    split_sts(v, (char*)(hi + o), (char*)(lo + o), 0);
}
// g_vproj (b,s,h*64+d) -> (b,h,d,s) bf16 hi/lo
__global__ void vtsplit(const float* __restrict__ src,
                        __nv_bfloat16* __restrict__ hi, __nv_bfloat16* __restrict__ lo) {
    __shared__ float t[64*65];
    int w0 = (blockIdx.x & 15) * 64, bh = blockIdx.x >> 4;
    int b = bh >> 4, h = bh & 15, tid = threadIdx.x;
    #pragma unroll
    for (int it = 0; it < 4; it++) {
        int idx = tid + it*256, w = idx >> 4, dq = idx & 15;
        float4 v = *(const float4*)(src + ((size_t)(b*SEQ + w0 + w))*DM + h*HD + dq*4);
        t[w*65+dq*4+0] = v.x; t[w*65+dq*4+1] = v.y;
        t[w*65+dq*4+2] = v.z; t[w*65+dq*4+3] = v.w;
    }
    __syncthreads();
    #pragma unroll
    for (int it = 0; it < 4; it++) {
        int idx = tid + it*256, d = idx >> 4, wq = idx & 15;
        float4 v = make_float4(t[(wq*4+0)*65+d], t[(wq*4+1)*65+d],
                               t[(wq*4+2)*65+d], t[(wq*4+3)*65+d]);
        size_t o = ((size_t)bh*HD + d)*SEQ + w0 + wq*4;
        split_sts(v, (char*)(hi + o), (char*)(lo + o), 0);
    }
}

// --------- bf16x2-split GEMM (NT); MODE 0: fp32 C, MODE 1: split to (b,h,s,d) ---------
#define TSTRIDE 40
#define TILE_B  (128 * TSTRIDE * 2)
#define BUF_B   (4 * TILE_B)
#define HG_SMEM (2 * BUF_B)

template<int MODE>
__global__ __launch_bounds__(256) void hgemm_k(
    const float* __restrict__ A, const float* __restrict__ B,
    const float* __restrict__ bias, float* __restrict__ C,
    __nv_bfloat16* __restrict__ Hi, __nv_bfloat16* __restrict__ Lo, int M, int N)
{
    extern __shared__ __align__(16) char smraw[];
    const int tid = threadIdx.x, lane = tid & 31, wid = tid >> 5;
    const int wm = wid & 1, wn = wid >> 1;
    const int row0 = blockIdx.y * 128, col0 = blockIdx.x * 128;
    const int lr = tid >> 1, lc = (tid & 1) * 16;
    const float* Ap = A + (size_t)(row0 + lr) * GK + lc;
    const float* Bp = B + (size_t)(col0 + lr) * GK + lc;
    const uint32_t sbase = smem_u32(smraw);
    const int a_r = lane & 15, a_c = (lane >> 4) << 3;
    const int b_r = (lane & 7) + ((lane & 16) >> 1), b_c = lane & 8;

    float acc[4][4][4];
    #pragma unroll
    for (int i = 0; i < 4; i++)
        #pragma unroll
        for (int j = 0; j < 4; j++)
            #pragma unroll
            for (int c = 0; c < 4; c++) acc[i][j][c] = 0.f;

    float4 av[4], bv[4];
    #pragma unroll
    for (int q = 0; q < 4; q++) { av[q] = *(const float4*)(Ap+4*q); bv[q] = *(const float4*)(Bp+4*q); }
    {
        char* hA = smraw;
        const int bo = (lr*TSTRIDE + lc) * 2;
        #pragma unroll
        for (int q = 0; q < 4; q++) {
            split_sts(av[q], hA,            hA + TILE_B,   bo + 8*q);
            split_sts(bv[q], hA + 2*TILE_B, hA + 3*TILE_B, bo + 8*q);
        }
    }
    __syncthreads();

    for (int kt = 0; kt < 32; kt++) {
        if (kt < 31) {
            #pragma unroll
            for (int q = 0; q < 4; q++) {
                av[q] = *(const float4*)(Ap + (kt+1)*32 + 4*q);
                bv[q] = *(const float4*)(Bp + (kt+1)*32 + 4*q);
            }
        }
        const uint32_t base = sbase + (kt & 1) * BUF_B;
        #pragma unroll
        for (int kk = 0; kk < 2; kk++) {
            const int koff = kk * 16;
            uint32_t ah[4][4], al[4][4];
            #pragma unroll
            for (int i = 0; i < 4; i++) {
                const uint32_t off = (uint32_t)(((wm*64 + i*16 + a_r)*TSTRIDE + koff + a_c) * 2);
                ldsm_x4(ah[i], base + off);
                ldsm_x4(al[i], base + TILE_B + off);
            }
            uint32_t bh[2][4], bl[2][4];
            #pragma unroll
            for (int p = 0; p < 2; p++) {
                const uint32_t off = (uint32_t)(((wn*32 + p*16 + b_r)*TSTRIDE + koff + b_c) * 2);
                ldsm_x4(bh[p], base + 2*TILE_B + off);
                ldsm_x4(bl[p], base + 3*TILE_B + off);
            }
            #pragma unroll
            for (int i = 0; i < 4; i++)
                #pragma unroll
                for (int j = 0; j < 4; j++) {
                    const int p = j >> 1, s = (j & 1) * 2;
                    mma_bf16(acc[i][j], ah[i], bh[p][s], bh[p][s+1]);
                    mma_bf16(acc[i][j], ah[i], bl[p][s], bl[p][s+1]);
                    mma_bf16(acc[i][j], al[i], bh[p][s], bh[p][s+1]);
                }
        }
        if (kt < 31) {
            char* hA = smraw + ((kt+1) & 1) * BUF_B;
            const int bo = (lr*TSTRIDE + lc) * 2;
            #pragma unroll
            for (int q = 0; q < 4; q++) {
                split_sts(av[q], hA,            hA + TILE_B,   bo + 8*q);
                split_sts(bv[q], hA + 2*TILE_B, hA + 3*TILE_B, bo + 8*q);
            }
            __syncthreads();
        }
    }
    const int grp = lane >> 2, qid = lane & 3;
    #pragma unroll
    for (int j = 0; j < 4; j++) {
        const int col = col0 + wn*32 + j*8 + qid*2;
        const float2 bj = *(const float2*)(bias + col);
        #pragma unroll
        for (int i = 0; i < 4; i++) {
            const int row = row0 + wm*64 + i*16 + grp;
            float v0 = acc[i][j][0]+bj.x, v1 = acc[i][j][1]+bj.y;
            float v2 = acc[i][j][2]+bj.x, v3 = acc[i][j][3]+bj.y;
            if (MODE == 0) {
                *(float2*)(C + (size_t)row*N + col)     = make_float2(v0, v1);
                *(float2*)(C + (size_t)(row+8)*N + col) = make_float2(v2, v3);
            } else {
                const int b = row >> 10, s = row & 1023, h = col >> 6, d = col & 63;
                size_t o = (((size_t)(b*NH + h))*SEQ + s)*HD + d;
                uint32_t lo0, lo1;
                uint32_t hi0 = packsplit(v0, v1, lo0);
                uint32_t hi1 = packsplit(v2, v3, lo1);
                *(uint32_t*)(Hi + o) = hi0;           *(uint32_t*)(Lo + o) = lo0;
                *(uint32_t*)(Hi + o + 8*HD) = hi1;    *(uint32_t*)(Lo + o + 8*HD) = lo1;
            }
        }
    }
}

// --------- tensor-core fused attention with rolling R band ---------
// smem: Qhi 0 | Qlo 16384 | Shi 32768 | Slo 49152 | R0 @65536 | R1 @133120 | vb @200704
#define RSTR 132
#define A_SMEM 201728

__global__ __launch_bounds__(256, 1) void attn_mma()
{
    extern __shared__ __align__(16) char sm[];
    float* Rb[2] = { (float*)(sm + 65536), (float*)(sm + 133120) };
    float* vbp   = (float*)(sm + 200704);
    const int tid = threadIdx.x, lane = tid & 31, wid = tid >> 5;
    const int grp = lane >> 2, qid = lane & 3;
    const int q0 = blockIdx.x*128, h = blockIdx.y, b = blockIdx.z, bh = b*NH + h;
    const uint32_t sbQ = smem_u32(sm), sbS = sbQ + 32768;
    const int wm = wid & 1, wn = wid >> 1;
    const int u0w = wid*16, r0 = u0w + grp;
    const int lmin0 = SEQ - q0 - 127;

    {   // Q stage
        const uint4* sh = (const uint4*)(g_qhi + ((size_t)bh*SEQ + q0)*HD);
        const uint4* sl = (const uint4*)(g_qlo + ((size_t)bh*SEQ + q0)*HD);
        #pragma unroll
        for (int r = 0; r < 4; r++) {
            int idx = tid + r*256, row = idx >> 3, c = idx & 7;
            int off = row*128 + ((c ^ (row & 7)) << 4);
            *(uint4*)(sm + off) = sh[idx];
            *(uint4*)(sm + 16384 + off) = sl[idx];
        }
    }
    float O[8][4];
    #pragma unroll
    for (int j = 0; j < 8; j++) { O[j][0]=0;O[j][1]=0;O[j][2]=0;O[j][3]=0; }
    float mr0 = -INFINITY, mr1 = -INFINITY, lr0 = 0.f, lr1 = 0.f;

    for (int kt = 0; kt < 8; kt++) {
        const int k0 = kt*128;

        // ---- compute new R half/halves (tile 0: g=0,1; else g=kt+1) ----
        const int g0 = (kt == 0) ? 0 : kt + 1;
        for (int g = g0; g <= kt + 1; g++) {
            const int slot = g & 1, l0 = lmin0 + 128*g;
            __syncthreads();
            {
                const uint4* sh = (const uint4*)(g_poshi + (size_t)l0*HD);
                const uint4* sl = (const uint4*)(g_poslo + (size_t)l0*HD);
                #pragma unroll
                for (int r = 0; r < 4; r++) {
                    int idx = tid + r*256, row = idx >> 3, c = idx & 7;
                    int off = 32768 + row*128 + ((c ^ (row & 7)) << 4);
                    *(uint4*)(sm + off) = sh[idx];
                    *(uint4*)(sm + 16384 + off) = sl[idx];
                }
                if (tid < 128) vbp[slot*128 + tid] = g_vbrel[h*2048 + l0 + tid];
            }
            __syncthreads();
            float rc[4][4][4];
            #pragma unroll
            for (int i = 0; i < 4; i++)
                #pragma unroll
                for (int j = 0; j < 4; j++) { rc[i][j][0]=0;rc[i][j][1]=0;rc[i][j][2]=0;rc[i][j][3]=0; }
            #pragma unroll
            for (int kb = 0; kb < 4; kb++) {
                uint32_t ah[4][4], al[4][4];
                #pragma unroll
                for (int i = 0; i < 4; i++) {
                    uint32_t ao = (uint32_t)((wm*64 + i*16 + (lane&15))*128
                                 + (((kb*2 + (lane>>4)) ^ (lane&7)) << 4));
                    ldsm_x4(ah[i], sbQ + ao);
                    ldsm_x4(al[i], sbQ + 16384 + ao);
                }
                uint32_t bh2[2][4], bl2[2][4];
                #pragma unroll
                for (int jp = 0; jp < 2; jp++) {
                    uint32_t bo = (uint32_t)((wn*32 + jp*16 + (lane&7) + ((lane&16)>>1))*128
                                 + (((kb*2 + ((lane&8)>>3)) ^ (lane&7)) << 4));
                    ldsm_x4(bh2[jp], sbS + bo);
                    ldsm_x4(bl2[jp], sbS + 16384 + bo);
                }
                #pragma unroll
                for (int i = 0; i < 4; i++)
                    #pragma unroll
                    for (int j = 0; j < 4; j++) {
                        const int jp = j >> 1, s = (j & 1)*2;
                        mma_bf16(rc[i][j], ah[i], bh2[jp][s], bh2[jp][s+1]);
                        mma_bf16(rc[i][j], ah[i], bl2[jp][s], bl2[jp][s+1]);
                        mma_bf16(rc[i][j], al[i], bh2[jp][s], bh2[jp][s+1]);
                    }
            }
            float* R = Rb[slot];
            #pragma unroll
            for (int i = 0; i < 4; i++) {
                const int u = wm*64 + i*16 + grp;
                #pragma unroll
                for (int j = 0; j < 4; j++) {
                    const int l = wn*32 + j*8 + qid*2;
                    float v0 = vbp[slot*128 + l], v1 = vbp[slot*128 + l + 1];
                    *(float2*)&R[u*RSTR + l]     = make_float2(rc[i][j][0]+v0, rc[i][j][1]+v1);
                    *(float2*)&R[(u+8)*RSTR + l] = make_float2(rc[i][j][2]+v0, rc[i][j][3]+v1);
                }
            }
        }

        __syncthreads();
        {   // K stage
            const uint4* sh = (const uint4*)(g_khi + ((size_t)bh*SEQ + k0)*HD);
            const uint4* sl = (const uint4*)(g_klo + ((size_t)bh*SEQ + k0)*HD);
            #pragma unroll
            for (int r = 0; r < 4; r++) {
                int idx = tid + r*256, row = idx >> 3, c = idx & 7;
                int off = 32768 + row*128 + ((c ^ (row & 7)) << 4);
                *(uint4*)(sm + off) = sh[idx];
                *(uint4*)(sm + 16384 + off) = sl[idx];
            }
        }
        __syncthreads();

        // ---- QK ----
        float aq[16][4];
        #pragma unroll
        for (int j = 0; j < 16; j++) { aq[j][0]=0;aq[j][1]=0;aq[j][2]=0;aq[j][3]=0; }
        #pragma unroll
        for (int kb = 0; kb < 4; kb++) {
            uint32_t ah[4], al[4];
            uint32_t ao = (uint32_t)((u0w + (lane&15))*128
                         + (((kb*2 + (lane>>4)) ^ (lane&7)) << 4));
            ldsm_x4(ah, sbQ + ao);
            ldsm_x4(al, sbQ + 16384 + ao);
            #pragma unroll
            for (int jp = 0; jp < 8; jp++) {
                uint32_t bh4[4], bl4[4];
                uint32_t bo = (uint32_t)((jp*16 + (lane&7) + ((lane&16)>>1))*128
                             + (((kb*2 + ((lane&8)>>3)) ^ (lane&7)) << 4));
                ldsm_x4(bh4, sbS + bo);
                ldsm_x4(bl4, sbS + 16384 + bo);
                #pragma unroll
                for (int jj = 0; jj < 2; jj++) {
                    const int j = jp*2 + jj, s = jj*2;
                    mma_bf16(aq[j], ah, bh4[s], bh4[s+1]);
                    mma_bf16(aq[j], ah, bl4[s], bl4[s+1]);
                    mma_bf16(aq[j], al, bh4[s], bh4[s+1]);
                }
            }
        }

        // ---- rel gather (rolling slots) + online softmax + pack P ----
        const float* RA = Rb[kt & 1];          // band cols [0,128)
        const float* RBf = Rb[(kt + 1) & 1];   // band cols [128,256)
        float m0 = -INFINITY, m1 = -INFINITY;
        #pragma unroll
        for (int j = 0; j < 16; j++) {
            const int w = j*8 + qid*2;
            const int ma = 127 + w - r0, mb = ma - 8;
            aq[j][0] += (ma < 128)   ? RA[r0*RSTR + ma]           : RBf[r0*RSTR + ma - 128];
            aq[j][1] += (ma+1 < 128) ? RA[r0*RSTR + ma + 1]       : RBf[r0*RSTR + ma - 127];
            aq[j][2] += (mb < 128)   ? RA[(r0+8)*RSTR + mb]       : RBf[(r0+8)*RSTR + mb - 128];
            aq[j][3] += (mb+1 < 128) ? RA[(r0+8)*RSTR + mb + 1]   : RBf[(r0+8)*RSTR + mb - 127];
            m0 = fmaxf(m0, fmaxf(aq[j][0], aq[j][1]));
            m1 = fmaxf(m1, fmaxf(aq[j][2], aq[j][3]));
        }
        m0 = fmaxf(m0, __shfl_xor_sync(~0u, m0, 1));
        m0 = fmaxf(m0, __shfl_xor_sync(~0u, m0, 2));
        m1 = fmaxf(m1, __shfl_xor_sync(~0u, m1, 1));
        m1 = fmaxf(m1, __shfl_xor_sync(~0u, m1, 2));
        const float mn0 = fmaxf(mr0, m0), mn1 = fmaxf(mr1, m1);
        const float scl0 = __expf(mr0 - mn0), scl1 = __expf(mr1 - mn1);
        mr0 = mn0; mr1 = mn1;

        uint32_t phi[8][4], plo[8][4];
        float s0 = 0.f, s1 = 0.f;
        #pragma unroll
        for (int j = 0; j < 16; j++) {
            float p0 = __expf(aq[j][0]-mn0), p1 = __expf(aq[j][1]-mn0);
            float p2 = __expf(aq[j][2]-mn1), p3 = __expf(aq[j][3]-mn1);
            s0 += p0 + p1; s1 += p2 + p3;
            const int kk = j >> 1, bs = (j & 1)*2;
            phi[kk][bs]   = packsplit(p0, p1, plo[kk][bs]);
            phi[kk][bs+1] = packsplit(p2, p3, plo[kk][bs+1]);
        }
        s0 += __shfl_xor_sync(~0u, s0, 1); s0 += __shfl_xor_sync(~0u, s0, 2);
        s1 += __shfl_xor_sync(~0u, s1, 1); s1 += __shfl_xor_sync(~0u, s1, 2);
        lr0 = lr0*scl0 + s0; lr1 = lr1*scl1 + s1;
        #pragma unroll
        for (int j = 0; j < 8; j++) {
            O[j][0] *= scl0; O[j][1] *= scl0; O[j][2] *= scl1; O[j][3] *= scl1;
        }

        __syncthreads();
        {   // Vt stage
            #pragma unroll
            for (int r = 0; r < 4; r++) {
                int idx = tid + r*256, d = idx >> 4, c = idx & 15;
                const uint4* sh = (const uint4*)(g_vthi + ((size_t)bh*HD + d)*SEQ + k0);
                const uint4* sl = (const uint4*)(g_vtlo + ((size_t)bh*HD + d)*SEQ + k0);
                int off = 32768 + d*256 + ((c ^ (d & 7)) << 4);
                *(uint4*)(sm + off) = sh[c];
                *(uint4*)(sm + 16384 + off) = sl[c];
            }
        }
        __syncthreads();

        // ---- PV ----
        #pragma unroll
        for (int kk = 0; kk < 8; kk++) {
            #pragma unroll
            for (int jp = 0; jp < 4; jp++) {
                uint32_t bh4[4], bl4[4];
                uint32_t bo = (uint32_t)((jp*16 + (lane&7) + ((lane&16)>>1))*256
                             + (((kk*2 + ((lane&8)>>3)) ^ (lane&7)) << 4));
                ldsm_x4(bh4, sbS + bo);
                ldsm_x4(bl4, sbS + 16384 + bo);
                #pragma unroll
                for (int jj = 0; jj < 2; jj++) {
                    const int j = jp*2 + jj, s = jj*2;
                    mma_bf16(O[j], phi[kk], bh4[s], bh4[s+1]);
                    mma_bf16(O[j], phi[kk], bl4[s], bl4[s+1]);
                    mma_bf16(O[j], plo[kk], bh4[s], bh4[s+1]);
                }
            }
        }
    }

    const float i0 = 1.f/lr0, i1 = 1.f/lr1;
    float* x0 = g_x + ((size_t)(b*SEQ + q0 + r0))*DM + h*HD;
    float* x1 = g_x + ((size_t)(b*SEQ + q0 + r0 + 8))*DM + h*HD;
    #pragma unroll
    for (int j = 0; j < 8; j++) {
        const int col = j*8 + qid*2;
        *(float2*)(x0 + col) = make_float2(O[j][0]*i0, O[j][1]*i0);
        *(float2*)(x1 + col) = make_float2(O[j][2]*i1, O[j][3]*i1);
    }
}

// ---------------------------------------------------------------------------
extern "C" void kernel_launch(void* const* d_in, const int* in_sizes, int n_in,
                              void* d_out, int out_size) {
    const float* query  = (const float*)d_in[0];
    const float* key    = (const float*)d_in[1];
    const float* value  = (const float*)d_in[2];
    const float* Wq     = (const float*)d_in[4];
    const float* bq     = (const float*)d_in[5];
    const float* Wv     = (const float*)d_in[6];
    const float* bv     = (const float*)d_in[7];
    const float* Wo     = (const float*)d_in[8];
    const float* bo     = (const float*)d_in[9];
    const float* v_bias = (const float*)d_in[10];
    float* out = (float*)d_out;

    void *vp, *xp, *qh, *ql, *kh, *kl, *vh, *vl;
    cudaGetSymbolAddress(&vp, g_vproj);
    cudaGetSymbolAddress(&xp, g_x);
    cudaGetSymbolAddress(&qh, g_qhi); cudaGetSymbolAddress(&ql, g_qlo);
    cudaGetSymbolAddress(&kh, g_khi); cudaGetSymbolAddress(&kl, g_klo);
    cudaGetSymbolAddress(&vh, g_vthi); cudaGetSymbolAddress(&vl, g_vtlo);

    cudaFuncSetAttribute(hgemm_k<0>, cudaFuncAttributeMaxDynamicSharedMemorySize, HG_SMEM);
    cudaFuncSetAttribute(hgemm_k<1>, cudaFuncAttributeMaxDynamicSharedMemorySize, HG_SMEM);
    cudaFuncSetAttribute(attn_mma, cudaFuncAttributeMaxDynamicSharedMemorySize, A_SMEM);

    pos_split<<<256, 256>>>();
    vbrel_k<<<128, 256>>>(v_bias);
    split_bhsd<<<2048, 256>>>(key, (__nv_bfloat16*)kh, (__nv_bfloat16*)kl);

    dim3 ggrid(DM/128, (NB*SEQ)/128);
    hgemm_k<1><<<ggrid, 256, HG_SMEM>>>(query, Wq, bq, nullptr,
        (__nv_bfloat16*)qh, (__nv_bfloat16*)ql, NB*SEQ, DM);
    hgemm_k<0><<<ggrid, 256, HG_SMEM>>>(value, Wv, bv, (float*)vp,
        nullptr, nullptr, NB*SEQ, DM);
    vtsplit<<<512, 256>>>((const float*)vp, (__nv_bfloat16*)vh, (__nv_bfloat16*)vl);

    dim3 agrid(SEQ/128, NH, NB);
    attn_mma<<<agrid, 256, A_SMEM>>>();

    hgemm_k<0><<<ggrid, 256, HG_SMEM>>>((const float*)xp, Wo, bo, out,
        nullptr, nullptr, NB*SEQ, DM);
}

// round 8
// speedup vs baseline: 2.2540x; 1.0256x over previous
#include <cuda_runtime.h>
#include <cuda_bf16.h>
#include <math.h>
#include <stdint.h>

#define SEQ 1024
#define DM  1024
#define NH  16
#define HD  64
#define NB  2
#define GK  1024

__device__ float g_x[NB*SEQ*DM];
__device__ float g_posf[2*SEQ*HD];
__device__ float g_vbrel[NH*2*SEQ + 32];
__device__ __nv_bfloat16 g_qhi[NB*NH*SEQ*HD], g_qlo[NB*NH*SEQ*HD];
__device__ __nv_bfloat16 g_khi[NB*NH*SEQ*HD], g_klo[NB*NH*SEQ*HD];
__device__ __nv_bfloat16 g_vthi[NB*NH*HD*SEQ], g_vtlo[NB*NH*HD*SEQ];
__device__ __nv_bfloat16 g_poshi[(2*SEQ+1)*HD], g_poslo[(2*SEQ+1)*HD];

__device__ __forceinline__ uint32_t smem_u32(const void* p) {
    uint32_t a;
    asm("{ .reg .u64 t; cvta.to.shared.u64 t, %1; cvt.u32.u64 %0, t; }" : "=r"(a) : "l"(p));
    return a;
}
__device__ __forceinline__ void ldsm_x4(uint32_t (&r)[4], uint32_t addr) {
    asm volatile("ldmatrix.sync.aligned.m8n8.x4.shared.b16 {%0,%1,%2,%3}, [%4];"
        : "=r"(r[0]), "=r"(r[1]), "=r"(r[2]), "=r"(r[3]) : "r"(addr));
}
__device__ __forceinline__ void mma_bf16(float (&d)[4], const uint32_t (&a)[4],
                                         uint32_t b0, uint32_t b1) {
    asm volatile("mma.sync.aligned.m16n8k16.row.col.f32.bf16.bf16.f32 "
        "{%0,%1,%2,%3}, {%4,%5,%6,%7}, {%8,%9}, {%0,%1,%2,%3};"
        : "+f"(d[0]), "+f"(d[1]), "+f"(d[2]), "+f"(d[3])
        : "r"(a[0]), "r"(a[1]), "r"(a[2]), "r"(a[3]), "r"(b0), "r"(b1));
}
__device__ __forceinline__ void split_sts(float4 v, char* hi, char* lo, int byteoff) {
    __nv_bfloat162 h01 = __floats2bfloat162_rn(v.x, v.y);
    __nv_bfloat162 h23 = __floats2bfloat162_rn(v.z, v.w);
    float2 f01 = __bfloat1622float2(h01);
    float2 f23 = __bfloat1622float2(h23);
    __nv_bfloat162 l01 = __floats2bfloat162_rn(v.x - f01.x, v.y - f01.y);
    __nv_bfloat162 l23 = __floats2bfloat162_rn(v.z - f23.x, v.w - f23.y);
    *(uint2*)(hi + byteoff) = make_uint2(*(uint32_t*)&h01, *(uint32_t*)&h23);
    *(uint2*)(lo + byteoff) = make_uint2(*(uint32_t*)&l01, *(uint32_t*)&l23);
}
__device__ __forceinline__ uint32_t packsplit(float a, float b, uint32_t& lo) {
    __nv_bfloat162 hh = __floats2bfloat162_rn(a, b);
    float2 ff = __bfloat1622float2(hh);
    __nv_bfloat162 ll = __floats2bfloat162_rn(a - ff.x, b - ff.y);
    lo = *(uint32_t*)&ll;
    return *(uint32_t*)&hh;
}
__device__ __forceinline__ void split1(float v, __nv_bfloat16& hi, __nv_bfloat16& lo) {
    hi = __float2bfloat16_rn(v);
    lo = __float2bfloat16_rn(v - __bfloat162float(hi));
}

// pos tables
__global__ void pos_split() {
    int idx = blockIdx.x * 256 + threadIdx.x;   // 65536
    int l = idx >> 5, j = idx & 31;
    float p = (float)(l - SEQ);
    const double negc = -log(10000.0) / 31.0;
    float ang = p * (float)exp((double)j * negc);
    float s = (float)sin((double)ang), c = (float)cos((double)ang);
    g_posf[l*64 + j]      = s;
    g_posf[l*64 + j + 32] = c;
    __nv_bfloat16 hh, ll;
    split1(s, hh, ll); g_poshi[l*64+j] = hh;      g_poslo[l*64+j] = ll;
    split1(c, hh, ll); g_poshi[l*64+j+32] = hh;   g_poslo[l*64+j+32] = ll;
}
__global__ void vbrel_k(const float* __restrict__ vb) {
    int idx = blockIdx.x * 256 + threadIdx.x;   // 32768
    int l = idx >> 4, h = idx & 15;
    float s = 0.f;
    #pragma unroll 8
    for (int d = 0; d < HD; d++) s = fmaf(__ldg(vb + h*HD + d), g_posf[l*64 + d], s);
    g_vbrel[h*2048 + l] = s;
}
__global__ void split_bhsd(const float* __restrict__ src,
                           __nv_bfloat16* __restrict__ hi, __nv_bfloat16* __restrict__ lo) {
    int idx = blockIdx.x * 256 + threadIdx.x;
    float4 v = ((const float4*)src)[idx];
    int c = idx & 255, s = (idx >> 8) & 1023, b = idx >> 18;
    size_t o = ((size_t)(b*NH + (c >> 4))*SEQ + s)*HD + (c & 15)*4;
    split_sts(v, (char*)(hi + o), (char*)(lo + o), 0);
}

// ---------------- 512-thread bf16x2-split GEMM core ----------------
#define TSTRIDE 40
#define TILE_B  (128 * TSTRIDE * 2)
#define BUF_B   (4 * TILE_B)
#define HG_SMEM (2 * BUF_B)

__device__ __forceinline__ void gemm_core512(
    const float* __restrict__ Ap, const float* __restrict__ Bp,
    char* smraw, uint32_t sbase, int tid, int lane, int wm, int wn,
    float acc[2][4][4])
{
    const int lr = tid >> 2, lc = (tid & 3) * 8;
    const int bo = (lr*TSTRIDE + lc) * 2;
    const int a_r = lane & 15, a_c = (lane >> 4) << 3;
    const int b_r = (lane & 7) + ((lane & 16) >> 1), b_c = lane & 8;

    float4 av[2], bv[2];
    #pragma unroll
    for (int q = 0; q < 2; q++) {
        av[q] = *(const float4*)(Ap + lr*GK + lc + 4*q);
        bv[q] = *(const float4*)(Bp + lr*GK + lc + 4*q);
    }
    #pragma unroll
    for (int q = 0; q < 2; q++) {
        split_sts(av[q], smraw,            smraw + TILE_B,   bo + 8*q);
        split_sts(bv[q], smraw + 2*TILE_B, smraw + 3*TILE_B, bo + 8*q);
    }
    __syncthreads();

    for (int kt = 0; kt < 32; kt++) {
        if (kt < 31) {
            #pragma unroll
            for (int q = 0; q < 2; q++) {
                av[q] = *(const float4*)(Ap + lr*GK + (kt+1)*32 + lc + 4*q);
                bv[q] = *(const float4*)(Bp + lr*GK + (kt+1)*32 + lc + 4*q);
            }
        }
        const uint32_t base = sbase + (kt & 1) * BUF_B;
        #pragma unroll
        for (int kk = 0; kk < 2; kk++) {
            const int koff = kk * 16;
            uint32_t ah[2][4], al[2][4];
            #pragma unroll
            for (int i = 0; i < 2; i++) {
                const uint32_t off = (uint32_t)(((wm*32 + i*16 + a_r)*TSTRIDE + koff + a_c) * 2);
                ldsm_x4(ah[i], base + off);
                ldsm_x4(al[i], base + TILE_B + off);
            }
            uint32_t bh[2][4], bl[2][4];
            #pragma unroll
            for (int p = 0; p < 2; p++) {
                const uint32_t off = (uint32_t)(((wn*32 + p*16 + b_r)*TSTRIDE + koff + b_c) * 2);
                ldsm_x4(bh[p], base + 2*TILE_B + off);
                ldsm_x4(bl[p], base + 3*TILE_B + off);
            }
            #pragma unroll
            for (int i = 0; i < 2; i++)
                #pragma unroll
                for (int j = 0; j < 4; j++) {
                    const int p = j >> 1, s = (j & 1) * 2;
                    mma_bf16(acc[i][j], ah[i], bh[p][s], bh[p][s+1]);
                    mma_bf16(acc[i][j], ah[i], bl[p][s], bl[p][s+1]);
                    mma_bf16(acc[i][j], al[i], bh[p][s], bh[p][s+1]);
                }
        }
        if (kt < 31) {
            char* hA = smraw + ((kt+1) & 1) * BUF_B;
            #pragma unroll
            for (int q = 0; q < 2; q++) {
                split_sts(av[q], hA,            hA + TILE_B,   bo + 8*q);
                split_sts(bv[q], hA + 2*TILE_B, hA + 3*TILE_B, bo + 8*q);
            }
            __syncthreads();
        }
    }
}

// merged Q/V projection: z=0 -> Q split (b,h,s,d); z=1 -> V split transposed (b,h,d,s)
__global__ __launch_bounds__(512) void qv_gemm512(
    const float* __restrict__ query, const float* __restrict__ value,
    const float* __restrict__ Wq, const float* __restrict__ Wv,
    const float* __restrict__ bq, const float* __restrict__ bv)
{
    extern __shared__ __align__(16) char smraw[];
    const int tid = threadIdx.x, lane = tid & 31, wid = tid >> 5;
    const int wm = wid & 3, wn = wid >> 2;
    const int row0 = blockIdx.y * 128, col0 = blockIdx.x * 128;
    const int z = blockIdx.z;
    const float* A = (z ? value : query) + (size_t)row0 * GK;
    const float* B = (z ? Wv : Wq) + (size_t)col0 * GK;
    const float* bias = z ? bv : bq;

    float acc[2][4][4];
    #pragma unroll
    for (int i = 0; i < 2; i++)
        #pragma unroll
        for (int j = 0; j < 4; j++)
            #pragma unroll
            for (int c = 0; c < 4; c++) acc[i][j][c] = 0.f;

    gemm_core512(A, B, smraw, smem_u32(smraw), tid, lane, wm, wn, acc);

    const int grp = lane >> 2, qid = lane & 3;
    #pragma unroll
    for (int j = 0; j < 4; j++) {
        const int col = col0 + wn*32 + j*8 + qid*2;
        const float2 bj = *(const float2*)(bias + col);
        const int h = col >> 6, d = col & 63;
        #pragma unroll
        for (int i = 0; i < 2; i++) {
            const int row = row0 + wm*32 + i*16 + grp;
            const int b = row >> 10, s = row & 1023;
            float v0 = acc[i][j][0]+bj.x, v1 = acc[i][j][1]+bj.y;
            float v2 = acc[i][j][2]+bj.x, v3 = acc[i][j][3]+bj.y;
            if (z == 0) {
                size_t o = (((size_t)(b*NH + h))*SEQ + s)*HD + d;
                uint32_t lo0, lo1;
                uint32_t hi0 = packsplit(v0, v1, lo0);
                uint32_t hi1 = packsplit(v2, v3, lo1);
                *(uint32_t*)(g_qhi + o) = hi0;        *(uint32_t*)(g_qlo + o) = lo0;
                *(uint32_t*)(g_qhi + o + 8*HD) = hi1; *(uint32_t*)(g_qlo + o + 8*HD) = lo1;
            } else {
                size_t o = (((size_t)(b*NH + h))*HD + d)*SEQ + s;
                __nv_bfloat16 hh, ll;
                split1(v0, hh, ll); g_vthi[o] = hh;          g_vtlo[o] = ll;
                split1(v1, hh, ll); g_vthi[o+SEQ] = hh;      g_vtlo[o+SEQ] = ll;
                split1(v2, hh, ll); g_vthi[o+8] = hh;        g_vtlo[o+8] = ll;
                split1(v3, hh, ll); g_vthi[o+SEQ+8] = hh;    g_vtlo[o+SEQ+8] = ll;
            }
        }
    }
}

// output GEMM: fp32 C (+bias)
__global__ __launch_bounds__(512) void o_gemm512(
    const float* __restrict__ A, const float* __restrict__ B,
    const float* __restrict__ bias, float* __restrict__ C)
{
    extern __shared__ __align__(16) char smraw[];
    const int tid = threadIdx.x, lane = tid & 31, wid = tid >> 5;
    const int wm = wid & 3, wn = wid >> 2;
    const int row0 = blockIdx.y * 128, col0 = blockIdx.x * 128;

    float acc[2][4][4];
    #pragma unroll
    for (int i = 0; i < 2; i++)
        #pragma unroll
        for (int j = 0; j < 4; j++)
            #pragma unroll
            for (int c = 0; c < 4; c++) acc[i][j][c] = 0.f;

    gemm_core512(A + (size_t)row0*GK, B + (size_t)col0*GK,
                 smraw, smem_u32(smraw), tid, lane, wm, wn, acc);

    const int grp = lane >> 2, qid = lane & 3;
    #pragma unroll
    for (int j = 0; j < 4; j++) {
        const int col = col0 + wn*32 + j*8 + qid*2;
        const float2 bj = *(const float2*)(bias + col);
        #pragma unroll
        for (int i = 0; i < 2; i++) {
            const int row = row0 + wm*32 + i*16 + grp;
            *(float2*)(C + (size_t)row*DM + col)     = make_float2(acc[i][j][0]+bj.x, acc[i][j][1]+bj.y);
            *(float2*)(C + (size_t)(row+8)*DM + col) = make_float2(acc[i][j][2]+bj.x, acc[i][j][3]+bj.y);
        }
    }
}

// --------- tensor-core fused attention with rolling R band (unchanged) ---------
#define RSTR 132
#define A_SMEM 201728

__global__ __launch_bounds__(256, 1) void attn_mma()
{
    extern __shared__ __align__(16) char sm[];
    float* Rb[2] = { (float*)(sm + 65536), (float*)(sm + 133120) };
    float* vbp   = (float*)(sm + 200704);
    const int tid = threadIdx.x, lane = tid & 31, wid = tid >> 5;
    const int grp = lane >> 2, qid = lane & 3;
    const int q0 = blockIdx.x*128, h = blockIdx.y, b = blockIdx.z, bh = b*NH + h;
    const uint32_t sbQ = smem_u32(sm), sbS = sbQ + 32768;
    const int wm = wid & 1, wn = wid >> 1;
    const int u0w = wid*16, r0 = u0w + grp;
    const int lmin0 = SEQ - q0 - 127;

    {   // Q stage
        const uint4* sh = (const uint4*)(g_qhi + ((size_t)bh*SEQ + q0)*HD);
        const uint4* sl = (const uint4*)(g_qlo + ((size_t)bh*SEQ + q0)*HD);
        #pragma unroll
        for (int r = 0; r < 4; r++) {
            int idx = tid + r*256, row = idx >> 3, c = idx & 7;
            int off = row*128 + ((c ^ (row & 7)) << 4);
            *(uint4*)(sm + off) = sh[idx];
            *(uint4*)(sm + 16384 + off) = sl[idx];
        }
    }
    float O[8][4];
    #pragma unroll
    for (int j = 0; j < 8; j++) { O[j][0]=0;O[j][1]=0;O[j][2]=0;O[j][3]=0; }
    float mr0 = -INFINITY, mr1 = -INFINITY, lr0 = 0.f, lr1 = 0.f;

    for (int kt = 0; kt < 8; kt++) {
        const int k0 = kt*128;
        const int g0 = (kt == 0) ? 0 : kt + 1;
        for (int g = g0; g <= kt + 1; g++) {
            const int slot = g & 1, l0 = lmin0 + 128*g;
            __syncthreads();
            {
                const uint4* sh = (const uint4*)(g_poshi + (size_t)l0*HD);
                const uint4* sl = (const uint4*)(g_poslo + (size_t)l0*HD);
                #pragma unroll
                for (int r = 0; r < 4; r++) {
                    int idx = tid + r*256, row = idx >> 3, c = idx & 7;
                    int off = 32768 + row*128 + ((c ^ (row & 7)) << 4);
                    *(uint4*)(sm + off) = sh[idx];
                    *(uint4*)(sm + 16384 + off) = sl[idx];
                }
                if (tid < 128) vbp[slot*128 + tid] = g_vbrel[h*2048 + l0 + tid];
            }
            __syncthreads();
            float rc[4][4][4];
            #pragma unroll
            for (int i = 0; i < 4; i++)
                #pragma unroll
                for (int j = 0; j < 4; j++) { rc[i][j][0]=0;rc[i][j][1]=0;rc[i][j][2]=0;rc[i][j][3]=0; }
            #pragma unroll
            for (int kb = 0; kb < 4; kb++) {
                uint32_t ah[4][4], al[4][4];
                #pragma unroll
                for (int i = 0; i < 4; i++) {
                    uint32_t ao = (uint32_t)((wm*64 + i*16 + (lane&15))*128
                                 + (((kb*2 + (lane>>4)) ^ (lane&7)) << 4));
                    ldsm_x4(ah[i], sbQ + ao);
                    ldsm_x4(al[i], sbQ + 16384 + ao);
                }
                uint32_t bh2[2][4], bl2[2][4];
                #pragma unroll
                for (int jp = 0; jp < 2; jp++) {
                    uint32_t bo = (uint32_t)((wn*32 + jp*16 + (lane&7) + ((lane&16)>>1))*128
                                 + (((kb*2 + ((lane&8)>>3)) ^ (lane&7)) << 4));
                    ldsm_x4(bh2[jp], sbS + bo);
                    ldsm_x4(bl2[jp], sbS + 16384 + bo);
                }
                #pragma unroll
                for (int i = 0; i < 4; i++)
                    #pragma unroll
                    for (int j = 0; j < 4; j++) {
                        const int jp = j >> 1, s = (j & 1)*2;
                        mma_bf16(rc[i][j], ah[i], bh2[jp][s], bh2[jp][s+1]);
                        mma_bf16(rc[i][j], ah[i], bl2[jp][s], bl2[jp][s+1]);
                        mma_bf16(rc[i][j], al[i], bh2[jp][s], bh2[jp][s+1]);
                    }
            }
            float* R = Rb[slot];
            #pragma unroll
            for (int i = 0; i < 4; i++) {
                const int u = wm*64 + i*16 + grp;
                #pragma unroll
                for (int j = 0; j < 4; j++) {
                    const int l = wn*32 + j*8 + qid*2;
                    float v0 = vbp[slot*128 + l], v1 = vbp[slot*128 + l + 1];
                    *(float2*)&R[u*RSTR + l]     = make_float2(rc[i][j][0]+v0, rc[i][j][1]+v1);
                    *(float2*)&R[(u+8)*RSTR + l] = make_float2(rc[i][j][2]+v0, rc[i][j][3]+v1);
                }
            }
        }

        __syncthreads();
        {   // K stage
            const uint4* sh = (const uint4*)(g_khi + ((size_t)bh*SEQ + k0)*HD);
            const uint4* sl = (const uint4*)(g_klo + ((size_t)bh*SEQ + k0)*HD);
            #pragma unroll
            for (int r = 0; r < 4; r++) {
                int idx = tid + r*256, row = idx >> 3, c = idx & 7;
                int off = 32768 + row*128 + ((c ^ (row & 7)) << 4);
                *(uint4*)(sm + off) = sh[idx];
                *(uint4*)(sm + 16384 + off) = sl[idx];
            }
        }
        __syncthreads();

        float aq[16][4];
        #pragma unroll
        for (int j = 0; j < 16; j++) { aq[j][0]=0;aq[j][1]=0;aq[j][2]=0;aq[j][3]=0; }
        #pragma unroll
        for (int kb = 0; kb < 4; kb++) {
            uint32_t ah[4], al[4];
            uint32_t ao = (uint32_t)((u0w + (lane&15))*128
                         + (((kb*2 + (lane>>4)) ^ (lane&7)) << 4));
            ldsm_x4(ah, sbQ + ao);
            ldsm_x4(al, sbQ + 16384 + ao);
            #pragma unroll
            for (int jp = 0; jp < 8; jp++) {
                uint32_t bh4[4], bl4[4];
                uint32_t bo = (uint32_t)((jp*16 + (lane&7) + ((lane&16)>>1))*128
                             + (((kb*2 + ((lane&8)>>3)) ^ (lane&7)) << 4));
                ldsm_x4(bh4, sbS + bo);
                ldsm_x4(bl4, sbS + 16384 + bo);
                #pragma unroll
                for (int jj = 0; jj < 2; jj++) {
                    const int j = jp*2 + jj, s = jj*2;
                    mma_bf16(aq[j], ah, bh4[s], bh4[s+1]);
                    mma_bf16(aq[j], ah, bl4[s], bl4[s+1]);
                    mma_bf16(aq[j], al, bh4[s], bh4[s+1]);
                }
            }
        }

        const float* RA = Rb[kt & 1];
        const float* RBf = Rb[(kt + 1) & 1];
        float m0 = -INFINITY, m1 = -INFINITY;
        #pragma unroll
        for (int j = 0; j < 16; j++) {
            const int w = j*8 + qid*2;
            const int ma = 127 + w - r0, mb = ma - 8;
            aq[j][0] += (ma < 128)   ? RA[r0*RSTR + ma]           : RBf[r0*RSTR + ma - 128];
            aq[j][1] += (ma+1 < 128) ? RA[r0*RSTR + ma + 1]       : RBf[r0*RSTR + ma - 127];
            aq[j][2] += (mb < 128)   ? RA[(r0+8)*RSTR + mb]       : RBf[(r0+8)*RSTR + mb - 128];
            aq[j][3] += (mb+1 < 128) ? RA[(r0+8)*RSTR + mb + 1]   : RBf[(r0+8)*RSTR + mb - 127];
            m0 = fmaxf(m0, fmaxf(aq[j][0], aq[j][1]));
            m1 = fmaxf(m1, fmaxf(aq[j][2], aq[j][3]));
        }
        m0 = fmaxf(m0, __shfl_xor_sync(~0u, m0, 1));
        m0 = fmaxf(m0, __shfl_xor_sync(~0u, m0, 2));
        m1 = fmaxf(m1, __shfl_xor_sync(~0u, m1, 1));
        m1 = fmaxf(m1, __shfl_xor_sync(~0u, m1, 2));
        const float mn0 = fmaxf(mr0, m0), mn1 = fmaxf(mr1, m1);
        const float scl0 = __expf(mr0 - mn0), scl1 = __expf(mr1 - mn1);
        mr0 = mn0; mr1 = mn1;

        uint32_t phi[8][4], plo[8][4];
        float s0 = 0.f, s1 = 0.f;
        #pragma unroll
        for (int j = 0; j < 16; j++) {
            float p0 = __expf(aq[j][0]-mn0), p1 = __expf(aq[j][1]-mn0);
            float p2 = __expf(aq[j][2]-mn1), p3 = __expf(aq[j][3]-mn1);
            s0 += p0 + p1; s1 += p2 + p3;
            const int kk = j >> 1, bs = (j & 1)*2;
            phi[kk][bs]   = packsplit(p0, p1, plo[kk][bs]);
            phi[kk][bs+1] = packsplit(p2, p3, plo[kk][bs+1]);
        }
        s0 += __shfl_xor_sync(~0u, s0, 1); s0 += __shfl_xor_sync(~0u, s0, 2);
        s1 += __shfl_xor_sync(~0u, s1, 1); s1 += __shfl_xor_sync(~0u, s1, 2);
        lr0 = lr0*scl0 + s0; lr1 = lr1*scl1 + s1;
        #pragma unroll
        for (int j = 0; j < 8; j++) {
            O[j][0] *= scl0; O[j][1] *= scl0; O[j][2] *= scl1; O[j][3] *= scl1;
        }

        __syncthreads();
        {   // Vt stage
            #pragma unroll
            for (int r = 0; r < 4; r++) {
                int idx = tid + r*256, d = idx >> 4, c = idx & 15;
                const uint4* sh = (const uint4*)(g_vthi + ((size_t)bh*HD + d)*SEQ + k0);
                const uint4* sl = (const uint4*)(g_vtlo + ((size_t)bh*HD + d)*SEQ + k0);
                int off = 32768 + d*256 + ((c ^ (d & 7)) << 4);
                *(uint4*)(sm + off) = sh[c];
                *(uint4*)(sm + 16384 + off) = sl[c];
            }
        }
        __syncthreads();

        #pragma unroll
        for (int kk = 0; kk < 8; kk++) {
            #pragma unroll
            for (int jp = 0; jp < 4; jp++) {
                uint32_t bh4[4], bl4[4];
                uint32_t bo = (uint32_t)((jp*16 + (lane&7) + ((lane&16)>>1))*256
                             + (((kk*2 + ((lane&8)>>3)) ^ (lane&7)) << 4));
                ldsm_x4(bh4, sbS + bo);
                ldsm_x4(bl4, sbS + 16384 + bo);
                #pragma unroll
                for (int jj = 0; jj < 2; jj++) {
                    const int j = jp*2 + jj, s = jj*2;
                    mma_bf16(O[j], phi[kk], bh4[s], bh4[s+1]);
                    mma_bf16(O[j], phi[kk], bl4[s], bl4[s+1]);
                    mma_bf16(O[j], plo[kk], bh4[s], bh4[s+1]);
                }
            }
        }
    }

    const float i0 = 1.f/lr0, i1 = 1.f/lr1;
    float* x0 = g_x + ((size_t)(b*SEQ + q0 + r0))*DM + h*HD;
    float* x1 = g_x + ((size_t)(b*SEQ + q0 + r0 + 8))*DM + h*HD;
    #pragma unroll
    for (int j = 0; j < 8; j++) {
        const int col = j*8 + qid*2;
        *(float2*)(x0 + col) = make_float2(O[j][0]*i0, O[j][1]*i0);
        *(float2*)(x1 + col) = make_float2(O[j][2]*i1, O[j][3]*i1);
    }
}

// ---------------------------------------------------------------------------
extern "C" void kernel_launch(void* const* d_in, const int* in_sizes, int n_in,
                              void* d_out, int out_size) {
    const float* query  = (const float*)d_in[0];
    const float* key    = (const float*)d_in[1];
    const float* value  = (const float*)d_in[2];
    const float* Wq     = (const float*)d_in[4];
    const float* bq     = (const float*)d_in[5];
    const float* Wv     = (const float*)d_in[6];
    const float* bv     = (const float*)d_in[7];
    const float* Wo     = (const float*)d_in[8];
    const float* bo     = (const float*)d_in[9];
    const float* v_bias = (const float*)d_in[10];
    float* out = (float*)d_out;

    void *xp, *kh, *kl;
    cudaGetSymbolAddress(&xp, g_x);
    cudaGetSymbolAddress(&kh, g_khi); cudaGetSymbolAddress(&kl, g_klo);

    cudaFuncSetAttribute(qv_gemm512, cudaFuncAttributeMaxDynamicSharedMemorySize, HG_SMEM);
    cudaFuncSetAttribute(o_gemm512, cudaFuncAttributeMaxDynamicSharedMemorySize, HG_SMEM);
    cudaFuncSetAttribute(attn_mma, cudaFuncAttributeMaxDynamicSharedMemorySize, A_SMEM);

    pos_split<<<256, 256>>>();
    vbrel_k<<<128, 256>>>(v_bias);
    split_bhsd<<<2048, 256>>>(key, (__nv_bfloat16*)kh, (__nv_bfloat16*)kl);

    dim3 qvgrid(DM/128, (NB*SEQ)/128, 2);
    qv_gemm512<<<qvgrid, 512, HG_SMEM>>>(query, value, Wq, Wv, bq, bv);

    dim3 agrid(SEQ/128, NH, NB);
    attn_mma<<<agrid, 256, A_SMEM>>>();

    dim3 ogrid(DM/128, (NB*SEQ)/128);
    o_gemm512<<<ogrid, 512, HG_SMEM>>>((const float*)xp, Wo, bo, out);
}

// round 9
// speedup vs baseline: 2.3180x; 1.0284x over previous
#include <cuda_runtime.h>
#include <cuda_bf16.h>
#include <math.h>
#include <stdint.h>

#define SEQ 1024
#define DM  1024
#define NH  16
#define HD  64
#define NB  2
#define GK  1024

__device__ float g_x[NB*SEQ*DM];
__device__ float g_posf[2*SEQ*HD];
__device__ float g_vbrel[NH*2*SEQ + 32];
__device__ __nv_bfloat16 g_qhi[NB*NH*SEQ*HD], g_qlo[NB*NH*SEQ*HD];
__device__ __nv_bfloat16 g_khi[NB*NH*SEQ*HD], g_klo[NB*NH*SEQ*HD];
__device__ __nv_bfloat16 g_vthi[NB*NH*HD*SEQ], g_vtlo[NB*NH*HD*SEQ];
__device__ __nv_bfloat16 g_poshi[(2*SEQ+1)*HD], g_poslo[(2*SEQ+1)*HD];

__device__ __forceinline__ uint32_t smem_u32(const void* p) {
    uint32_t a;
    asm("{ .reg .u64 t; cvta.to.shared.u64 t, %1; cvt.u32.u64 %0, t; }" : "=r"(a) : "l"(p));
    return a;
}
__device__ __forceinline__ void ldsm_x4(uint32_t (&r)[4], uint32_t addr) {
    asm volatile("ldmatrix.sync.aligned.m8n8.x4.shared.b16 {%0,%1,%2,%3}, [%4];"
        : "=r"(r[0]), "=r"(r[1]), "=r"(r[2]), "=r"(r[3]) : "r"(addr));
}
__device__ __forceinline__ void mma_bf16(float (&d)[4], const uint32_t (&a)[4],
                                         uint32_t b0, uint32_t b1) {
    asm volatile("mma.sync.aligned.m16n8k16.row.col.f32.bf16.bf16.f32 "
        "{%0,%1,%2,%3}, {%4,%5,%6,%7}, {%8,%9}, {%0,%1,%2,%3};"
        : "+f"(d[0]), "+f"(d[1]), "+f"(d[2]), "+f"(d[3])
        : "r"(a[0]), "r"(a[1]), "r"(a[2]), "r"(a[3]), "r"(b0), "r"(b1));
}
__device__ __forceinline__ void cpa16(uint32_t dst, const void* src) {
    asm volatile("cp.async.cg.shared.global [%0], [%1], 16;" :: "r"(dst), "l"(src));
}
#define CP_COMMIT() asm volatile("cp.async.commit_group;" ::: "memory")
#define CP_WAIT0()  asm volatile("cp.async.wait_group 0;" ::: "memory")

__device__ __forceinline__ void split_sts(float4 v, char* hi, char* lo, int byteoff) {
    __nv_bfloat162 h01 = __floats2bfloat162_rn(v.x, v.y);
    __nv_bfloat162 h23 = __floats2bfloat162_rn(v.z, v.w);
    float2 f01 = __bfloat1622float2(h01);
    float2 f23 = __bfloat1622float2(h23);
    __nv_bfloat162 l01 = __floats2bfloat162_rn(v.x - f01.x, v.y - f01.y);
    __nv_bfloat162 l23 = __floats2bfloat162_rn(v.z - f23.x, v.w - f23.y);
    *(uint2*)(hi + byteoff) = make_uint2(*(uint32_t*)&h01, *(uint32_t*)&h23);
    *(uint2*)(lo + byteoff) = make_uint2(*(uint32_t*)&l01, *(uint32_t*)&l23);
}
__device__ __forceinline__ uint32_t packsplit(float a, float b, uint32_t& lo) {
    __nv_bfloat162 hh = __floats2bfloat162_rn(a, b);
    float2 ff = __bfloat1622float2(hh);
    __nv_bfloat162 ll = __floats2bfloat162_rn(a - ff.x, b - ff.y);
    lo = *(uint32_t*)&ll;
    return *(uint32_t*)&hh;
}
__device__ __forceinline__ void split1(float v, __nv_bfloat16& hi, __nv_bfloat16& lo) {
    hi = __float2bfloat16_rn(v);
    lo = __float2bfloat16_rn(v - __bfloat162float(hi));
}

// ---------------- prep kernels ----------------
__global__ void pos_split() {
    int idx = blockIdx.x * 256 + threadIdx.x;   // 65536
    int l = idx >> 5, j = idx & 31;
    float p = (float)(l - SEQ);
    const double negc = -log(10000.0) / 31.0;
    float ang = p * (float)exp((double)j * negc);
    float s = (float)sin((double)ang), c = (float)cos((double)ang);
    g_posf[l*64 + j]      = s;
    g_posf[l*64 + j + 32] = c;
    __nv_bfloat16 hh, ll;
    split1(s, hh, ll); g_poshi[l*64+j] = hh;      g_poslo[l*64+j] = ll;
    split1(c, hh, ll); g_poshi[l*64+j+32] = hh;   g_poslo[l*64+j+32] = ll;
}
__global__ void vbrel_k(const float* __restrict__ vb) {
    int idx = blockIdx.x * 256 + threadIdx.x;   // 32768
    int l = idx >> 4, h = idx & 15;
    float s = 0.f;
    #pragma unroll 8
    for (int d = 0; d < HD; d++) s = fmaf(__ldg(vb + h*HD + d), g_posf[l*64 + d], s);
    g_vbrel[h*2048 + l] = s;
}
__global__ void split_bhsd(const float* __restrict__ src,
                           __nv_bfloat16* __restrict__ hi, __nv_bfloat16* __restrict__ lo) {
    int idx = blockIdx.x * 256 + threadIdx.x;
    float4 v = ((const float4*)src)[idx];
    int c = idx & 255, s = (idx >> 8) & 1023, b = idx >> 18;
    size_t o = ((size_t)(b*NH + (c >> 4))*SEQ + s)*HD + (c & 15)*4;
    split_sts(v, (char*)(hi + o), (char*)(lo + o), 0);
}

// ---------------- 512-thread bf16x2-split GEMM core ----------------
#define TSTRIDE 40
#define TILE_B  (128 * TSTRIDE * 2)
#define BUF_B   (4 * TILE_B)
#define HG_SMEM (2 * BUF_B)

__device__ __forceinline__ void gemm_core512(
    const float* __restrict__ Ap, const float* __restrict__ Bp,
    char* smraw, uint32_t sbase, int tid, int lane, int wm, int wn,
    float acc[2][4][4])
{
    const int lr = tid >> 2, lc = (tid & 3) * 8;
    const int bo = (lr*TSTRIDE + lc) * 2;
    const int a_r = lane & 15, a_c = (lane >> 4) << 3;
    const int b_r = (lane & 7) + ((lane & 16) >> 1), b_c = lane & 8;

    float4 av[2], bv[2];
    #pragma unroll
    for (int q = 0; q < 2; q++) {
        av[q] = *(const float4*)(Ap + lr*GK + lc + 4*q);
        bv[q] = *(const float4*)(Bp + lr*GK + lc + 4*q);
    }
    #pragma unroll
    for (int q = 0; q < 2; q++) {
        split_sts(av[q], smraw,            smraw + TILE_B,   bo + 8*q);
        split_sts(bv[q], smraw + 2*TILE_B, smraw + 3*TILE_B, bo + 8*q);
    }
    __syncthreads();

    for (int kt = 0; kt < 32; kt++) {
        if (kt < 31) {
            #pragma unroll
            for (int q = 0; q < 2; q++) {
                av[q] = *(const float4*)(Ap + lr*GK + (kt+1)*32 + lc + 4*q);
                bv[q] = *(const float4*)(Bp + lr*GK + (kt+1)*32 + lc + 4*q);
            }
        }
        const uint32_t base = sbase + (kt & 1) * BUF_B;
        #pragma unroll
        for (int kk = 0; kk < 2; kk++) {
            const int koff = kk * 16;
            uint32_t ah[2][4], al[2][4];
            #pragma unroll
            for (int i = 0; i < 2; i++) {
                const uint32_t off = (uint32_t)(((wm*32 + i*16 + a_r)*TSTRIDE + koff + a_c) * 2);
                ldsm_x4(ah[i], base + off);
                ldsm_x4(al[i], base + TILE_B + off);
            }
            uint32_t bh[2][4], bl[2][4];
            #pragma unroll
            for (int p = 0; p < 2; p++) {
                const uint32_t off = (uint32_t)(((wn*32 + p*16 + b_r)*TSTRIDE + koff + b_c) * 2);
                ldsm_x4(bh[p], base + 2*TILE_B + off);
                ldsm_x4(bl[p], base + 3*TILE_B + off);
            }
            #pragma unroll
            for (int i = 0; i < 2; i++)
                #pragma unroll
                for (int j = 0; j < 4; j++) {
                    const int p = j >> 1, s = (j & 1) * 2;
                    mma_bf16(acc[i][j], ah[i], bh[p][s], bh[p][s+1]);
                    mma_bf16(acc[i][j], ah[i], bl[p][s], bl[p][s+1]);
                    mma_bf16(acc[i][j], al[i], bh[p][s], bh[p][s+1]);
                }
        }
        if (kt < 31) {
            char* hA = smraw + ((kt+1) & 1) * BUF_B;
            #pragma unroll
            for (int q = 0; q < 2; q++) {
                split_sts(av[q], hA,            hA + TILE_B,   bo + 8*q);
                split_sts(bv[q], hA + 2*TILE_B, hA + 3*TILE_B, bo + 8*q);
            }
            __syncthreads();
        }
    }
}

__global__ __launch_bounds__(512) void qv_gemm512(
    const float* __restrict__ query, const float* __restrict__ value,
    const float* __restrict__ Wq, const float* __restrict__ Wv,
    const float* __restrict__ bq, const float* __restrict__ bv)
{
    extern __shared__ __align__(16) char smraw[];
    const int tid = threadIdx.x, lane = tid & 31, wid = tid >> 5;
    const int wm = wid & 3, wn = wid >> 2;
    const int row0 = blockIdx.y * 128, col0 = blockIdx.x * 128;
    const int z = blockIdx.z;
    const float* A = (z ? value : query) + (size_t)row0 * GK;
    const float* B = (z ? Wv : Wq) + (size_t)col0 * GK;
    const float* bias = z ? bv : bq;

    float acc[2][4][4];
    #pragma unroll
    for (int i = 0; i < 2; i++)
        #pragma unroll
        for (int j = 0; j < 4; j++)
            #pragma unroll
            for (int c = 0; c < 4; c++) acc[i][j][c] = 0.f;

    gemm_core512(A, B, smraw, smem_u32(smraw), tid, lane, wm, wn, acc);

    const int grp = lane >> 2, qid = lane & 3;
    #pragma unroll
    for (int j = 0; j < 4; j++) {
        const int col = col0 + wn*32 + j*8 + qid*2;
        const float2 bj = *(const float2*)(bias + col);
        const int h = col >> 6, d = col & 63;
        #pragma unroll
        for (int i = 0; i < 2; i++) {
            const int row = row0 + wm*32 + i*16 + grp;
            const int b = row >> 10, s = row & 1023;
            float v0 = acc[i][j][0]+bj.x, v1 = acc[i][j][1]+bj.y;
            float v2 = acc[i][j][2]+bj.x, v3 = acc[i][j][3]+bj.y;
            if (z == 0) {
                size_t o = (((size_t)(b*NH + h))*SEQ + s)*HD + d;
                uint32_t lo0, lo1;
                uint32_t hi0 = packsplit(v0, v1, lo0);
                uint32_t hi1 = packsplit(v2, v3, lo1);
                *(uint32_t*)(g_qhi + o) = hi0;        *(uint32_t*)(g_qlo + o) = lo0;
                *(uint32_t*)(g_qhi + o + 8*HD) = hi1; *(uint32_t*)(g_qlo + o + 8*HD) = lo1;
            } else {
                size_t o = (((size_t)(b*NH + h))*HD + d)*SEQ + s;
                __nv_bfloat16 hh, ll;
                split1(v0, hh, ll); g_vthi[o] = hh;          g_vtlo[o] = ll;
                split1(v1, hh, ll); g_vthi[o+SEQ] = hh;      g_vtlo[o+SEQ] = ll;
                split1(v2, hh, ll); g_vthi[o+8] = hh;        g_vtlo[o+8] = ll;
                split1(v3, hh, ll); g_vthi[o+SEQ+8] = hh;    g_vtlo[o+SEQ+8] = ll;
            }
        }
    }
}

__global__ __launch_bounds__(512) void o_gemm512(
    const float* __restrict__ A, const float* __restrict__ B,
    const float* __restrict__ bias, float* __restrict__ C)
{
    extern __shared__ __align__(16) char smraw[];
    const int tid = threadIdx.x, lane = tid & 31, wid = tid >> 5;
    const int wm = wid & 3, wn = wid >> 2;
    const int row0 = blockIdx.y * 128, col0 = blockIdx.x * 128;

    float acc[2][4][4];
    #pragma unroll
    for (int i = 0; i < 2; i++)
        #pragma unroll
        for (int j = 0; j < 4; j++)
            #pragma unroll
            for (int c = 0; c < 4; c++) acc[i][j][c] = 0.f;

    gemm_core512(A + (size_t)row0*GK, B + (size_t)col0*GK,
                 smraw, smem_u32(smraw), tid, lane, wm, wn, acc);

    const int grp = lane >> 2, qid = lane & 3;
    #pragma unroll
    for (int j = 0; j < 4; j++) {
        const int col = col0 + wn*32 + j*8 + qid*2;
        const float2 bj = *(const float2*)(bias + col);
        #pragma unroll
        for (int i = 0; i < 2; i++) {
            const int row = row0 + wm*32 + i*16 + grp;
            *(float2*)(C + (size_t)row*DM + col)     = make_float2(acc[i][j][0]+bj.x, acc[i][j][1]+bj.y);
            *(float2*)(C + (size_t)(row+8)*DM + col) = make_float2(acc[i][j][2]+bj.x, acc[i][j][3]+bj.y);
        }
    }
}

// --------- pipelined tensor-core fused attention ---------
// smem: Qhi 0 | Qlo 16384 | S0 32768 (hi/lo 16K each) | S1 65536 | R 98304 (2x66560)
#define RSTR 130
#define S0OFF 32768u
#define S1OFF 65536u
#define ROFF  98304
#define RSLOT 66560
#define A_SMEM 231424

// async stagers (row-major 128x64 bf16, XOR-swizzled 16B chunks)
__device__ __forceinline__ void stage_rows_async(
    uint32_t sb, uint32_t so, int tid,
    const __nv_bfloat16* hp, const __nv_bfloat16* lp)
{
    #pragma unroll
    for (int r = 0; r < 4; r++) {
        int idx = tid + r*256, row = idx >> 3, c = idx & 7;
        uint32_t off = so + row*128 + ((c ^ (row & 7)) << 4);
        cpa16(sb + off,         (const char*)hp + idx*16);
        cpa16(sb + off + 16384, (const char*)lp + idx*16);
    }
}
// Vt: 64 rows(d) x 128 bf16, row stride 256B
__device__ __forceinline__ void stage_vt_async(
    uint32_t sb, uint32_t so, int tid,
    const __nv_bfloat16* hp, const __nv_bfloat16* lp, int k0)
{
    #pragma unroll
    for (int r = 0; r < 4; r++) {
        int idx = tid + r*256, d = idx >> 4, c = idx & 15;
        uint32_t off = so + d*256 + ((c ^ (d & 7)) << 4);
        cpa16(sb + off,         (const char*)(hp + (size_t)d*SEQ + k0) + c*16);
        cpa16(sb + off + 16384, (const char*)(lp + (size_t)d*SEQ + k0) + c*16);
    }
}

// R-GEMM: Q[128x64] @ posband[128x64]^T -> R[128][RSTR] (+vbrel from global)
__device__ __forceinline__ void rgemm_band(
    uint32_t sb, uint32_t so, int lane, int wm, int wn, int grp, int qid,
    float* R, const float* __restrict__ vbg)
{
    float rc[4][4][4];
    #pragma unroll
    for (int i = 0; i < 4; i++)
        #pragma unroll
        for (int j = 0; j < 4; j++) { rc[i][j][0]=0;rc[i][j][1]=0;rc[i][j][2]=0;rc[i][j][3]=0; }
    #pragma unroll
    for (int kb = 0; kb < 4; kb++) {
        uint32_t ah[4][4], al[4][4];
        #pragma unroll
        for (int i = 0; i < 4; i++) {
            uint32_t ao = (uint32_t)((wm*64 + i*16 + (lane&15))*128
                         + (((kb*2 + (lane>>4)) ^ (lane&7)) << 4));
            ldsm_x4(ah[i], sb + ao);
            ldsm_x4(al[i], sb + 16384 + ao);
        }
        uint32_t bh2[2][4], bl2[2][4];
        #pragma unroll
        for (int jp = 0; jp < 2; jp++) {
            uint32_t bo = (uint32_t)((wn*32 + jp*16 + (lane&7) + ((lane&16)>>1))*128
                         + (((kb*2 + ((lane&8)>>3)) ^ (lane&7)) << 4));
            ldsm_x4(bh2[jp], sb + so + bo);
            ldsm_x4(bl2[jp], sb + so + 16384 + bo);
        }
        #pragma unroll
        for (int i = 0; i < 4; i++)
            #pragma unroll
            for (int j = 0; j < 4; j++) {
                const int jp = j >> 1, s = (j & 1)*2;
                mma_bf16(rc[i][j], ah[i], bh2[jp][s], bh2[jp][s+1]);
                mma_bf16(rc[i][j], ah[i], bl2[jp][s], bl2[jp][s+1]);
                mma_bf16(rc[i][j], al[i], bh2[jp][s], bh2[jp][s+1]);
            }
    }
    #pragma unroll
    for (int i = 0; i < 4; i++) {
        const int u = wm*64 + i*16 + grp;
        #pragma unroll
        for (int j = 0; j < 4; j++) {
            const int l = wn*32 + j*8 + qid*2;
            float v0 = __ldg(vbg + l), v1 = __ldg(vbg + l + 1);
            *(float2*)&R[u*RSTR + l]     = make_float2(rc[i][j][0]+v0, rc[i][j][1]+v1);
            *(float2*)&R[(u+8)*RSTR + l] = make_float2(rc[i][j][2]+v0, rc[i][j][3]+v1);
        }
    }
}

__global__ __launch_bounds__(256, 1) void attn_mma()
{
    extern __shared__ __align__(16) char sm[];
    float* Rb0 = (float*)(sm + ROFF);
    float* Rb1 = (float*)(sm + ROFF + RSLOT);
    const int tid = threadIdx.x, lane = tid & 31, wid = tid >> 5;
    const int grp = lane >> 2, qid = lane & 3;
    const int q0 = blockIdx.x*128, h = blockIdx.y, b = blockIdx.z, bh = b*NH + h;
    const uint32_t sb = smem_u32(sm);
    const int wm = wid & 1, wn = wid >> 1;
    const int u0w = wid*16, r0 = u0w + grp;
    const int lmin0 = SEQ - q0 - 127;
    const float* vbg = g_vbrel + h*2048;
    const __nv_bfloat16* khB = g_khi + (size_t)bh*SEQ*HD;
    const __nv_bfloat16* klB = g_klo + (size_t)bh*SEQ*HD;
    const __nv_bfloat16* vhB = g_vthi + (size_t)bh*HD*SEQ;
    const __nv_bfloat16* vlB = g_vtlo + (size_t)bh*HD*SEQ;

    {   // Q stage (sync, once)
        const uint4* sh = (const uint4*)(g_qhi + ((size_t)bh*SEQ + q0)*HD);
        const uint4* sl = (const uint4*)(g_qlo + ((size_t)bh*SEQ + q0)*HD);
        #pragma unroll
        for (int r = 0; r < 4; r++) {
            int idx = tid + r*256, row = idx >> 3, c = idx & 7;
            int off = row*128 + ((c ^ (row & 7)) << 4);
            *(uint4*)(sm + off) = sh[idx];
            *(uint4*)(sm + 16384 + off) = sl[idx];
        }
    }
    float O[8][4];
    #pragma unroll
    for (int j = 0; j < 8; j++) { O[j][0]=0;O[j][1]=0;O[j][2]=0;O[j][3]=0; }
    float mr0 = -INFINITY, mr1 = -INFINITY, lr0 = 0.f, lr1 = 0.f;

    // ---- prologue: band 0 & 1 R-GEMMs, K(0) prefetch ----
    stage_rows_async(sb, S0OFF, tid, g_poshi + (size_t)lmin0*HD, g_poslo + (size_t)lmin0*HD);
    CP_COMMIT(); CP_WAIT0(); __syncthreads();

    stage_rows_async(sb, S1OFF, tid, g_poshi + (size_t)(lmin0+128)*HD, g_poslo + (size_t)(lmin0+128)*HD);
    CP_COMMIT();
    rgemm_band(sb, S0OFF, lane, wm, wn, grp, qid, Rb0, vbg + lmin0);
    CP_WAIT0(); __syncthreads();

    stage_rows_async(sb, S0OFF, tid, khB, klB);   // K(0)
    CP_COMMIT();
    rgemm_band(sb, S1OFF, lane, wm, wn, grp, qid, Rb1, vbg + lmin0 + 128);
    CP_WAIT0(); __syncthreads();

    for (int kt = 0; kt < 8; kt++) {
        const int k0 = kt*128;
        const uint32_t kOff = (kt & 1) ? S1OFF : S0OFF;
        const uint32_t vOff = (kt & 1) ? S0OFF : S1OFF;

        if (kt > 0) {
            // phase A: K(kt) prefetch into kOff, R-GEMM band kt+1 from vOff
            stage_rows_async(sb, kOff, tid, khB + (size_t)k0*HD, klB + (size_t)k0*HD);
            CP_COMMIT();
            rgemm_band(sb, vOff, lane, wm, wn, grp, qid,
                       ((kt+1) & 1) ? Rb1 : Rb0, vbg + lmin0 + 128*(kt+1));
            CP_WAIT0(); __syncthreads();
        }

        // phase B: Vt(kt) prefetch into vOff, QK from kOff
        stage_vt_async(sb, vOff, tid, vhB, vlB, k0);
        CP_COMMIT();

        float aq[16][4];
        #pragma unroll
        for (int j = 0; j < 16; j++) { aq[j][0]=0;aq[j][1]=0;aq[j][2]=0;aq[j][3]=0; }
        #pragma unroll
        for (int kb = 0; kb < 4; kb++) {
            uint32_t ah[4], al[4];
            uint32_t ao = (uint32_t)((u0w + (lane&15))*128
                         + (((kb*2 + (lane>>4)) ^ (lane&7)) << 4));
            ldsm_x4(ah, sb + ao);
            ldsm_x4(al, sb + 16384 + ao);
            #pragma unroll
            for (int jp = 0; jp < 8; jp++) {
                uint32_t bh4[4], bl4[4];
                uint32_t bo = (uint32_t)((jp*16 + (lane&7) + ((lane&16)>>1))*128
                             + (((kb*2 + ((lane&8)>>3)) ^ (lane&7)) << 4));
                ldsm_x4(bh4, sb + kOff + bo);
                ldsm_x4(bl4, sb + kOff + 16384 + bo);
                #pragma unroll
                for (int jj = 0; jj < 2; jj++) {
                    const int j = jp*2 + jj, s = jj*2;
                    mma_bf16(aq[j], ah, bh4[s], bh4[s+1]);
                    mma_bf16(aq[j], ah, bl4[s], bl4[s+1]);
                    mma_bf16(aq[j], al, bh4[s], bh4[s+1]);
                }
            }
        }

        // rel gather + online softmax + pack P
        const float* RA  = (kt & 1) ? Rb1 : Rb0;
        const float* RBf = (kt & 1) ? Rb0 : Rb1;
        float m0 = -INFINITY, m1 = -INFINITY;
        #pragma unroll
        for (int j = 0; j < 16; j++) {
            const int w = j*8 + qid*2;
            const int ma = 127 + w - r0, mb = ma - 8;
            aq[j][0] += (ma < 128)   ? RA[r0*RSTR + ma]         : RBf[r0*RSTR + ma - 128];
            aq[j][1] += (ma+1 < 128) ? RA[r0*RSTR + ma + 1]     : RBf[r0*RSTR + ma - 127];
            aq[j][2] += (mb < 128)   ? RA[(r0+8)*RSTR + mb]     : RBf[(r0+8)*RSTR + mb - 128];
            aq[j][3] += (mb+1 < 128) ? RA[(r0+8)*RSTR + mb + 1] : RBf[(r0+8)*RSTR + mb - 127];
            m0 = fmaxf(m0, fmaxf(aq[j][0], aq[j][1]));
            m1 = fmaxf(m1, fmaxf(aq[j][2], aq[j][3]));
        }
        m0 = fmaxf(m0, __shfl_xor_sync(~0u, m0, 1));
        m0 = fmaxf(m0, __shfl_xor_sync(~0u, m0, 2));
        m1 = fmaxf(m1, __shfl_xor_sync(~0u, m1, 1));
        m1 = fmaxf(m1, __shfl_xor_sync(~0u, m1, 2));
        const float mn0 = fmaxf(mr0, m0), mn1 = fmaxf(mr1, m1);
        const float scl0 = __expf(mr0 - mn0), scl1 = __expf(mr1 - mn1);
        mr0 = mn0; mr1 = mn1;

        uint32_t phi[8][4], plo[8][4];
        float s0 = 0.f, s1 = 0.f;
        #pragma unroll
        for (int j = 0; j < 16; j++) {
            float p0 = __expf(aq[j][0]-mn0), p1 = __expf(aq[j][1]-mn0);
            float p2 = __expf(aq[j][2]-mn1), p3 = __expf(aq[j][3]-mn1);
            s0 += p0 + p1; s1 += p2 + p3;
            const int kk = j >> 1, bs = (j & 1)*2;
            phi[kk][bs]   = packsplit(p0, p1, plo[kk][bs]);
            phi[kk][bs+1] = packsplit(p2, p3, plo[kk][bs+1]);
        }
        s0 += __shfl_xor_sync(~0u, s0, 1); s0 += __shfl_xor_sync(~0u, s0, 2);
        s1 += __shfl_xor_sync(~0u, s1, 1); s1 += __shfl_xor_sync(~0u, s1, 2);
        lr0 = lr0*scl0 + s0; lr1 = lr1*scl1 + s1;
        #pragma unroll
        for (int j = 0; j < 8; j++) {
            O[j][0] *= scl0; O[j][1] *= scl0; O[j][2] *= scl1; O[j][3] *= scl1;
        }

        CP_WAIT0(); __syncthreads();

        // phase C: pos(band kt+2) prefetch into kOff, PV from vOff
        if (kt < 7) {
            const int l0n = lmin0 + 128*(kt+2);
            stage_rows_async(sb, kOff, tid, g_poshi + (size_t)l0n*HD, g_poslo + (size_t)l0n*HD);
            CP_COMMIT();
        }

        #pragma unroll
        for (int kk = 0; kk < 8; kk++) {
            #pragma unroll
            for (int jp = 0; jp < 4; jp++) {
                uint32_t bh4[4], bl4[4];
                uint32_t bo = (uint32_t)((jp*16 + (lane&7) + ((lane&16)>>1))*256
                             + (((kk*2 + ((lane&8)>>3)) ^ (lane&7)) << 4));
                ldsm_x4(bh4, sb + vOff + bo);
                ldsm_x4(bl4, sb + vOff + 16384 + bo);
                #pragma unroll
                for (int jj = 0; jj < 2; jj++) {
                    const int j = jp*2 + jj, s = jj*2;
                    mma_bf16(O[j], phi[kk], bh4[s], bh4[s+1]);
                    mma_bf16(O[j], phi[kk], bl4[s], bl4[s+1]);
                    mma_bf16(O[j], plo[kk], bh4[s], bh4[s+1]);
                }
            }
        }
        if (kt < 7) CP_WAIT0();
        __syncthreads();
    }

    const float i0 = 1.f/lr0, i1 = 1.f/lr1;
    float* x0 = g_x + ((size_t)(b*SEQ + q0 + r0))*DM + h*HD;
    float* x1 = g_x + ((size_t)(b*SEQ + q0 + r0 + 8))*DM + h*HD;
    #pragma unroll
    for (int j = 0; j < 8; j++) {
        const int col = j*8 + qid*2;
        *(float2*)(x0 + col) = make_float2(O[j][0]*i0, O[j][1]*i0);
        *(float2*)(x1 + col) = make_float2(O[j][2]*i1, O[j][3]*i1);
    }
}

// ---------------------------------------------------------------------------
extern "C" void kernel_launch(void* const* d_in, const int* in_sizes, int n_in,
                              void* d_out, int out_size) {
    const float* query  = (const float*)d_in[0];
    const float* key    = (const float*)d_in[1];
    const float* value  = (const float*)d_in[2];
    const float* Wq     = (const float*)d_in[4];
    const float* bq     = (const float*)d_in[5];
    const float* Wv     = (const float*)d_in[6];
    const float* bv     = (const float*)d_in[7];
    const float* Wo     = (const float*)d_in[8];
    const float* bo     = (const float*)d_in[9];
    const float* v_bias = (const float*)d_in[10];
    float* out = (float*)d_out;

    void *xp, *kh, *kl;
    cudaGetSymbolAddress(&xp, g_x);
    cudaGetSymbolAddress(&kh, g_khi); cudaGetSymbolAddress(&kl, g_klo);

    cudaFuncSetAttribute(qv_gemm512, cudaFuncAttributeMaxDynamicSharedMemorySize, HG_SMEM);
    cudaFuncSetAttribute(o_gemm512, cudaFuncAttributeMaxDynamicSharedMemorySize, HG_SMEM);
    cudaFuncSetAttribute(attn_mma, cudaFuncAttributeMaxDynamicSharedMemorySize, A_SMEM);

    pos_split<<<256, 256>>>();
    vbrel_k<<<128, 256>>>(v_bias);
    split_bhsd<<<2048, 256>>>(key, (__nv_bfloat16*)kh, (__nv_bfloat16*)kl);

    dim3 qvgrid(DM/128, (NB*SEQ)/128, 2);
    qv_gemm512<<<qvgrid, 512, HG_SMEM>>>(query, value, Wq, Wv, bq, bv);

    dim3 agrid(SEQ/128, NH, NB);
    attn_mma<<<agrid, 256, A_SMEM>>>();

    dim3 ogrid(DM/128, (NB*SEQ)/128);
    o_gemm512<<<ogrid, 512, HG_SMEM>>>((const float*)xp, Wo, bo, out);
}

// round 10
// speedup vs baseline: 2.6221x; 1.1312x over previous
#include <cuda_runtime.h>
#include <cuda_bf16.h>
#include <cuda_fp16.h>
#include <math.h>
#include <stdint.h>

#define SEQ 1024
#define DM  1024
#define NH  16
#define HD  64
#define NB  2
#define GK  1024

__device__ __half g_xh[NB*SEQ*DM];
__device__ float g_posf[2*SEQ*HD];
__device__ float g_vbrel[NH*2*SEQ + 32];
__device__ __nv_bfloat16 g_qhi[NB*NH*SEQ*HD], g_qlo[NB*NH*SEQ*HD];
__device__ __nv_bfloat16 g_khi[NB*NH*SEQ*HD], g_klo[NB*NH*SEQ*HD];
__device__ __half g_vth[NB*NH*HD*SEQ];
__device__ __nv_bfloat16 g_poshi[(2*SEQ+1)*HD], g_poslo[(2*SEQ+1)*HD];

__device__ __forceinline__ uint32_t smem_u32(const void* p) {
    uint32_t a;
    asm("{ .reg .u64 t; cvta.to.shared.u64 t, %1; cvt.u32.u64 %0, t; }" : "=r"(a) : "l"(p));
    return a;
}
__device__ __forceinline__ void ldsm_x4(uint32_t (&r)[4], uint32_t addr) {
    asm volatile("ldmatrix.sync.aligned.m8n8.x4.shared.b16 {%0,%1,%2,%3}, [%4];"
        : "=r"(r[0]), "=r"(r[1]), "=r"(r[2]), "=r"(r[3]) : "r"(addr));
}
__device__ __forceinline__ void mma_bf16(float (&d)[4], const uint32_t (&a)[4],
                                         uint32_t b0, uint32_t b1) {
    asm volatile("mma.sync.aligned.m16n8k16.row.col.f32.bf16.bf16.f32 "
        "{%0,%1,%2,%3}, {%4,%5,%6,%7}, {%8,%9}, {%0,%1,%2,%3};"
        : "+f"(d[0]), "+f"(d[1]), "+f"(d[2]), "+f"(d[3])
        : "r"(a[0]), "r"(a[1]), "r"(a[2]), "r"(a[3]), "r"(b0), "r"(b1));
}
__device__ __forceinline__ void mma_f16(float (&d)[4], const uint32_t (&a)[4],
                                        uint32_t b0, uint32_t b1) {
    asm volatile("mma.sync.aligned.m16n8k16.row.col.f32.f16.f16.f32 "
        "{%0,%1,%2,%3}, {%4,%5,%6,%7}, {%8,%9}, {%0,%1,%2,%3};"
        : "+f"(d[0]), "+f"(d[1]), "+f"(d[2]), "+f"(d[3])
        : "r"(a[0]), "r"(a[1]), "r"(a[2]), "r"(a[3]), "r"(b0), "r"(b1));
}
__device__ __forceinline__ void cpa16(uint32_t dst, const void* src) {
    asm volatile("cp.async.cg.shared.global [%0], [%1], 16;" :: "r"(dst), "l"(src));
}
#define CP_COMMIT() asm volatile("cp.async.commit_group;" ::: "memory")
#define CP_WAIT0()  asm volatile("cp.async.wait_group 0;" ::: "memory")

__device__ __forceinline__ void split_sts(float4 v, char* hi, char* lo, int byteoff) {
    __nv_bfloat162 h01 = __floats2bfloat162_rn(v.x, v.y);
    __nv_bfloat162 h23 = __floats2bfloat162_rn(v.z, v.w);
    float2 f01 = __bfloat1622float2(h01);
    float2 f23 = __bfloat1622float2(h23);
    __nv_bfloat162 l01 = __floats2bfloat162_rn(v.x - f01.x, v.y - f01.y);
    __nv_bfloat162 l23 = __floats2bfloat162_rn(v.z - f23.x, v.w - f23.y);
    *(uint2*)(hi + byteoff) = make_uint2(*(uint32_t*)&h01, *(uint32_t*)&h23);
    *(uint2*)(lo + byteoff) = make_uint2(*(uint32_t*)&l01, *(uint32_t*)&l23);
}
__device__ __forceinline__ uint32_t packsplit(float a, float b, uint32_t& lo) {
    __nv_bfloat162 hh = __floats2bfloat162_rn(a, b);
    float2 ff = __bfloat1622float2(hh);
    __nv_bfloat162 ll = __floats2bfloat162_rn(a - ff.x, b - ff.y);
    lo = *(uint32_t*)&ll;
    return *(uint32_t*)&hh;
}
__device__ __forceinline__ uint32_t packsplit_h(float a, float b, uint32_t& lo) {
    __half2 hh = __floats2half2_rn(a, b);
    float2 ff = __half22float2(hh);
    __half2 ll = __floats2half2_rn(a - ff.x, b - ff.y);
    lo = *(uint32_t*)&ll;
    return *(uint32_t*)&hh;
}
__device__ __forceinline__ void split1(float v, __nv_bfloat16& hi, __nv_bfloat16& lo) {
    hi = __float2bfloat16_rn(v);
    lo = __float2bfloat16_rn(v - __bfloat162float(hi));
}

// ---------------- prep kernels ----------------
__global__ void pos_split() {
    int idx = blockIdx.x * 256 + threadIdx.x;   // 65536
    int l = idx >> 5, j = idx & 31;
    float p = (float)(l - SEQ);
    const double negc = -log(10000.0) / 31.0;
    float ang = p * (float)exp((double)j * negc);
    float s = (float)sin((double)ang), c = (float)cos((double)ang);
    g_posf[l*64 + j]      = s;
    g_posf[l*64 + j + 32] = c;
    __nv_bfloat16 hh, ll;
    split1(s, hh, ll); g_poshi[l*64+j] = hh;      g_poslo[l*64+j] = ll;
    split1(c, hh, ll); g_poshi[l*64+j+32] = hh;   g_poslo[l*64+j+32] = ll;
}
__global__ void vbrel_k(const float* __restrict__ vb) {
    int idx = blockIdx.x * 256 + threadIdx.x;   // 32768
    int l = idx >> 4, h = idx & 15;
    float s = 0.f;
    #pragma unroll 8
    for (int d = 0; d < HD; d++) s = fmaf(__ldg(vb + h*HD + d), g_posf[l*64 + d], s);
    g_vbrel[h*2048 + l] = s;
}
__global__ void split_bhsd(const float* __restrict__ src,
                           __nv_bfloat16* __restrict__ hi, __nv_bfloat16* __restrict__ lo) {
    int idx = blockIdx.x * 256 + threadIdx.x;
    float4 v = ((const float4*)src)[idx];
    int c = idx & 255, s = (idx >> 8) & 1023, b = idx >> 18;
    size_t o = ((size_t)(b*NH + (c >> 4))*SEQ + s)*HD + (c & 15)*4;
    split_sts(v, (char*)(hi + o), (char*)(lo + o), 0);
}

// ---------------- GEMM cores ----------------
#define TSTRIDE 40
#define TILE_B  (128 * TSTRIDE * 2)
#define BUF_B   (4 * TILE_B)
#define HG_SMEM (2 * BUF_B)
#define BUF_H   (3 * TILE_B)

// bf16 3-term core (score path; proven)
__device__ __forceinline__ void gemm_core512(
    const float* __restrict__ Ap, const float* __restrict__ Bp,
    char* smraw, uint32_t sbase, int tid, int lane, int wm, int wn,
    float acc[2][4][4])
{
    const int lr = tid >> 2, lc = (tid & 3) * 8;
    const int bo = (lr*TSTRIDE + lc) * 2;
    const int a_r = lane & 15, a_c = (lane >> 4) << 3;
    const int b_r = (lane & 7) + ((lane & 16) >> 1), b_c = lane & 8;

    float4 av[2], bv[2];
    #pragma unroll
    for (int q = 0; q < 2; q++) {
        av[q] = *(const float4*)(Ap + lr*GK + lc + 4*q);
        bv[q] = *(const float4*)(Bp + lr*GK + lc + 4*q);
    }
    #pragma unroll
    for (int q = 0; q < 2; q++) {
        split_sts(av[q], smraw,            smraw + TILE_B,   bo + 8*q);
        split_sts(bv[q], smraw + 2*TILE_B, smraw + 3*TILE_B, bo + 8*q);
    }
    __syncthreads();

    for (int kt = 0; kt < 32; kt++) {
        if (kt < 31) {
            #pragma unroll
            for (int q = 0; q < 2; q++) {
                av[q] = *(const float4*)(Ap + lr*GK + (kt+1)*32 + lc + 4*q);
                bv[q] = *(const float4*)(Bp + lr*GK + (kt+1)*32 + lc + 4*q);
            }
        }
        const uint32_t base = sbase + (kt & 1) * BUF_B;
        #pragma unroll
        for (int kk = 0; kk < 2; kk++) {
            const int koff = kk * 16;
            uint32_t ah[2][4], al[2][4];
            #pragma unroll
            for (int i = 0; i < 2; i++) {
                const uint32_t off = (uint32_t)(((wm*32 + i*16 + a_r)*TSTRIDE + koff + a_c) * 2);
                ldsm_x4(ah[i], base + off);
                ldsm_x4(al[i], base + TILE_B + off);
            }
            uint32_t bh[2][4], bl[2][4];
            #pragma unroll
            for (int p = 0; p < 2; p++) {
                const uint32_t off = (uint32_t)(((wn*32 + p*16 + b_r)*TSTRIDE + koff + b_c) * 2);
                ldsm_x4(bh[p], base + 2*TILE_B + off);
                ldsm_x4(bl[p], base + 3*TILE_B + off);
            }
            #pragma unroll
            for (int i = 0; i < 2; i++)
                #pragma unroll
                for (int j = 0; j < 4; j++) {
                    const int p = j >> 1, s = (j & 1) * 2;
                    mma_bf16(acc[i][j], ah[i], bh[p][s], bh[p][s+1]);
                    mma_bf16(acc[i][j], ah[i], bl[p][s], bl[p][s+1]);
                    mma_bf16(acc[i][j], al[i], bh[p][s], bh[p][s+1]);
                }
        }
        if (kt < 31) {
            char* hA = smraw + ((kt+1) & 1) * BUF_B;
            #pragma unroll
            for (int q = 0; q < 2; q++) {
                split_sts(av[q], hA,            hA + TILE_B,   bo + 8*q);
                split_sts(bv[q], hA + 2*TILE_B, hA + 3*TILE_B, bo + 8*q);
            }
            __syncthreads();
        }
    }
}

// fp16 2-MMA core (linear path): A single fp16 plane, B fp16 hi+lo.
// AH=true: A already fp16 in global; AH=false: A fp32 -> fp16.
template<bool AH>
__device__ __forceinline__ void gemm_core512_h(
    const char* __restrict__ Ap, const float* __restrict__ Bp,
    char* smraw, uint32_t sbase, int tid, int lane, int wm, int wn,
    float acc[2][4][4])
{
    const int lr = tid >> 2, lc = (tid & 3) * 8;
    const int bo = (lr*TSTRIDE + lc) * 2;
    const int a_r = lane & 15, a_c = (lane >> 4) << 3;
    const int b_r = (lane & 7) + ((lane & 16) >> 1), b_c = lane & 8;

    float4 av[2], bv[2];
    uint4 ahr;

    #pragma unroll 1
    for (int kt = -1; kt < 32; kt++) {
        // prefetch chunk kt+1
        if (kt < 31) {
            const int kn = kt + 1;
            if (AH) {
                ahr = *(const uint4*)(Ap + ((size_t)lr*GK + kn*32 + lc)*2);
            } else {
                av[0] = *(const float4*)((const float*)Ap + (size_t)lr*GK + kn*32 + lc);
                av[1] = *(const float4*)((const float*)Ap + (size_t)lr*GK + kn*32 + lc + 4);
            }
            bv[0] = *(const float4*)(Bp + (size_t)lr*GK + kn*32 + lc);
            bv[1] = *(const float4*)(Bp + (size_t)lr*GK + kn*32 + lc + 4);
        }

        if (kt >= 0) {
            const uint32_t base = sbase + (kt & 1) * BUF_H;
            #pragma unroll
            for (int kk = 0; kk < 2; kk++) {
                const int koff = kk * 16;
                uint32_t af[2][4];
                #pragma unroll
                for (int i = 0; i < 2; i++) {
                    const uint32_t off = (uint32_t)(((wm*32 + i*16 + a_r)*TSTRIDE + koff + a_c) * 2);
                    ldsm_x4(af[i], base + off);
                }
                uint32_t bh[2][4], bl[2][4];
                #pragma unroll
                for (int p = 0; p < 2; p++) {
                    const uint32_t off = (uint32_t)(((wn*32 + p*16 + b_r)*TSTRIDE + koff + b_c) * 2);
                    ldsm_x4(bh[p], base + TILE_B + off);
                    ldsm_x4(bl[p], base + 2*TILE_B + off);
                }
                #pragma unroll
                for (int i = 0; i < 2; i++)
                    #pragma unroll
                    for (int j = 0; j < 4; j++) {
                        const int p = j >> 1, s = (j & 1) * 2;
                        mma_f16(acc[i][j], af[i], bh[p][s], bh[p][s+1]);
                        mma_f16(acc[i][j], af[i], bl[p][s], bl[p][s+1]);
                    }
            }
        }

        // stage chunk kt+1 into buf (kt+1)&1
        if (kt < 31) {
            char* buf = smraw + ((kt+1) & 1) * BUF_H;
            if (AH) {
                *(uint4*)(buf + bo) = ahr;
            } else {
                __half2 h0 = __floats2half2_rn(av[0].x, av[0].y);
                __half2 h1 = __floats2half2_rn(av[0].z, av[0].w);
                __half2 h2 = __floats2half2_rn(av[1].x, av[1].y);
                __half2 h3 = __floats2half2_rn(av[1].z, av[1].w);
                *(uint4*)(buf + bo) = make_uint4(*(uint32_t*)&h0, *(uint32_t*)&h1,
                                                 *(uint32_t*)&h2, *(uint32_t*)&h3);
            }
            {
                __half2 h0 = __floats2half2_rn(bv[0].x, bv[0].y);
                __half2 h1 = __floats2half2_rn(bv[0].z, bv[0].w);
                __half2 h2 = __floats2half2_rn(bv[1].x, bv[1].y);
                __half2 h3 = __floats2half2_rn(bv[1].z, bv[1].w);
                float2 f0 = __half22float2(h0), f1 = __half22float2(h1);
                float2 f2 = __half22float2(h2), f3 = __half22float2(h3);
                __half2 l0 = __floats2half2_rn(bv[0].x - f0.x, bv[0].y - f0.y);
                __half2 l1 = __floats2half2_rn(bv[0].z - f1.x, bv[0].w - f1.y);
                __half2 l2 = __floats2half2_rn(bv[1].x - f2.x, bv[1].y - f2.y);
                __half2 l3 = __floats2half2_rn(bv[1].z - f3.x, bv[1].w - f3.y);
                *(uint4*)(buf + TILE_B + bo)   = make_uint4(*(uint32_t*)&h0, *(uint32_t*)&h1,
                                                            *(uint32_t*)&h2, *(uint32_t*)&h3);
                *(uint4*)(buf + 2*TILE_B + bo) = make_uint4(*(uint32_t*)&l0, *(uint32_t*)&l1,
                                                            *(uint32_t*)&l2, *(uint32_t*)&l3);
            }
            __syncthreads();
        }
    }
}

// merged Q/V projection: z=0 -> Q bf16 3-term, split out (b,h,s,d);
//                        z=1 -> V fp16 2-term, single fp16 transposed (b,h,d,s)
__global__ __launch_bounds__(512) void qv_gemm512(
    const float* __restrict__ query, const float* __restrict__ value,
    const float* __restrict__ Wq, const float* __restrict__ Wv,
    const float* __restrict__ bq, const float* __restrict__ bv)
{
    extern __shared__ __align__(16) char smraw[];
    const int tid = threadIdx.x, lane = tid & 31, wid = tid >> 5;
    const int wm = wid & 3, wn = wid >> 2;
    const int row0 = blockIdx.y * 128, col0 = blockIdx.x * 128;
    const int z = blockIdx.z;

    float acc[2][4][4];
    #pragma unroll
    for (int i = 0; i < 2; i++)
        #pragma unroll
        for (int j = 0; j < 4; j++)
            #pragma unroll
            for (int c = 0; c < 4; c++) acc[i][j][c] = 0.f;

    const int grp = lane >> 2, qid = lane & 3;

    if (z == 0) {
        gemm_core512(query + (size_t)row0*GK, Wq + (size_t)col0*GK,
                     smraw, smem_u32(smraw), tid, lane, wm, wn, acc);
        #pragma unroll
        for (int j = 0; j < 4; j++) {
            const int col = col0 + wn*32 + j*8 + qid*2;
            const float2 bj = *(const float2*)(bq + col);
            const int h = col >> 6, d = col & 63;
            #pragma unroll
            for (int i = 0; i < 2; i++) {
                const int row = row0 + wm*32 + i*16 + grp;
                const int b = row >> 10, s = row & 1023;
                size_t o = (((size_t)(b*NH + h))*SEQ + s)*HD + d;
                uint32_t lo0, lo1;
                uint32_t hi0 = packsplit(acc[i][j][0]+bj.x, acc[i][j][1]+bj.y, lo0);
                uint32_t hi1 = packsplit(acc[i][j][2]+bj.x, acc[i][j][3]+bj.y, lo1);
                *(uint32_t*)(g_qhi + o) = hi0;        *(uint32_t*)(g_qlo + o) = lo0;
                *(uint32_t*)(g_qhi + o + 8*HD) = hi1; *(uint32_t*)(g_qlo + o + 8*HD) = lo1;
            }
        }
    } else {
        gemm_core512_h<false>((const char*)(value + (size_t)row0*GK), Wv + (size_t)col0*GK,
                              smraw, smem_u32(smraw), tid, lane, wm, wn, acc);
        #pragma unroll
        for (int j = 0; j < 4; j++) {
            const int col = col0 + wn*32 + j*8 + qid*2;
            const float2 bj = *(const float2*)(bv + col);
            const int h = col >> 6, d = col & 63;
            #pragma unroll
            for (int i = 0; i < 2; i++) {
                const int row = row0 + wm*32 + i*16 + grp;
                const int b = row >> 10, s = row & 1023;
                size_t o = (((size_t)(b*NH + h))*HD + d)*SEQ + s;
                g_vth[o]        = __float2half_rn(acc[i][j][0]+bj.x);
                g_vth[o+SEQ]    = __float2half_rn(acc[i][j][1]+bj.y);
                g_vth[o+8]      = __float2half_rn(acc[i][j][2]+bj.x);
                g_vth[o+SEQ+8]  = __float2half_rn(acc[i][j][3]+bj.y);
            }
        }
    }
}

// output GEMM: A = g_xh fp16 (pre-stored), B = Wo fp32 -> fp16 hi/lo, 2 MMAs
__global__ __launch_bounds__(512) void o_gemm512(
    const __half* __restrict__ A, const float* __restrict__ B,
    const float* __restrict__ bias, float* __restrict__ C)
{
    extern __shared__ __align__(16) char smraw[];
    const int tid = threadIdx.x, lane = tid & 31, wid = tid >> 5;
    const int wm = wid & 3, wn = wid >> 2;
    const int row0 = blockIdx.y * 128, col0 = blockIdx.x * 128;

    float acc[2][4][4];
    #pragma unroll
    for (int i = 0; i < 2; i++)
        #pragma unroll
        for (int j = 0; j < 4; j++)
            #pragma unroll
            for (int c = 0; c < 4; c++) acc[i][j][c] = 0.f;

    gemm_core512_h<true>((const char*)(A + (size_t)row0*GK), B + (size_t)col0*GK,
                         smraw, smem_u32(smraw), tid, lane, wm, wn, acc);

    const int grp = lane >> 2, qid = lane & 3;
    #pragma unroll
    for (int j = 0; j < 4; j++) {
        const int col = col0 + wn*32 + j*8 + qid*2;
        const float2 bj = *(const float2*)(bias + col);
        #pragma unroll
        for (int i = 0; i < 2; i++) {
            const int row = row0 + wm*32 + i*16 + grp;
            *(float2*)(C + (size_t)row*DM + col)     = make_float2(acc[i][j][0]+bj.x, acc[i][j][1]+bj.y);
            *(float2*)(C + (size_t)(row+8)*DM + col) = make_float2(acc[i][j][2]+bj.x, acc[i][j][3]+bj.y);
        }
    }
}

// --------- pipelined tensor-core fused attention ---------
// smem: Qhi 0 | Qlo 16384 | S0 32768 (32K) | S1 65536 (32K) | R 98304 (2x66560)
#define RSTR 130
#define S0OFF 32768u
#define S1OFF 65536u
#define ROFF  98304
#define RSLOT 66560
#define A_SMEM 231424

__device__ __forceinline__ void stage_rows_async(
    uint32_t sb, uint32_t so, int tid,
    const __nv_bfloat16* hp, const __nv_bfloat16* lp)
{
    #pragma unroll
    for (int r = 0; r < 4; r++) {
        int idx = tid + r*256, row = idx >> 3, c = idx & 7;
        uint32_t off = so + row*128 + ((c ^ (row & 7)) << 4);
        cpa16(sb + off,         (const char*)hp + idx*16);
        cpa16(sb + off + 16384, (const char*)lp + idx*16);
    }
}
// Vt: 64 rows(d) x 128 fp16, single plane, row stride 256B
__device__ __forceinline__ void stage_vt_async(
    uint32_t sb, uint32_t so, int tid, const __half* hp, int k0)
{
    #pragma unroll
    for (int r = 0; r < 4; r++) {
        int idx = tid + r*256, d = idx >> 4, c = idx & 15;
        uint32_t off = so + d*256 + ((c ^ (d & 7)) << 4);
        cpa16(sb + off, (const char*)(hp + (size_t)d*SEQ + k0) + c*16);
    }
}

__device__ __forceinline__ void rgemm_band(
    uint32_t sb, uint32_t so, int lane, int wm, int wn, int grp, int qid,
    float* R, const float* __restrict__ vbg)
{
    float rc[4][4][4];
    #pragma unroll
    for (int i = 0; i < 4; i++)
        #pragma unroll
        for (int j = 0; j < 4; j++) { rc[i][j][0]=0;rc[i][j][1]=0;rc[i][j][2]=0;rc[i][j][3]=0; }
    #pragma unroll
    for (int kb = 0; kb < 4; kb++) {
        uint32_t ah[4][4], al[4][4];
        #pragma unroll
        for (int i = 0; i < 4; i++) {
            uint32_t ao = (uint32_t)((wm*64 + i*16 + (lane&15))*128
                         + (((kb*2 + (lane>>4)) ^ (lane&7)) << 4));
            ldsm_x4(ah[i], sb + ao);
            ldsm_x4(al[i], sb + 16384 + ao);
        }
        uint32_t bh2[2][4], bl2[2][4];
        #pragma unroll
        for (int jp = 0; jp < 2; jp++) {
            uint32_t bo = (uint32_t)((wn*32 + jp*16 + (lane&7) + ((lane&16)>>1))*128
                         + (((kb*2 + ((lane&8)>>3)) ^ (lane&7)) << 4));
            ldsm_x4(bh2[jp], sb + so + bo);
            ldsm_x4(bl2[jp], sb + so + 16384 + bo);
        }
        #pragma unroll
        for (int i = 0; i < 4; i++)
            #pragma unroll
            for (int j = 0; j < 4; j++) {
                const int jp = j >> 1, s = (j & 1)*2;
                mma_bf16(rc[i][j], ah[i], bh2[jp][s], bh2[jp][s+1]);
                mma_bf16(rc[i][j], ah[i], bl2[jp][s], bl2[jp][s+1]);
                mma_bf16(rc[i][j], al[i], bh2[jp][s], bh2[jp][s+1]);
            }
    }
    #pragma unroll
    for (int i = 0; i < 4; i++) {
        const int u = wm*64 + i*16 + grp;
        #pragma unroll
        for (int j = 0; j < 4; j++) {
            const int l = wn*32 + j*8 + qid*2;
            float v0 = __ldg(vbg + l), v1 = __ldg(vbg + l + 1);
            *(float2*)&R[u*RSTR + l]     = make_float2(rc[i][j][0]+v0, rc[i][j][1]+v1);
            *(float2*)&R[(u+8)*RSTR + l] = make_float2(rc[i][j][2]+v0, rc[i][j][3]+v1);
        }
    }
}

__global__ __launch_bounds__(256, 1) void attn_mma()
{
    extern __shared__ __align__(16) char sm[];
    float* Rb0 = (float*)(sm + ROFF);
    float* Rb1 = (float*)(sm + ROFF + RSLOT);
    const int tid = threadIdx.x, lane = tid & 31, wid = tid >> 5;
    const int grp = lane >> 2, qid = lane & 3;
    const int q0 = blockIdx.x*128, h = blockIdx.y, b = blockIdx.z, bh = b*NH + h;
    const uint32_t sb = smem_u32(sm);
    const int wm = wid & 1, wn = wid >> 1;
    const int u0w = wid*16, r0 = u0w + grp;
    const int lmin0 = SEQ - q0 - 127;
    const float* vbg = g_vbrel + h*2048;
    const __nv_bfloat16* khB = g_khi + (size_t)bh*SEQ*HD;
    const __nv_bfloat16* klB = g_klo + (size_t)bh*SEQ*HD;
    const __half* vhB = g_vth + (size_t)bh*HD*SEQ;

    {   // Q stage (sync, once)
        const uint4* sh = (const uint4*)(g_qhi + ((size_t)bh*SEQ + q0)*HD);
        const uint4* sl = (const uint4*)(g_qlo + ((size_t)bh*SEQ + q0)*HD);
        #pragma unroll
        for (int r = 0; r < 4; r++) {
            int idx = tid + r*256, row = idx >> 3, c = idx & 7;
            int off = row*128 + ((c ^ (row & 7)) << 4);
            *(uint4*)(sm + off) = sh[idx];
            *(uint4*)(sm + 16384 + off) = sl[idx];
        }
    }
    float O[8][4];
    #pragma unroll
    for (int j = 0; j < 8; j++) { O[j][0]=0;O[j][1]=0;O[j][2]=0;O[j][3]=0; }
    float mr0 = -INFINITY, mr1 = -INFINITY, lr0 = 0.f, lr1 = 0.f;

    // prologue: bands 0,1 R-GEMMs; K(0) prefetch
    stage_rows_async(sb, S0OFF, tid, g_poshi + (size_t)lmin0*HD, g_poslo + (size_t)lmin0*HD);
    CP_COMMIT(); CP_WAIT0(); __syncthreads();

    stage_rows_async(sb, S1OFF, tid, g_poshi + (size_t)(lmin0+128)*HD, g_poslo + (size_t)(lmin0+128)*HD);
    CP_COMMIT();
    rgemm_band(sb, S0OFF, lane, wm, wn, grp, qid, Rb0, vbg + lmin0);
    CP_WAIT0(); __syncthreads();

    stage_rows_async(sb, S0OFF, tid, khB, klB);
    CP_COMMIT();
    rgemm_band(sb, S1OFF, lane, wm, wn, grp, qid, Rb1, vbg + lmin0 + 128);
    CP_WAIT0(); __syncthreads();

    for (int kt = 0; kt < 8; kt++) {
        const int k0 = kt*128;
        const uint32_t kOff = (kt & 1) ? S1OFF : S0OFF;
        const uint32_t vOff = (kt & 1) ? S0OFF : S1OFF;

        if (kt > 0) {
            stage_rows_async(sb, kOff, tid, khB + (size_t)k0*HD, klB + (size_t)k0*HD);
            CP_COMMIT();
            rgemm_band(sb, vOff, lane, wm, wn, grp, qid,
                       ((kt+1) & 1) ? Rb1 : Rb0, vbg + lmin0 + 128*(kt+1));
            CP_WAIT0(); __syncthreads();
        }

        // Vt(kt) prefetch into vOff (single fp16 plane), QK from kOff
        stage_vt_async(sb, vOff, tid, vhB, k0);
        CP_COMMIT();

        float aq[16][4];
        #pragma unroll
        for (int j = 0; j < 16; j++) { aq[j][0]=0;aq[j][1]=0;aq[j][2]=0;aq[j][3]=0; }
        #pragma unroll
        for (int kb = 0; kb < 4; kb++) {
            uint32_t ah[4], al[4];
            uint32_t ao = (uint32_t)((u0w + (lane&15))*128
                         + (((kb*2 + (lane>>4)) ^ (lane&7)) << 4));
            ldsm_x4(ah, sb + ao);
            ldsm_x4(al, sb + 16384 + ao);
            #pragma unroll
            for (int jp = 0; jp < 8; jp++) {
                uint32_t bh4[4], bl4[4];
                uint32_t bo = (uint32_t)((jp*16 + (lane&7) + ((lane&16)>>1))*128
                             + (((kb*2 + ((lane&8)>>3)) ^ (lane&7)) << 4));
                ldsm_x4(bh4, sb + kOff + bo);
                ldsm_x4(bl4, sb + kOff + 16384 + bo);
                #pragma unroll
                for (int jj = 0; jj < 2; jj++) {
                    const int j = jp*2 + jj, s = jj*2;
                    mma_bf16(aq[j], ah, bh4[s], bh4[s+1]);
                    mma_bf16(aq[j], ah, bl4[s], bl4[s+1]);
                    mma_bf16(aq[j], al, bh4[s], bh4[s+1]);
                }
            }
        }

        const float* RA  = (kt & 1) ? Rb1 : Rb0;
        const float* RBf = (kt & 1) ? Rb0 : Rb1;
        float m0 = -INFINITY, m1 = -INFINITY;
        #pragma unroll
        for (int j = 0; j < 16; j++) {
            const int w = j*8 + qid*2;
            const int ma = 127 + w - r0, mb = ma - 8;
            aq[j][0] += (ma < 128)   ? RA[r0*RSTR + ma]         : RBf[r0*RSTR + ma - 128];
            aq[j][1] += (ma+1 < 128) ? RA[r0*RSTR + ma + 1]     : RBf[r0*RSTR + ma - 127];
            aq[j][2] += (mb < 128)   ? RA[(r0+8)*RSTR + mb]     : RBf[(r0+8)*RSTR + mb - 128];
            aq[j][3] += (mb+1 < 128) ? RA[(r0+8)*RSTR + mb + 1] : RBf[(r0+8)*RSTR + mb - 127];
            m0 = fmaxf(m0, fmaxf(aq[j][0], aq[j][1]));
            m1 = fmaxf(m1, fmaxf(aq[j][2], aq[j][3]));
        }
        m0 = fmaxf(m0, __shfl_xor_sync(~0u, m0, 1));
        m0 = fmaxf(m0, __shfl_xor_sync(~0u, m0, 2));
        m1 = fmaxf(m1, __shfl_xor_sync(~0u, m1, 1));
        m1 = fmaxf(m1, __shfl_xor_sync(~0u, m1, 2));
        const float mn0 = fmaxf(mr0, m0), mn1 = fmaxf(mr1, m1);
        const float scl0 = __expf(mr0 - mn0), scl1 = __expf(mr1 - mn1);
        mr0 = mn0; mr1 = mn1;

        uint32_t phi[8][4], plo[8][4];
        float s0 = 0.f, s1 = 0.f;
        #pragma unroll
        for (int j = 0; j < 16; j++) {
            float p0 = __expf(aq[j][0]-mn0), p1 = __expf(aq[j][1]-mn0);
            float p2 = __expf(aq[j][2]-mn1), p3 = __expf(aq[j][3]-mn1);
            s0 += p0 + p1; s1 += p2 + p3;
            const int kk = j >> 1, bs = (j & 1)*2;
            phi[kk][bs]   = packsplit_h(p0, p1, plo[kk][bs]);
            phi[kk][bs+1] = packsplit_h(p2, p3, plo[kk][bs+1]);
        }
        s0 += __shfl_xor_sync(~0u, s0, 1); s0 += __shfl_xor_sync(~0u, s0, 2);
        s1 += __shfl_xor_sync(~0u, s1, 1); s1 += __shfl_xor_sync(~0u, s1, 2);
        lr0 = lr0*scl0 + s0; lr1 = lr1*scl1 + s1;
        #pragma unroll
        for (int j = 0; j < 8; j++) {
            O[j][0] *= scl0; O[j][1] *= scl0; O[j][2] *= scl1; O[j][3] *= scl1;
        }

        CP_WAIT0(); __syncthreads();

        // pos(band kt+2) prefetch into kOff, PV (fp16, 2 MMAs) from vOff
        if (kt < 7) {
            const int l0n = lmin0 + 128*(kt+2);
            stage_rows_async(sb, kOff, tid, g_poshi + (size_t)l0n*HD, g_poslo + (size_t)l0n*HD);
            CP_COMMIT();
        }

        #pragma unroll
        for (int kk = 0; kk < 8; kk++) {
            #pragma unroll
            for (int jp = 0; jp < 4; jp++) {
                uint32_t bh4[4];
                uint32_t bo = (uint32_t)((jp*16 + (lane&7) + ((lane&16)>>1))*256
                             + (((kk*2 + ((lane&8)>>3)) ^ (lane&7)) << 4));
                ldsm_x4(bh4, sb + vOff + bo);
                #pragma unroll
                for (int jj = 0; jj < 2; jj++) {
                    const int j = jp*2 + jj, s = jj*2;
                    mma_f16(O[j], phi[kk], bh4[s], bh4[s+1]);
                    mma_f16(O[j], plo[kk], bh4[s], bh4[s+1]);
                }
            }
        }
        if (kt < 7) CP_WAIT0();
        __syncthreads();
    }

    // epilogue: write x as fp16 (b,s,h*64+d)
    const float i0 = 1.f/lr0, i1 = 1.f/lr1;
    __half* x0 = g_xh + ((size_t)(b*SEQ + q0 + r0))*DM + h*HD;
    __half* x1 = g_xh + ((size_t)(b*SEQ + q0 + r0 + 8))*DM + h*HD;
    #pragma unroll
    for (int j = 0; j < 8; j++) {
        const int col = j*8 + qid*2;
        __half2 o0 = __floats2half2_rn(O[j][0]*i0, O[j][1]*i0);
        __half2 o1 = __floats2half2_rn(O[j][2]*i1, O[j][3]*i1);
        *(__half2*)(x0 + col) = o0;
        *(__half2*)(x1 + col) = o1;
    }
}

// ---------------------------------------------------------------------------
extern "C" void kernel_launch(void* const* d_in, const int* in_sizes, int n_in,
                              void* d_out, int out_size) {
    const float* query  = (const float*)d_in[0];
    const float* key    = (const float*)d_in[1];
    const float* value  = (const float*)d_in[2];
    const float* Wq     = (const float*)d_in[4];
    const float* bq     = (const float*)d_in[5];
    const float* Wv     = (const float*)d_in[6];
    const float* bv     = (const float*)d_in[7];
    const float* Wo     = (const float*)d_in[8];
    const float* bo     = (const float*)d_in[9];
    const float* v_bias = (const float*)d_in[10];
    float* out = (float*)d_out;

    void *xp, *kh, *kl;
    cudaGetSymbolAddress(&xp, g_xh);
    cudaGetSymbolAddress(&kh, g_khi); cudaGetSymbolAddress(&kl, g_klo);

    cudaFuncSetAttribute(qv_gemm512, cudaFuncAttributeMaxDynamicSharedMemorySize, HG_SMEM);
    cudaFuncSetAttribute(o_gemm512, cudaFuncAttributeMaxDynamicSharedMemorySize, HG_SMEM);
    cudaFuncSetAttribute(attn_mma, cudaFuncAttributeMaxDynamicSharedMemorySize, A_SMEM);

    pos_split<<<256, 256>>>();
    vbrel_k<<<128, 256>>>(v_bias);
    split_bhsd<<<2048, 256>>>(key, (__nv_bfloat16*)kh, (__nv_bfloat16*)kl);

    dim3 qvgrid(DM/128, (NB*SEQ)/128, 2);
    qv_gemm512<<<qvgrid, 512, HG_SMEM>>>(query, value, Wq, Wv, bq, bv);

    dim3 agrid(SEQ/128, NH, NB);
    attn_mma<<<agrid, 256, A_SMEM>>>();

    dim3 ogrid(DM/128, (NB*SEQ)/128);
    o_gemm512<<<ogrid, 512, HG_SMEM>>>((const __half*)xp, Wo, bo, out);
}

// round 11
// speedup vs baseline: 2.8072x; 1.0706x over previous
#include <cuda_runtime.h>
#include <cuda_bf16.h>
#include <cuda_fp16.h>
#include <math.h>
#include <stdint.h>

#define SEQ 1024
#define DM  1024
#define NH  16
#define HD  64
#define NB  2
#define GK  1024

__device__ __half g_xh[NB*SEQ*DM];
__device__ float g_vbrel[NH*2*SEQ + 32];
__device__ __nv_bfloat16 g_qhi[NB*NH*SEQ*HD], g_qlo[NB*NH*SEQ*HD];
__device__ __nv_bfloat16 g_khi[NB*NH*SEQ*HD], g_klo[NB*NH*SEQ*HD];
__device__ __half g_vth[NB*NH*HD*SEQ];
__device__ __nv_bfloat16 g_poshi[(2*SEQ+1)*HD], g_poslo[(2*SEQ+1)*HD];

__device__ __forceinline__ uint32_t smem_u32(const void* p) {
    uint32_t a;
    asm("{ .reg .u64 t; cvta.to.shared.u64 t, %1; cvt.u32.u64 %0, t; }" : "=r"(a) : "l"(p));
    return a;
}
__device__ __forceinline__ void ldsm_x4(uint32_t (&r)[4], uint32_t addr) {
    asm volatile("ldmatrix.sync.aligned.m8n8.x4.shared.b16 {%0,%1,%2,%3}, [%4];"
        : "=r"(r[0]), "=r"(r[1]), "=r"(r[2]), "=r"(r[3]) : "r"(addr));
}
__device__ __forceinline__ void mma_bf16(float (&d)[4], const uint32_t (&a)[4],
                                         uint32_t b0, uint32_t b1) {
    asm volatile("mma.sync.aligned.m16n8k16.row.col.f32.bf16.bf16.f32 "
        "{%0,%1,%2,%3}, {%4,%5,%6,%7}, {%8,%9}, {%0,%1,%2,%3};"
        : "+f"(d[0]), "+f"(d[1]), "+f"(d[2]), "+f"(d[3])
        : "r"(a[0]), "r"(a[1]), "r"(a[2]), "r"(a[3]), "r"(b0), "r"(b1));
}
__device__ __forceinline__ void mma_f16(float (&d)[4], const uint32_t (&a)[4],
                                        uint32_t b0, uint32_t b1) {
    asm volatile("mma.sync.aligned.m16n8k16.row.col.f32.f16.f16.f32 "
        "{%0,%1,%2,%3}, {%4,%5,%6,%7}, {%8,%9}, {%0,%1,%2,%3};"
        : "+f"(d[0]), "+f"(d[1]), "+f"(d[2]), "+f"(d[3])
        : "r"(a[0]), "r"(a[1]), "r"(a[2]), "r"(a[3]), "r"(b0), "r"(b1));
}
__device__ __forceinline__ void cpa16(uint32_t dst, const void* src) {
    asm volatile("cp.async.cg.shared.global [%0], [%1], 16;" :: "r"(dst), "l"(src));
}
#define CP_COMMIT() asm volatile("cp.async.commit_group;" ::: "memory")
#define CP_WAIT0()  asm volatile("cp.async.wait_group 0;" ::: "memory")

__device__ __forceinline__ void split_sts(float4 v, char* hi, char* lo, int byteoff) {
    __nv_bfloat162 h01 = __floats2bfloat162_rn(v.x, v.y);
    __nv_bfloat162 h23 = __floats2bfloat162_rn(v.z, v.w);
    float2 f01 = __bfloat1622float2(h01);
    float2 f23 = __bfloat1622float2(h23);
    __nv_bfloat162 l01 = __floats2bfloat162_rn(v.x - f01.x, v.y - f01.y);
    __nv_bfloat162 l23 = __floats2bfloat162_rn(v.z - f23.x, v.w - f23.y);
    *(uint2*)(hi + byteoff) = make_uint2(*(uint32_t*)&h01, *(uint32_t*)&h23);
    *(uint2*)(lo + byteoff) = make_uint2(*(uint32_t*)&l01, *(uint32_t*)&l23);
}
__device__ __forceinline__ uint32_t packsplit(float a, float b, uint32_t& lo) {
    __nv_bfloat162 hh = __floats2bfloat162_rn(a, b);
    float2 ff = __bfloat1622float2(hh);
    __nv_bfloat162 ll = __floats2bfloat162_rn(a - ff.x, b - ff.y);
    lo = *(uint32_t*)&ll;
    return *(uint32_t*)&hh;
}
__device__ __forceinline__ void split1(float v, __nv_bfloat16& hi, __nv_bfloat16& lo) {
    hi = __float2bfloat16_rn(v);
    lo = __float2bfloat16_rn(v - __bfloat162float(hi));
}

// ---------------- GEMM cores ----------------
#define TSTRIDE 40
#define TILE_B  (128 * TSTRIDE * 2)
#define BUF_B   (4 * TILE_B)
#define HG_SMEM (2 * BUF_B)
#define BUF_H   (3 * TILE_B)

// bf16 3-term core (score path)
__device__ __forceinline__ void gemm_core512(
    const float* __restrict__ Ap, const float* __restrict__ Bp,
    char* smraw, uint32_t sbase, int tid, int lane, int wm, int wn,
    float acc[2][4][4])
{
    const int lr = tid >> 2, lc = (tid & 3) * 8;
    const int bo = (lr*TSTRIDE + lc) * 2;
    const int a_r = lane & 15, a_c = (lane >> 4) << 3;
    const int b_r = (lane & 7) + ((lane & 16) >> 1), b_c = lane & 8;

    float4 av[2], bv[2];
    #pragma unroll
    for (int q = 0; q < 2; q++) {
        av[q] = *(const float4*)(Ap + lr*GK + lc + 4*q);
        bv[q] = *(const float4*)(Bp + lr*GK + lc + 4*q);
    }
    #pragma unroll
    for (int q = 0; q < 2; q++) {
        split_sts(av[q], smraw,            smraw + TILE_B,   bo + 8*q);
        split_sts(bv[q], smraw + 2*TILE_B, smraw + 3*TILE_B, bo + 8*q);
    }
    __syncthreads();

    for (int kt = 0; kt < 32; kt++) {
        if (kt < 31) {
            #pragma unroll
            for (int q = 0; q < 2; q++) {
                av[q] = *(const float4*)(Ap + lr*GK + (kt+1)*32 + lc + 4*q);
                bv[q] = *(const float4*)(Bp + lr*GK + (kt+1)*32 + lc + 4*q);
            }
        }
        const uint32_t base = sbase + (kt & 1) * BUF_B;
        #pragma unroll
        for (int kk = 0; kk < 2; kk++) {
            const int koff = kk * 16;
            uint32_t ah[2][4], al[2][4];
            #pragma unroll
            for (int i = 0; i < 2; i++) {
                const uint32_t off = (uint32_t)(((wm*32 + i*16 + a_r)*TSTRIDE + koff + a_c) * 2);
                ldsm_x4(ah[i], base + off);
                ldsm_x4(al[i], base + TILE_B + off);
            }
            uint32_t bh[2][4], bl[2][4];
            #pragma unroll
            for (int p = 0; p < 2; p++) {
                const uint32_t off = (uint32_t)(((wn*32 + p*16 + b_r)*TSTRIDE + koff + b_c) * 2);
                ldsm_x4(bh[p], base + 2*TILE_B + off);
                ldsm_x4(bl[p], base + 3*TILE_B + off);
            }
            #pragma unroll
            for (int i = 0; i < 2; i++)
                #pragma unroll
                for (int j = 0; j < 4; j++) {
                    const int p = j >> 1, s = (j & 1) * 2;
                    mma_bf16(acc[i][j], ah[i], bh[p][s], bh[p][s+1]);
                    mma_bf16(acc[i][j], ah[i], bl[p][s], bl[p][s+1]);
                    mma_bf16(acc[i][j], al[i], bh[p][s], bh[p][s+1]);
                }
        }
        if (kt < 31) {
            char* hA = smraw + ((kt+1) & 1) * BUF_B;
            #pragma unroll
            for (int q = 0; q < 2; q++) {
                split_sts(av[q], hA,            hA + TILE_B,   bo + 8*q);
                split_sts(bv[q], hA + 2*TILE_B, hA + 3*TILE_B, bo + 8*q);
            }
            __syncthreads();
        }
    }
}

// fp16 2-MMA core (linear path)
template<bool AH>
__device__ __forceinline__ void gemm_core512_h(
    const char* __restrict__ Ap, const float* __restrict__ Bp,
    char* smraw, uint32_t sbase, int tid, int lane, int wm, int wn,
    float acc[2][4][4])
{
    const int lr = tid >> 2, lc = (tid & 3) * 8;
    const int bo = (lr*TSTRIDE + lc) * 2;
    const int a_r = lane & 15, a_c = (lane >> 4) << 3;
    const int b_r = (lane & 7) + ((lane & 16) >> 1), b_c = lane & 8;

    float4 av[2], bv[2];
    uint4 ahr;

    #pragma unroll 1
    for (int kt = -1; kt < 32; kt++) {
        if (kt < 31) {
            const int kn = kt + 1;
            if (AH) {
                ahr = *(const uint4*)(Ap + ((size_t)lr*GK + kn*32 + lc)*2);
            } else {
                av[0] = *(const float4*)((const float*)Ap + (size_t)lr*GK + kn*32 + lc);
                av[1] = *(const float4*)((const float*)Ap + (size_t)lr*GK + kn*32 + lc + 4);
            }
            bv[0] = *(const float4*)(Bp + (size_t)lr*GK + kn*32 + lc);
            bv[1] = *(const float4*)(Bp + (size_t)lr*GK + kn*32 + lc + 4);
        }

        if (kt >= 0) {
            const uint32_t base = sbase + (kt & 1) * BUF_H;
            #pragma unroll
            for (int kk = 0; kk < 2; kk++) {
                const int koff = kk * 16;
                uint32_t af[2][4];
                #pragma unroll
                for (int i = 0; i < 2; i++) {
                    const uint32_t off = (uint32_t)(((wm*32 + i*16 + a_r)*TSTRIDE + koff + a_c) * 2);
                    ldsm_x4(af[i], base + off);
                }
                uint32_t bh[2][4], bl[2][4];
                #pragma unroll
                for (int p = 0; p < 2; p++) {
                    const uint32_t off = (uint32_t)(((wn*32 + p*16 + b_r)*TSTRIDE + koff + b_c) * 2);
                    ldsm_x4(bh[p], base + TILE_B + off);
                    ldsm_x4(bl[p], base + 2*TILE_B + off);
                }
                #pragma unroll
                for (int i = 0; i < 2; i++)
                    #pragma unroll
                    for (int j = 0; j < 4; j++) {
                        const int p = j >> 1, s = (j & 1) * 2;
                        mma_f16(acc[i][j], af[i], bh[p][s], bh[p][s+1]);
                        mma_f16(acc[i][j], af[i], bl[p][s], bl[p][s+1]);
                    }
            }
        }

        if (kt < 31) {
            char* buf = smraw + ((kt+1) & 1) * BUF_H;
            if (AH) {
                *(uint4*)(buf + bo) = ahr;
            } else {
                __half2 h0 = __floats2half2_rn(av[0].x, av[0].y);
                __half2 h1 = __floats2half2_rn(av[0].z, av[0].w);
                __half2 h2 = __floats2half2_rn(av[1].x, av[1].y);
                __half2 h3 = __floats2half2_rn(av[1].z, av[1].w);
                *(uint4*)(buf + bo) = make_uint4(*(uint32_t*)&h0, *(uint32_t*)&h1,
                                                 *(uint32_t*)&h2, *(uint32_t*)&h3);
            }
            {
                __half2 h0 = __floats2half2_rn(bv[0].x, bv[0].y);
                __half2 h1 = __floats2half2_rn(bv[0].z, bv[0].w);
                __half2 h2 = __floats2half2_rn(bv[1].x, bv[1].y);
                __half2 h3 = __floats2half2_rn(bv[1].z, bv[1].w);
                float2 f0 = __half22float2(h0), f1 = __half22float2(h1);
                float2 f2 = __half22float2(h2), f3 = __half22float2(h3);
                __half2 l0 = __floats2half2_rn(bv[0].x - f0.x, bv[0].y - f0.y);
                __half2 l1 = __floats2half2_rn(bv[0].z - f1.x, bv[0].w - f1.y);
                __half2 l2 = __floats2half2_rn(bv[1].x - f2.x, bv[1].y - f2.y);
                __half2 l3 = __floats2half2_rn(bv[1].z - f3.x, bv[1].w - f3.y);
                *(uint4*)(buf + TILE_B + bo)   = make_uint4(*(uint32_t*)&h0, *(uint32_t*)&h1,
                                                            *(uint32_t*)&h2, *(uint32_t*)&h3);
                *(uint4*)(buf + 2*TILE_B + bo) = make_uint4(*(uint32_t*)&l0, *(uint32_t*)&l1,
                                                            *(uint32_t*)&l2, *(uint32_t*)&l3);
            }
            __syncthreads();
        }
    }
}

// z=0: Q proj (bf16 3-term, split out); z=1: V proj (fp16, transposed out);
// z=2: prep (pos tables + vbrel + K split) — hides prep inside this launch.
__global__ __launch_bounds__(512) void qv_gemm512(
    const float* __restrict__ query, const float* __restrict__ value,
    const float* __restrict__ keyg,
    const float* __restrict__ Wq, const float* __restrict__ Wv,
    const float* __restrict__ bq, const float* __restrict__ bv,
    const float* __restrict__ vbias)
{
    extern __shared__ __align__(16) char smraw[];
    const int tid = threadIdx.x, lane = tid & 31, wid = tid >> 5;
    const int wm = wid & 3, wn = wid >> 2;
    const int row0 = blockIdx.y * 128, col0 = blockIdx.x * 128;
    const int z = blockIdx.z;

    if (z == 2) {
        // ---- prep CTA: pid in 0..127 ----
        const int pid = blockIdx.y * 8 + blockIdx.x;
        float* ps  = (float*)smraw;           // 16 x 64
        float* vbs = (float*)smraw + 1024;    // 16 x 64
        for (int i = tid; i < 1024; i += 512) vbs[i] = vbias[i];
        {
            const int li = tid >> 5, j = tid & 31;
            const int l = pid * 16 + li;
            float p = (float)(l - SEQ);
            const double negc = -log(10000.0) / 31.0;
            float ang = p * (float)exp((double)j * negc);
            float s = (float)sin((double)ang), c = (float)cos((double)ang);
            ps[li*64 + j] = s; ps[li*64 + j + 32] = c;
            __nv_bfloat16 hh, ll;
            split1(s, hh, ll); g_poshi[l*64+j] = hh;      g_poslo[l*64+j] = ll;
            split1(c, hh, ll); g_poshi[l*64+j+32] = hh;   g_poslo[l*64+j+32] = ll;
        }
        __syncthreads();
        if (tid < 256) {
            const int li = tid >> 4, h = tid & 15;
            float sum = 0.f;
            #pragma unroll 8
            for (int d = 0; d < 64; d++) sum = fmaf(vbs[h*64+d], ps[li*64+d], sum);
            g_vbrel[h*2048 + pid*16 + li] = sum;
        }
        // K split: 524288 float4 total, 4096 per CTA
        #pragma unroll
        for (int r = 0; r < 8; r++) {
            int idx = pid*4096 + r*512 + tid;
            float4 v = ((const float4*)keyg)[idx];
            int cc = idx & 255, ss = (idx >> 8) & 1023, bb = idx >> 18;
            size_t o = ((size_t)(bb*NH + (cc >> 4))*SEQ + ss)*HD + (cc & 15)*4;
            split_sts(v, (char*)(g_khi + o), (char*)(g_klo + o), 0);
        }
        return;
    }

    float acc[2][4][4];
    #pragma unroll
    for (int i = 0; i < 2; i++)
        #pragma unroll
        for (int j = 0; j < 4; j++)
            #pragma unroll
            for (int c = 0; c < 4; c++) acc[i][j][c] = 0.f;

    const int grp = lane >> 2, qid = lane & 3;

    if (z == 0) {
        gemm_core512(query + (size_t)row0*GK, Wq + (size_t)col0*GK,
                     smraw, smem_u32(smraw), tid, lane, wm, wn, acc);
        #pragma unroll
        for (int j = 0; j < 4; j++) {
            const int col = col0 + wn*32 + j*8 + qid*2;
            const float2 bj = *(const float2*)(bq + col);
            const int h = col >> 6, d = col & 63;
            #pragma unroll
            for (int i = 0; i < 2; i++) {
                const int row = row0 + wm*32 + i*16 + grp;
                const int b = row >> 10, s = row & 1023;
                size_t o = (((size_t)(b*NH + h))*SEQ + s)*HD + d;
                uint32_t lo0, lo1;
                uint32_t hi0 = packsplit(acc[i][j][0]+bj.x, acc[i][j][1]+bj.y, lo0);
                uint32_t hi1 = packsplit(acc[i][j][2]+bj.x, acc[i][j][3]+bj.y, lo1);
                *(uint32_t*)(g_qhi + o) = hi0;        *(uint32_t*)(g_qlo + o) = lo0;
                *(uint32_t*)(g_qhi + o + 8*HD) = hi1; *(uint32_t*)(g_qlo + o + 8*HD) = lo1;
            }
        }
    } else {
        gemm_core512_h<false>((const char*)(value + (size_t)row0*GK), Wv + (size_t)col0*GK,
                              smraw, smem_u32(smraw), tid, lane, wm, wn, acc);
        #pragma unroll
        for (int j = 0; j < 4; j++) {
            const int col = col0 + wn*32 + j*8 + qid*2;
            const float2 bj = *(const float2*)(bv + col);
            const int h = col >> 6, d = col & 63;
            #pragma unroll
            for (int i = 0; i < 2; i++) {
                const int row = row0 + wm*32 + i*16 + grp;
                const int b = row >> 10, s = row & 1023;
                size_t o = (((size_t)(b*NH + h))*HD + d)*SEQ + s;
                g_vth[o]        = __float2half_rn(acc[i][j][0]+bj.x);
                g_vth[o+SEQ]    = __float2half_rn(acc[i][j][1]+bj.y);
                g_vth[o+8]      = __float2half_rn(acc[i][j][2]+bj.x);
                g_vth[o+SEQ+8]  = __float2half_rn(acc[i][j][3]+bj.y);
            }
        }
    }
}

// output GEMM: A = g_xh fp16, B = Wo fp16 hi/lo
__global__ __launch_bounds__(512) void o_gemm512(
    const __half* __restrict__ A, const float* __restrict__ B,
    const float* __restrict__ bias, float* __restrict__ C)
{
    extern __shared__ __align__(16) char smraw[];
    const int tid = threadIdx.x, lane = tid & 31, wid = tid >> 5;
    const int wm = wid & 3, wn = wid >> 2;
    const int row0 = blockIdx.y * 128, col0 = blockIdx.x * 128;

    float acc[2][4][4];
    #pragma unroll
    for (int i = 0; i < 2; i++)
        #pragma unroll
        for (int j = 0; j < 4; j++)
            #pragma unroll
            for (int c = 0; c < 4; c++) acc[i][j][c] = 0.f;

    gemm_core512_h<true>((const char*)(A + (size_t)row0*GK), B + (size_t)col0*GK,
                         smraw, smem_u32(smraw), tid, lane, wm, wn, acc);

    const int grp = lane >> 2, qid = lane & 3;
    #pragma unroll
    for (int j = 0; j < 4; j++) {
        const int col = col0 + wn*32 + j*8 + qid*2;
        const float2 bj = *(const float2*)(bias + col);
        #pragma unroll
        for (int i = 0; i < 2; i++) {
            const int row = row0 + wm*32 + i*16 + grp;
            *(float2*)(C + (size_t)row*DM + col)     = make_float2(acc[i][j][0]+bj.x, acc[i][j][1]+bj.y);
            *(float2*)(C + (size_t)(row+8)*DM + col) = make_float2(acc[i][j][2]+bj.x, acc[i][j][3]+bj.y);
        }
    }
}

// --------- pipelined tensor-core fused attention ---------
#define RSTR 130
#define S0OFF 32768u
#define S1OFF 65536u
#define ROFF  98304
#define RSLOT 66560
#define A_SMEM 231424

__device__ __forceinline__ void stage_rows_async(
    uint32_t sb, uint32_t so, int tid,
    const __nv_bfloat16* hp, const __nv_bfloat16* lp)
{
    #pragma unroll
    for (int r = 0; r < 4; r++) {
        int idx = tid + r*256, row = idx >> 3, c = idx & 7;
        uint32_t off = so + row*128 + ((c ^ (row & 7)) << 4);
        cpa16(sb + off,         (const char*)hp + idx*16);
        cpa16(sb + off + 16384, (const char*)lp + idx*16);
    }
}
__device__ __forceinline__ void stage_vt_async(
    uint32_t sb, uint32_t so, int tid, const __half* hp, int k0)
{
    #pragma unroll
    for (int r = 0; r < 4; r++) {
        int idx = tid + r*256, d = idx >> 4, c = idx & 15;
        uint32_t off = so + d*256 + ((c ^ (d & 7)) << 4);
        cpa16(sb + off, (const char*)(hp + (size_t)d*SEQ + k0) + c*16);
    }
}

__device__ __forceinline__ void rgemm_band(
    uint32_t sb, uint32_t so, int lane, int wm, int wn, int grp, int qid,
    float* R, const float* __restrict__ vbg)
{
    float rc[4][4][4];
    #pragma unroll
    for (int i = 0; i < 4; i++)
        #pragma unroll
        for (int j = 0; j < 4; j++) { rc[i][j][0]=0;rc[i][j][1]=0;rc[i][j][2]=0;rc[i][j][3]=0; }
    #pragma unroll
    for (int kb = 0; kb < 4; kb++) {
        uint32_t ah[4][4], al[4][4];
        #pragma unroll
        for (int i = 0; i < 4; i++) {
            uint32_t ao = (uint32_t)((wm*64 + i*16 + (lane&15))*128
                         + (((kb*2 + (lane>>4)) ^ (lane&7)) << 4));
            ldsm_x4(ah[i], sb + ao);
            ldsm_x4(al[i], sb + 16384 + ao);
        }
        uint32_t bh2[2][4], bl2[2][4];
        #pragma unroll
        for (int jp = 0; jp < 2; jp++) {
            uint32_t bo = (uint32_t)((wn*32 + jp*16 + (lane&7) + ((lane&16)>>1))*128
                         + (((kb*2 + ((lane&8)>>3)) ^ (lane&7)) << 4));
            ldsm_x4(bh2[jp], sb + so + bo);
            ldsm_x4(bl2[jp], sb + so + 16384 + bo);
        }
        #pragma unroll
        for (int i = 0; i < 4; i++)
            #pragma unroll
            for (int j = 0; j < 4; j++) {
                const int jp = j >> 1, s = (j & 1)*2;
                mma_bf16(rc[i][j], ah[i], bh2[jp][s], bh2[jp][s+1]);
                mma_bf16(rc[i][j], ah[i], bl2[jp][s], bl2[jp][s+1]);
                mma_bf16(rc[i][j], al[i], bh2[jp][s], bh2[jp][s+1]);
            }
    }
    #pragma unroll
    for (int i = 0; i < 4; i++) {
        const int u = wm*64 + i*16 + grp;
        #pragma unroll
        for (int j = 0; j < 4; j++) {
            const int l = wn*32 + j*8 + qid*2;
            float v0 = __ldg(vbg + l), v1 = __ldg(vbg + l + 1);
            *(float2*)&R[u*RSTR + l]     = make_float2(rc[i][j][0]+v0, rc[i][j][1]+v1);
            *(float2*)&R[(u+8)*RSTR + l] = make_float2(rc[i][j][2]+v0, rc[i][j][3]+v1);
        }
    }
}

__global__ __launch_bounds__(256, 1) void attn_mma()
{
    extern __shared__ __align__(16) char sm[];
    float* Rb0 = (float*)(sm + ROFF);
    float* Rb1 = (float*)(sm + ROFF + RSLOT);
    const int tid = threadIdx.x, lane = tid & 31, wid = tid >> 5;
    const int grp = lane >> 2, qid = lane & 3;
    const int q0 = blockIdx.x*128, h = blockIdx.y, b = blockIdx.z, bh = b*NH + h;
    const uint32_t sb = smem_u32(sm);
    const int wm = wid & 1, wn = wid >> 1;
    const int u0w = wid*16, r0 = u0w + grp;
    const int lmin0 = SEQ - q0 - 127;
    const float* vbg = g_vbrel + h*2048;
    const __nv_bfloat16* khB = g_khi + (size_t)bh*SEQ*HD;
    const __nv_bfloat16* klB = g_klo + (size_t)bh*SEQ*HD;
    const __half* vhB = g_vth + (size_t)bh*HD*SEQ;

    {   // Q stage (sync, once)
        const uint4* sh = (const uint4*)(g_qhi + ((size_t)bh*SEQ + q0)*HD);
        const uint4* sl = (const uint4*)(g_qlo + ((size_t)bh*SEQ + q0)*HD);
        #pragma unroll
        for (int r = 0; r < 4; r++) {
            int idx = tid + r*256, row = idx >> 3, c = idx & 7;
            int off = row*128 + ((c ^ (row & 7)) << 4);
            *(uint4*)(sm + off) = sh[idx];
            *(uint4*)(sm + 16384 + off) = sl[idx];
        }
    }
    float O[8][4];
    #pragma unroll
    for (int j = 0; j < 8; j++) { O[j][0]=0;O[j][1]=0;O[j][2]=0;O[j][3]=0; }
    float mr0 = -INFINITY, mr1 = -INFINITY, lr0 = 0.f, lr1 = 0.f;

    // prologue: bands 0,1 R-GEMMs; K(0) prefetch
    stage_rows_async(sb, S0OFF, tid, g_poshi + (size_t)lmin0*HD, g_poslo + (size_t)lmin0*HD);
    CP_COMMIT(); CP_WAIT0(); __syncthreads();

    stage_rows_async(sb, S1OFF, tid, g_poshi + (size_t)(lmin0+128)*HD, g_poslo + (size_t)(lmin0+128)*HD);
    CP_COMMIT();
    rgemm_band(sb, S0OFF, lane, wm, wn, grp, qid, Rb0, vbg + lmin0);
    CP_WAIT0(); __syncthreads();

    stage_rows_async(sb, S0OFF, tid, khB, klB);
    CP_COMMIT();
    rgemm_band(sb, S1OFF, lane, wm, wn, grp, qid, Rb1, vbg + lmin0 + 128);
    CP_WAIT0(); __syncthreads();

    for (int kt = 0; kt < 8; kt++) {
        const int k0 = kt*128;
        const uint32_t kOff = (kt & 1) ? S1OFF : S0OFF;
        const uint32_t vOff = (kt & 1) ? S0OFF : S1OFF;

        if (kt > 0) {
            stage_rows_async(sb, kOff, tid, khB + (size_t)k0*HD, klB + (size_t)k0*HD);
            CP_COMMIT();
            rgemm_band(sb, vOff, lane, wm, wn, grp, qid,
                       ((kt+1) & 1) ? Rb1 : Rb0, vbg + lmin0 + 128*(kt+1));
            CP_WAIT0(); __syncthreads();
        }

        stage_vt_async(sb, vOff, tid, vhB, k0);
        CP_COMMIT();

        float aq[16][4];
        #pragma unroll
        for (int j = 0; j < 16; j++) { aq[j][0]=0;aq[j][1]=0;aq[j][2]=0;aq[j][3]=0; }
        #pragma unroll
        for (int kb = 0; kb < 4; kb++) {
            uint32_t ah[4], al[4];
            uint32_t ao = (uint32_t)((u0w + (lane&15))*128
                         + (((kb*2 + (lane>>4)) ^ (lane&7)) << 4));
            ldsm_x4(ah, sb + ao);
            ldsm_x4(al, sb + 16384 + ao);
            #pragma unroll
            for (int jp = 0; jp < 8; jp++) {
                uint32_t bh4[4], bl4[4];
                uint32_t bo = (uint32_t)((jp*16 + (lane&7) + ((lane&16)>>1))*128
                             + (((kb*2 + ((lane&8)>>3)) ^ (lane&7)) << 4));
                ldsm_x4(bh4, sb + kOff + bo);
                ldsm_x4(bl4, sb + kOff + 16384 + bo);
                #pragma unroll
                for (int jj = 0; jj < 2; jj++) {
                    const int j = jp*2 + jj, s = jj*2;
                    mma_bf16(aq[j], ah, bh4[s], bh4[s+1]);
                    mma_bf16(aq[j], ah, bl4[s], bl4[s+1]);
                    mma_bf16(aq[j], al, bh4[s], bh4[s+1]);
                }
            }
        }

        const float* RA  = (kt & 1) ? Rb1 : Rb0;
        const float* RBf = (kt & 1) ? Rb0 : Rb1;
        float m0 = -INFINITY, m1 = -INFINITY;
        #pragma unroll
        for (int j = 0; j < 16; j++) {
            const int w = j*8 + qid*2;
            const int ma = 127 + w - r0, mb = ma - 8;
            aq[j][0] += (ma < 128)   ? RA[r0*RSTR + ma]         : RBf[r0*RSTR + ma - 128];
            aq[j][1] += (ma+1 < 128) ? RA[r0*RSTR + ma + 1]     : RBf[r0*RSTR + ma - 127];
            aq[j][2] += (mb < 128)   ? RA[(r0+8)*RSTR + mb]     : RBf[(r0+8)*RSTR + mb - 128];
            aq[j][3] += (mb+1 < 128) ? RA[(r0+8)*RSTR + mb + 1] : RBf[(r0+8)*RSTR + mb - 127];
            m0 = fmaxf(m0, fmaxf(aq[j][0], aq[j][1]));
            m1 = fmaxf(m1, fmaxf(aq[j][2], aq[j][3]));
        }
        m0 = fmaxf(m0, __shfl_xor_sync(~0u, m0, 1));
        m0 = fmaxf(m0, __shfl_xor_sync(~0u, m0, 2));
        m1 = fmaxf(m1, __shfl_xor_sync(~0u, m1, 1));
        m1 = fmaxf(m1, __shfl_xor_sync(~0u, m1, 2));
        const float mn0 = fmaxf(mr0, m0), mn1 = fmaxf(mr1, m1);
        const float scl0 = __expf(mr0 - mn0), scl1 = __expf(mr1 - mn1);
        mr0 = mn0; mr1 = mn1;

        uint32_t phi[8][4];
        float s0 = 0.f, s1 = 0.f;
        #pragma unroll
        for (int j = 0; j < 16; j++) {
            float p0 = __expf(aq[j][0]-mn0), p1 = __expf(aq[j][1]-mn0);
            float p2 = __expf(aq[j][2]-mn1), p3 = __expf(aq[j][3]-mn1);
            s0 += p0 + p1; s1 += p2 + p3;
            const int kk = j >> 1, bs = (j & 1)*2;
            __half2 hA = __floats2half2_rn(p0, p1);
            __half2 hB = __floats2half2_rn(p2, p3);
            phi[kk][bs]   = *(uint32_t*)&hA;
            phi[kk][bs+1] = *(uint32_t*)&hB;
        }
        s0 += __shfl_xor_sync(~0u, s0, 1); s0 += __shfl_xor_sync(~0u, s0, 2);
        s1 += __shfl_xor_sync(~0u, s1, 1); s1 += __shfl_xor_sync(~0u, s1, 2);
        lr0 = lr0*scl0 + s0; lr1 = lr1*scl1 + s1;
        #pragma unroll
        for (int j = 0; j < 8; j++) {
            O[j][0] *= scl0; O[j][1] *= scl0; O[j][2] *= scl1; O[j][3] *= scl1;
        }

        CP_WAIT0(); __syncthreads();

        if (kt < 7) {
            const int l0n = lmin0 + 128*(kt+2);
            stage_rows_async(sb, kOff, tid, g_poshi + (size_t)l0n*HD, g_poslo + (size_t)l0n*HD);
            CP_COMMIT();
        }

        // PV: single-plane fp16 P (1 MMA per tile-step)
        #pragma unroll
        for (int kk = 0; kk < 8; kk++) {
            #pragma unroll
            for (int jp = 0; jp < 4; jp++) {
                uint32_t bh4[4];
                uint32_t bo = (uint32_t)((jp*16 + (lane&7) + ((lane&16)>>1))*256
                             + (((kk*2 + ((lane&8)>>3)) ^ (lane&7)) << 4));
                ldsm_x4(bh4, sb + vOff + bo);
                mma_f16(O[jp*2],   phi[kk], bh4[0], bh4[1]);
                mma_f16(O[jp*2+1], phi[kk], bh4[2], bh4[3]);
            }
        }
        if (kt < 7) CP_WAIT0();
        __syncthreads();
    }

    const float i0 = 1.f/lr0, i1 = 1.f/lr1;
    __half* x0 = g_xh + ((size_t)(b*SEQ + q0 + r0))*DM + h*HD;
    __half* x1 = g_xh + ((size_t)(b*SEQ + q0 + r0 + 8))*DM + h*HD;
    #pragma unroll
    for (int j = 0; j < 8; j++) {
        const int col = j*8 + qid*2;
        __half2 o0 = __floats2half2_rn(O[j][0]*i0, O[j][1]*i0);
        __half2 o1 = __floats2half2_rn(O[j][2]*i1, O[j][3]*i1);
        *(__half2*)(x0 + col) = o0;
        *(__half2*)(x1 + col) = o1;
    }
}

// ---------------------------------------------------------------------------
extern "C" void kernel_launch(void* const* d_in, const int* in_sizes, int n_in,
                              void* d_out, int out_size) {
    const float* query  = (const float*)d_in[0];
    const float* key    = (const float*)d_in[1];
    const float* value  = (const float*)d_in[2];
    const float* Wq     = (const float*)d_in[4];
    const float* bq     = (const float*)d_in[5];
    const float* Wv     = (const float*)d_in[6];
    const float* bv     = (const float*)d_in[7];
    const float* Wo     = (const float*)d_in[8];
    const float* bo     = (const float*)d_in[9];
    const float* v_bias = (const float*)d_in[10];
    float* out = (float*)d_out;

    void *xp;
    cudaGetSymbolAddress(&xp, g_xh);

    cudaFuncSetAttribute(qv_gemm512, cudaFuncAttributeMaxDynamicSharedMemorySize, HG_SMEM);
    cudaFuncSetAttribute(o_gemm512, cudaFuncAttributeMaxDynamicSharedMemorySize, HG_SMEM);
    cudaFuncSetAttribute(attn_mma, cudaFuncAttributeMaxDynamicSharedMemorySize, A_SMEM);

    dim3 qvgrid(DM/128, (NB*SEQ)/128, 3);   // z=0 Q, z=1 V, z=2 prep
    qv_gemm512<<<qvgrid, 512, HG_SMEM>>>(query, value, key, Wq, Wv, bq, bv, v_bias);

    dim3 agrid(SEQ/128, NH, NB);
    attn_mma<<<agrid, 256, A_SMEM>>>();

    dim3 ogrid(DM/128, (NB*SEQ)/128);
    o_gemm512<<<ogrid, 512, HG_SMEM>>>((const __half*)xp, Wo, bo, out);
}

// round 12
// speedup vs baseline: 2.8822x; 1.0267x over previous
#include <cuda_runtime.h>
#include <cuda_bf16.h>
#include <cuda_fp16.h>
#include <math.h>
#include <stdint.h>

#define SEQ 1024
#define DM  1024
#define NH  16
#define HD  64
#define NB  2
#define GK  1024

__device__ __half g_xh[NB*SEQ*DM];
__device__ float g_vbrel[NH*2*SEQ + 32];
__device__ __nv_bfloat16 g_qhi[NB*NH*SEQ*HD], g_qlo[NB*NH*SEQ*HD];
__device__ __nv_bfloat16 g_khi[NB*NH*SEQ*HD], g_klo[NB*NH*SEQ*HD];
__device__ __half g_vth[NB*NH*HD*SEQ];
__device__ __nv_bfloat16 g_poshi[(2*SEQ+1)*HD], g_poslo[(2*SEQ+1)*HD];
// pre-split GEMM operands
__device__ __nv_bfloat16 g_qryhi[NB*SEQ*GK], g_qrylo[NB*SEQ*GK];
__device__ __half        g_valh[NB*SEQ*GK];
__device__ __nv_bfloat16 g_wqhi[DM*GK], g_wqlo[DM*GK];
__device__ __half        g_wvhi[DM*GK], g_wvlo[DM*GK];
__device__ __half        g_wohi[DM*GK], g_wolo[DM*GK];

__device__ __forceinline__ uint32_t smem_u32(const void* p) {
    uint32_t a;
    asm("{ .reg .u64 t; cvta.to.shared.u64 t, %1; cvt.u32.u64 %0, t; }" : "=r"(a) : "l"(p));
    return a;
}
__device__ __forceinline__ void ldsm_x4(uint32_t (&r)[4], uint32_t addr) {
    asm volatile("ldmatrix.sync.aligned.m8n8.x4.shared.b16 {%0,%1,%2,%3}, [%4];"
        : "=r"(r[0]), "=r"(r[1]), "=r"(r[2]), "=r"(r[3]) : "r"(addr));
}
__device__ __forceinline__ void mma_bf16(float (&d)[4], const uint32_t (&a)[4],
                                         uint32_t b0, uint32_t b1) {
    asm volatile("mma.sync.aligned.m16n8k16.row.col.f32.bf16.bf16.f32 "
        "{%0,%1,%2,%3}, {%4,%5,%6,%7}, {%8,%9}, {%0,%1,%2,%3};"
        : "+f"(d[0]), "+f"(d[1]), "+f"(d[2]), "+f"(d[3])
        : "r"(a[0]), "r"(a[1]), "r"(a[2]), "r"(a[3]), "r"(b0), "r"(b1));
}
__device__ __forceinline__ void mma_f16(float (&d)[4], const uint32_t (&a)[4],
                                        uint32_t b0, uint32_t b1) {
    asm volatile("mma.sync.aligned.m16n8k16.row.col.f32.f16.f16.f32 "
        "{%0,%1,%2,%3}, {%4,%5,%6,%7}, {%8,%9}, {%0,%1,%2,%3};"
        : "+f"(d[0]), "+f"(d[1]), "+f"(d[2]), "+f"(d[3])
        : "r"(a[0]), "r"(a[1]), "r"(a[2]), "r"(a[3]), "r"(b0), "r"(b1));
}
__device__ __forceinline__ void cpa16(uint32_t dst, const void* src) {
    asm volatile("cp.async.cg.shared.global [%0], [%1], 16;" :: "r"(dst), "l"(src));
}
#define CP_COMMIT() asm volatile("cp.async.commit_group;" ::: "memory")
#define CP_WAIT0()  asm volatile("cp.async.wait_group 0;" ::: "memory")

__device__ __forceinline__ void split_sts(float4 v, char* hi, char* lo) {
    __nv_bfloat162 h01 = __floats2bfloat162_rn(v.x, v.y);
    __nv_bfloat162 h23 = __floats2bfloat162_rn(v.z, v.w);
    float2 f01 = __bfloat1622float2(h01);
    float2 f23 = __bfloat1622float2(h23);
    __nv_bfloat162 l01 = __floats2bfloat162_rn(v.x - f01.x, v.y - f01.y);
    __nv_bfloat162 l23 = __floats2bfloat162_rn(v.z - f23.x, v.w - f23.y);
    *(uint2*)hi = make_uint2(*(uint32_t*)&h01, *(uint32_t*)&h23);
    *(uint2*)lo = make_uint2(*(uint32_t*)&l01, *(uint32_t*)&l23);
}
__device__ __forceinline__ void split_sts_h(float4 v, char* hi, char* lo) {
    __half2 h01 = __floats2half2_rn(v.x, v.y);
    __half2 h23 = __floats2half2_rn(v.z, v.w);
    float2 f01 = __half22float2(h01);
    float2 f23 = __half22float2(h23);
    __half2 l01 = __floats2half2_rn(v.x - f01.x, v.y - f01.y);
    __half2 l23 = __floats2half2_rn(v.z - f23.x, v.w - f23.y);
    *(uint2*)hi = make_uint2(*(uint32_t*)&h01, *(uint32_t*)&h23);
    *(uint2*)lo = make_uint2(*(uint32_t*)&l01, *(uint32_t*)&l23);
}
__device__ __forceinline__ uint32_t packsplit(float a, float b, uint32_t& lo) {
    __nv_bfloat162 hh = __floats2bfloat162_rn(a, b);
    float2 ff = __bfloat1622float2(hh);
    __nv_bfloat162 ll = __floats2bfloat162_rn(a - ff.x, b - ff.y);
    lo = *(uint32_t*)&ll;
    return *(uint32_t*)&hh;
}
__device__ __forceinline__ void split1(float v, __nv_bfloat16& hi, __nv_bfloat16& lo) {
    hi = __float2bfloat16_rn(v);
    lo = __float2bfloat16_rn(v - __bfloat162float(hi));
}

// ---------------- front prep: pos+vbrel + ALL operand pre-splits ----------------
__global__ __launch_bounds__(512) void front_prep(
    const float* __restrict__ query, const float* __restrict__ keyg,
    const float* __restrict__ value,
    const float* __restrict__ Wq, const float* __restrict__ Wv,
    const float* __restrict__ Wo, const float* __restrict__ vbias)
{
    __shared__ float ps[1024], vbs[1024];
    const int tid = threadIdx.x;
    const int gid = blockIdx.x * 512 + tid;
    const int NT = 256 * 512;

    if (blockIdx.x < 128) {
        const int pid = blockIdx.x;
        for (int i = tid; i < 1024; i += 512) vbs[i] = vbias[i];
        {
            const int li = tid >> 5, j = tid & 31;
            const int l = pid * 16 + li;
            float p = (float)(l - SEQ);
            const double negc = -log(10000.0) / 31.0;
            float ang = p * (float)exp((double)j * negc);
            float s = (float)sin((double)ang), c = (float)cos((double)ang);
            ps[li*64 + j] = s; ps[li*64 + j + 32] = c;
            __nv_bfloat16 hh, ll;
            split1(s, hh, ll); g_poshi[l*64+j] = hh;      g_poslo[l*64+j] = ll;
            split1(c, hh, ll); g_poshi[l*64+j+32] = hh;   g_poslo[l*64+j+32] = ll;
        }
        __syncthreads();
        if (tid < 256) {
            const int li = tid >> 4, h = tid & 15;
            float sum = 0.f;
            #pragma unroll 8
            for (int d = 0; d < 64; d++) sum = fmaf(vbs[h*64+d], ps[li*64+d], sum);
            g_vbrel[h*2048 + pid*16 + li] = sum;
        }
    }

    // query -> bf16 hi/lo flat (524288 f4)
    for (int i = gid; i < 524288; i += NT) {
        float4 v = ((const float4*)query)[i];
        split_sts(v, (char*)g_qryhi + (size_t)i*8, (char*)g_qrylo + (size_t)i*8);
    }
    // key -> (b,h,s,d) bf16 hi/lo
    for (int i = gid; i < 524288; i += NT) {
        float4 v = ((const float4*)keyg)[i];
        int cc = i & 255, ss = (i >> 8) & 1023, bb = i >> 18;
        size_t o = ((size_t)(bb*NH + (cc >> 4))*SEQ + ss)*HD + (cc & 15)*4;
        split_sts(v, (char*)(g_khi + o), (char*)(g_klo + o));
    }
    // value -> fp16 flat
    for (int i = gid; i < 524288; i += NT) {
        float4 v = ((const float4*)value)[i];
        __half2 h0 = __floats2half2_rn(v.x, v.y);
        __half2 h1 = __floats2half2_rn(v.z, v.w);
        *(uint2*)((char*)g_valh + (size_t)i*8) = make_uint2(*(uint32_t*)&h0, *(uint32_t*)&h1);
    }
    // Wq -> bf16 hi/lo; Wv, Wo -> fp16 hi/lo (262144 f4 each)
    for (int i = gid; i < 262144; i += NT) {
        float4 v = ((const float4*)Wq)[i];
        split_sts(v, (char*)g_wqhi + (size_t)i*8, (char*)g_wqlo + (size_t)i*8);
        v = ((const float4*)Wv)[i];
        split_sts_h(v, (char*)g_wvhi + (size_t)i*8, (char*)g_wvlo + (size_t)i*8);
        v = ((const float4*)Wo)[i];
        split_sts_h(v, (char*)g_wohi + (size_t)i*8, (char*)g_wolo + (size_t)i*8);
    }
}

// ---------------- async GEMM cores (all operands pre-split) ----------------
#define TSTRIDE 40
#define TILE_B  (128 * TSTRIDE * 2)
#define BUF_B   (4 * TILE_B)
#define HG_SMEM (2 * BUF_B)
#define BUF_H   (3 * TILE_B)
#define OG_SMEM (2 * BUF_H)

// bf16 3-term: A hi/lo, B hi/lo
__device__ __forceinline__ void gemm3_async(
    const __nv_bfloat16* Ah, const __nv_bfloat16* Al,
    const __nv_bfloat16* Bh, const __nv_bfloat16* Bl,
    uint32_t sbase, int tid, int lane, int wm, int wn, float acc[2][4][4])
{
    const int lr = tid >> 2, lc = (tid & 3) * 8;
    const uint32_t bo = (uint32_t)(lr*TSTRIDE + lc) * 2;
    const int a_r = lane & 15, a_c = (lane >> 4) << 3;
    const int b_r = (lane & 7) + ((lane & 16) >> 1), b_c = lane & 8;

    {
        const size_t o = (size_t)lr*GK + lc;
        cpa16(sbase + bo,            Ah + o);
        cpa16(sbase + TILE_B + bo,   Al + o);
        cpa16(sbase + 2*TILE_B + bo, Bh + o);
        cpa16(sbase + 3*TILE_B + bo, Bl + o);
    }
    CP_COMMIT(); CP_WAIT0(); __syncthreads();

    for (int kt = 0; kt < 32; kt++) {
        if (kt < 31) {
            const size_t o = (size_t)lr*GK + (kt+1)*32 + lc;
            const uint32_t db = sbase + ((kt+1)&1)*BUF_B + bo;
            cpa16(db,            Ah + o);
            cpa16(db + TILE_B,   Al + o);
            cpa16(db + 2*TILE_B, Bh + o);
            cpa16(db + 3*TILE_B, Bl + o);
            CP_COMMIT();
        }
        const uint32_t base = sbase + (kt & 1) * BUF_B;
        #pragma unroll
        for (int kk = 0; kk < 2; kk++) {
            const int koff = kk * 16;
            uint32_t ah[2][4], al[2][4];
            #pragma unroll
            for (int i = 0; i < 2; i++) {
                const uint32_t off = (uint32_t)(((wm*32 + i*16 + a_r)*TSTRIDE + koff + a_c) * 2);
                ldsm_x4(ah[i], base + off);
                ldsm_x4(al[i], base + TILE_B + off);
            }
            uint32_t bh[2][4], bl[2][4];
            #pragma unroll
            for (int p = 0; p < 2; p++) {
                const uint32_t off = (uint32_t)(((wn*32 + p*16 + b_r)*TSTRIDE + koff + b_c) * 2);
                ldsm_x4(bh[p], base + 2*TILE_B + off);
                ldsm_x4(bl[p], base + 3*TILE_B + off);
            }
            #pragma unroll
            for (int i = 0; i < 2; i++)
                #pragma unroll
                for (int j = 0; j < 4; j++) {
                    const int p = j >> 1, s = (j & 1) * 2;
                    mma_bf16(acc[i][j], ah[i], bh[p][s], bh[p][s+1]);
                    mma_bf16(acc[i][j], ah[i], bl[p][s], bl[p][s+1]);
                    mma_bf16(acc[i][j], al[i], bh[p][s], bh[p][s+1]);
                }
        }
        if (kt < 31) { CP_WAIT0(); __syncthreads(); }
    }
}

// fp16 2-term: A single, B hi/lo
__device__ __forceinline__ void gemm2h_async(
    const __half* Ax, const __half* Bh, const __half* Bl,
    uint32_t sbase, int tid, int lane, int wm, int wn, float acc[2][4][4])
{
    const int lr = tid >> 2, lc = (tid & 3) * 8;
    const uint32_t bo = (uint32_t)(lr*TSTRIDE + lc) * 2;
    const int a_r = lane & 15, a_c = (lane >> 4) << 3;
    const int b_r = (lane & 7) + ((lane & 16) >> 1), b_c = lane & 8;

    {
        const size_t o = (size_t)lr*GK + lc;
        cpa16(sbase + bo,            Ax + o);
        cpa16(sbase + TILE_B + bo,   Bh + o);
        cpa16(sbase + 2*TILE_B + bo, Bl + o);
    }
    CP_COMMIT(); CP_WAIT0(); __syncthreads();

    for (int kt = 0; kt < 32; kt++) {
        if (kt < 31) {
            const size_t o = (size_t)lr*GK + (kt+1)*32 + lc;
            const uint32_t db = sbase + ((kt+1)&1)*BUF_H + bo;
            cpa16(db,            Ax + o);
            cpa16(db + TILE_B,   Bh + o);
            cpa16(db + 2*TILE_B, Bl + o);
            CP_COMMIT();
        }
        const uint32_t base = sbase + (kt & 1) * BUF_H;
        #pragma unroll
        for (int kk = 0; kk < 2; kk++) {
            const int koff = kk * 16;
            uint32_t af[2][4];
            #pragma unroll
            for (int i = 0; i < 2; i++) {
                const uint32_t off = (uint32_t)(((wm*32 + i*16 + a_r)*TSTRIDE + koff + a_c) * 2);
                ldsm_x4(af[i], base + off);
            }
            uint32_t bh[2][4], bl[2][4];
            #pragma unroll
            for (int p = 0; p < 2; p++) {
                const uint32_t off = (uint32_t)(((wn*32 + p*16 + b_r)*TSTRIDE + koff + b_c) * 2);
                ldsm_x4(bh[p], base + TILE_B + off);
                ldsm_x4(bl[p], base + 2*TILE_B + off);
            }
            #pragma unroll
            for (int i = 0; i < 2; i++)
                #pragma unroll
                for (int j = 0; j < 4; j++) {
                    const int p = j >> 1, s = (j & 1) * 2;
                    mma_f16(acc[i][j], af[i], bh[p][s], bh[p][s+1]);
                    mma_f16(acc[i][j], af[i], bl[p][s], bl[p][s+1]);
                }
        }
        if (kt < 31) { CP_WAIT0(); __syncthreads(); }
    }
}

// z=0: Q proj; z=1: V proj (transposed fp16 out)
__global__ __launch_bounds__(512) void qv_gemm512(
    const float* __restrict__ bq, const float* __restrict__ bv)
{
    extern __shared__ __align__(16) char smraw[];
    const int tid = threadIdx.x, lane = tid & 31, wid = tid >> 5;
    const int wm = wid & 3, wn = wid >> 2;
    const int row0 = blockIdx.y * 128, col0 = blockIdx.x * 128;
    const int z = blockIdx.z;

    float acc[2][4][4];
    #pragma unroll
    for (int i = 0; i < 2; i++)
        #pragma unroll
        for (int j = 0; j < 4; j++)
            #pragma unroll
            for (int c = 0; c < 4; c++) acc[i][j][c] = 0.f;

    const int grp = lane >> 2, qid = lane & 3;
    const uint32_t sb = smem_u32(smraw);

    if (z == 0) {
        gemm3_async(g_qryhi + (size_t)row0*GK, g_qrylo + (size_t)row0*GK,
                    g_wqhi + (size_t)col0*GK,  g_wqlo + (size_t)col0*GK,
                    sb, tid, lane, wm, wn, acc);
        #pragma unroll
        for (int j = 0; j < 4; j++) {
            const int col = col0 + wn*32 + j*8 + qid*2;
            const float2 bj = *(const float2*)(bq + col);
            const int h = col >> 6, d = col & 63;
            #pragma unroll
            for (int i = 0; i < 2; i++) {
                const int row = row0 + wm*32 + i*16 + grp;
                const int b = row >> 10, s = row & 1023;
                size_t o = (((size_t)(b*NH + h))*SEQ + s)*HD + d;
                uint32_t lo0, lo1;
                uint32_t hi0 = packsplit(acc[i][j][0]+bj.x, acc[i][j][1]+bj.y, lo0);
                uint32_t hi1 = packsplit(acc[i][j][2]+bj.x, acc[i][j][3]+bj.y, lo1);
                *(uint32_t*)(g_qhi + o) = hi0;        *(uint32_t*)(g_qlo + o) = lo0;
                *(uint32_t*)(g_qhi + o + 8*HD) = hi1; *(uint32_t*)(g_qlo + o + 8*HD) = lo1;
            }
        }
    } else {
        gemm2h_async(g_valh + (size_t)row0*GK,
                     g_wvhi + (size_t)col0*GK, g_wvlo + (size_t)col0*GK,
                     sb, tid, lane, wm, wn, acc);
        #pragma unroll
        for (int j = 0; j < 4; j++) {
            const int col = col0 + wn*32 + j*8 + qid*2;
            const float2 bj = *(const float2*)(bv + col);
            const int h = col >> 6, d = col & 63;
            #pragma unroll
            for (int i = 0; i < 2; i++) {
                const int row = row0 + wm*32 + i*16 + grp;
                const int b = row >> 10, s = row & 1023;
                size_t o = (((size_t)(b*NH + h))*HD + d)*SEQ + s;
                g_vth[o]        = __float2half_rn(acc[i][j][0]+bj.x);
                g_vth[o+SEQ]    = __float2half_rn(acc[i][j][1]+bj.y);
                g_vth[o+8]      = __float2half_rn(acc[i][j][2]+bj.x);
                g_vth[o+SEQ+8]  = __float2half_rn(acc[i][j][3]+bj.y);
            }
        }
    }
}

__global__ __launch_bounds__(512) void o_gemm512(
    const float* __restrict__ bias, float* __restrict__ C)
{
    extern __shared__ __align__(16) char smraw[];
    const int tid = threadIdx.x, lane = tid & 31, wid = tid >> 5;
    const int wm = wid & 3, wn = wid >> 2;
    const int row0 = blockIdx.y * 128, col0 = blockIdx.x * 128;

    float acc[2][4][4];
    #pragma unroll
    for (int i = 0; i < 2; i++)
        #pragma unroll
        for (int j = 0; j < 4; j++)
            #pragma unroll
            for (int c = 0; c < 4; c++) acc[i][j][c] = 0.f;

    gemm2h_async(g_xh + (size_t)row0*GK,
                 g_wohi + (size_t)col0*GK, g_wolo + (size_t)col0*GK,
                 smem_u32(smraw), tid, lane, wm, wn, acc);

    const int grp = lane >> 2, qid = lane & 3;
    #pragma unroll
    for (int j = 0; j < 4; j++) {
        const int col = col0 + wn*32 + j*8 + qid*2;
        const float2 bj = *(const float2*)(bias + col);
        #pragma unroll
        for (int i = 0; i < 2; i++) {
            const int row = row0 + wm*32 + i*16 + grp;
            *(float2*)(C + (size_t)row*DM + col)     = make_float2(acc[i][j][0]+bj.x, acc[i][j][1]+bj.y);
            *(float2*)(C + (size_t)(row+8)*DM + col) = make_float2(acc[i][j][2]+bj.x, acc[i][j][3]+bj.y);
        }
    }
}

// --------- pipelined tensor-core fused attention (reordered overlap) ---------
#define RSTR 130
#define S0OFF 32768u
#define S1OFF 65536u
#define ROFF  98304
#define RSLOT 66560
#define A_SMEM 231424

__device__ __forceinline__ void stage_rows_async(
    uint32_t sb, uint32_t so, int tid,
    const __nv_bfloat16* hp, const __nv_bfloat16* lp)
{
    #pragma unroll
    for (int r = 0; r < 4; r++) {
        int idx = tid + r*256, row = idx >> 3, c = idx & 7;
        uint32_t off = so + row*128 + ((c ^ (row & 7)) << 4);
        cpa16(sb + off,         (const char*)hp + idx*16);
        cpa16(sb + off + 16384, (const char*)lp + idx*16);
    }
}
__device__ __forceinline__ void stage_vt_async(
    uint32_t sb, uint32_t so, int tid, const __half* hp, int k0)
{
    #pragma unroll
    for (int r = 0; r < 4; r++) {
        int idx = tid + r*256, d = idx >> 4, c = idx & 15;
        uint32_t off = so + d*256 + ((c ^ (d & 7)) << 4);
        cpa16(sb + off, (const char*)(hp + (size_t)d*SEQ + k0) + c*16);
    }
}

__device__ __forceinline__ void rgemm_band(
    uint32_t sb, uint32_t so, int lane, int wm, int wn, int grp, int qid,
    float* R, const float* __restrict__ vbg)
{
    float rc[4][4][4];
    #pragma unroll
    for (int i = 0; i < 4; i++)
        #pragma unroll
        for (int j = 0; j < 4; j++) { rc[i][j][0]=0;rc[i][j][1]=0;rc[i][j][2]=0;rc[i][j][3]=0; }
    #pragma unroll
    for (int kb = 0; kb < 4; kb++) {
        uint32_t ah[4][4], al[4][4];
        #pragma unroll
        for (int i = 0; i < 4; i++) {
            uint32_t ao = (uint32_t)((wm*64 + i*16 + (lane&15))*128
                         + (((kb*2 + (lane>>4)) ^ (lane&7)) << 4));
            ldsm_x4(ah[i], sb + ao);
            ldsm_x4(al[i], sb + 16384 + ao);
        }
        uint32_t bh2[2][4], bl2[2][4];
        #pragma unroll
        for (int jp = 0; jp < 2; jp++) {
            uint32_t bo = (uint32_t)((wn*32 + jp*16 + (lane&7) + ((lane&16)>>1))*128
                         + (((kb*2 + ((lane&8)>>3)) ^ (lane&7)) << 4));
            ldsm_x4(bh2[jp], sb + so + bo);
            ldsm_x4(bl2[jp], sb + so + 16384 + bo);
        }
        #pragma unroll
        for (int i = 0; i < 4; i++)
            #pragma unroll
            for (int j = 0; j < 4; j++) {
                const int jp = j >> 1, s = (j & 1)*2;
                mma_bf16(rc[i][j], ah[i], bh2[jp][s], bh2[jp][s+1]);
                mma_bf16(rc[i][j], ah[i], bl2[jp][s], bl2[jp][s+1]);
                mma_bf16(rc[i][j], al[i], bh2[jp][s], bh2[jp][s+1]);
            }
    }
    #pragma unroll
    for (int i = 0; i < 4; i++) {
        const int u = wm*64 + i*16 + grp;
        #pragma unroll
        for (int j = 0; j < 4; j++) {
            const int l = wn*32 + j*8 + qid*2;
            float v0 = __ldg(vbg + l), v1 = __ldg(vbg + l + 1);
            *(float2*)&R[u*RSTR + l]     = make_float2(rc[i][j][0]+v0, rc[i][j][1]+v1);
            *(float2*)&R[(u+8)*RSTR + l] = make_float2(rc[i][j][2]+v0, rc[i][j][3]+v1);
        }
    }
}

__global__ __launch_bounds__(256, 1) void attn_mma()
{
    extern __shared__ __align__(16) char sm[];
    float* Rb0 = (float*)(sm + ROFF);
    float* Rb1 = (float*)(sm + ROFF + RSLOT);
    const int tid = threadIdx.x, lane = tid & 31, wid = tid >> 5;
    const int grp = lane >> 2, qid = lane & 3;
    const int q0 = blockIdx.x*128, h = blockIdx.y, b = blockIdx.z, bh = b*NH + h;
    const uint32_t sb = smem_u32(sm);
    const int wm = wid & 1, wn = wid >> 1;
    const int u0w = wid*16, r0 = u0w + grp;
    const int lmin0 = SEQ - q0 - 127;
    const float* vbg = g_vbrel + h*2048;
    const __nv_bfloat16* khB = g_khi + (size_t)bh*SEQ*HD;
    const __nv_bfloat16* klB = g_klo + (size_t)bh*SEQ*HD;
    const __half* vhB = g_vth + (size_t)bh*HD*SEQ;

    {   // Q stage (sync, once)
        const uint4* sh = (const uint4*)(g_qhi + ((size_t)bh*SEQ + q0)*HD);
        const uint4* sl = (const uint4*)(g_qlo + ((size_t)bh*SEQ + q0)*HD);
        #pragma unroll
        for (int r = 0; r < 4; r++) {
            int idx = tid + r*256, row = idx >> 3, c = idx & 7;
            int off = row*128 + ((c ^ (row & 7)) << 4);
            *(uint4*)(sm + off) = sh[idx];
            *(uint4*)(sm + 16384 + off) = sl[idx];
        }
    }
    float O[8][4];
    #pragma unroll
    for (int j = 0; j < 8; j++) { O[j][0]=0;O[j][1]=0;O[j][2]=0;O[j][3]=0; }
    float mr0 = -INFINITY, mr1 = -INFINITY, lr0 = 0.f, lr1 = 0.f;

    // prologue: bands 0,1 R-GEMMs; K(0) prefetch
    stage_rows_async(sb, S0OFF, tid, g_poshi + (size_t)lmin0*HD, g_poslo + (size_t)lmin0*HD);
    CP_COMMIT(); CP_WAIT0(); __syncthreads();

    stage_rows_async(sb, S1OFF, tid, g_poshi + (size_t)(lmin0+128)*HD, g_poslo + (size_t)(lmin0+128)*HD);
    CP_COMMIT();
    rgemm_band(sb, S0OFF, lane, wm, wn, grp, qid, Rb0, vbg + lmin0);
    CP_WAIT0(); __syncthreads();

    stage_rows_async(sb, S0OFF, tid, khB, klB);
    CP_COMMIT();
    rgemm_band(sb, S1OFF, lane, wm, wn, grp, qid, Rb1, vbg + lmin0 + 128);
    CP_WAIT0(); __syncthreads();

    for (int kt = 0; kt < 8; kt++) {
        const int k0 = kt*128;
        const uint32_t kOff = (kt & 1) ? S1OFF : S0OFF;
        const uint32_t vOff = (kt & 1) ? S0OFF : S1OFF;

        if (kt > 0) {
            stage_rows_async(sb, kOff, tid, khB + (size_t)k0*HD, klB + (size_t)k0*HD);
            CP_COMMIT();
            rgemm_band(sb, vOff, lane, wm, wn, grp, qid,
                       ((kt+1) & 1) ? Rb1 : Rb0, vbg + lmin0 + 128*(kt+1));
            CP_WAIT0(); __syncthreads();
        }

        stage_vt_async(sb, vOff, tid, vhB, k0);
        CP_COMMIT();

        float aq[16][4];
        #pragma unroll
        for (int j = 0; j < 16; j++) { aq[j][0]=0;aq[j][1]=0;aq[j][2]=0;aq[j][3]=0; }
        #pragma unroll
        for (int kb = 0; kb < 4; kb++) {
            uint32_t ah[4], al[4];
            uint32_t ao = (uint32_t)((u0w + (lane&15))*128
                         + (((kb*2 + (lane>>4)) ^ (lane&7)) << 4));
            ldsm_x4(ah, sb + ao);
            ldsm_x4(al, sb + 16384 + ao);
            #pragma unroll
            for (int jp = 0; jp < 8; jp++) {
                uint32_t bh4[4], bl4[4];
                uint32_t bo = (uint32_t)((jp*16 + (lane&7) + ((lane&16)>>1))*128
                             + (((kb*2 + ((lane&8)>>3)) ^ (lane&7)) << 4));
                ldsm_x4(bh4, sb + kOff + bo);
                ldsm_x4(bl4, sb + kOff + 16384 + bo);
                #pragma unroll
                for (int jj = 0; jj < 2; jj++) {
                    const int j = jp*2 + jj, s = jj*2;
                    mma_bf16(aq[j], ah, bh4[s], bh4[s+1]);
                    mma_bf16(aq[j], ah, bl4[s], bl4[s+1]);
                    mma_bf16(aq[j], al, bh4[s], bh4[s+1]);
                }
            }
        }

        // V ready + kOff free: sync HERE, then stage pos(kt+2), then softmax->PV unbarriered
        CP_WAIT0(); __syncthreads();
        if (kt < 7) {
            const int l0n = lmin0 + 128*(kt+2);
            stage_rows_async(sb, kOff, tid, g_poshi + (size_t)l0n*HD, g_poslo + (size_t)l0n*HD);
            CP_COMMIT();
        }

        const float* RA  = (kt & 1) ? Rb1 : Rb0;
        const float* RBf = (kt & 1) ? Rb0 : Rb1;
        float m0 = -INFINITY, m1 = -INFINITY;
        #pragma unroll
        for (int j = 0; j < 16; j++) {
            const int w = j*8 + qid*2;
            const int ma = 127 + w - r0, mb = ma - 8;
            aq[j][0] += (ma < 128)   ? RA[r0*RSTR + ma]         : RBf[r0*RSTR + ma - 128];
            aq[j][1] += (ma+1 < 128) ? RA[r0*RSTR + ma + 1]     : RBf[r0*RSTR + ma - 127];
            aq[j][2] += (mb < 128)   ? RA[(r0+8)*RSTR + mb]     : RBf[(r0+8)*RSTR + mb - 128];
            aq[j][3] += (mb+1 < 128) ? RA[(r0+8)*RSTR + mb + 1] : RBf[(r0+8)*RSTR + mb - 127];
            m0 = fmaxf(m0, fmaxf(aq[j][0], aq[j][1]));
            m1 = fmaxf(m1, fmaxf(aq[j][2], aq[j][3]));
        }
        m0 = fmaxf(m0, __shfl_xor_sync(~0u, m0, 1));
        m0 = fmaxf(m0, __shfl_xor_sync(~0u, m0, 2));
        m1 = fmaxf(m1, __shfl_xor_sync(~0u, m1, 1));
        m1 = fmaxf(m1, __shfl_xor_sync(~0u, m1, 2));
        const float mn0 = fmaxf(mr0, m0), mn1 = fmaxf(mr1, m1);
        const float scl0 = __expf(mr0 - mn0), scl1 = __expf(mr1 - mn1);
        mr0 = mn0; mr1 = mn1;

        uint32_t phi[8][4];
        float s0 = 0.f, s1 = 0.f;
        #pragma unroll
        for (int j = 0; j < 16; j++) {
            float p0 = __expf(aq[j][0]-mn0), p1 = __expf(aq[j][1]-mn0);
            float p2 = __expf(aq[j][2]-mn1), p3 = __expf(aq[j][3]-mn1);
            s0 += p0 + p1; s1 += p2 + p3;
            const int kk = j >> 1, bs = (j & 1)*2;
            __half2 hA = __floats2half2_rn(p0, p1);
            __half2 hB = __floats2half2_rn(p2, p3);
            phi[kk][bs]   = *(uint32_t*)&hA;
            phi[kk][bs+1] = *(uint32_t*)&hB;
        }
        s0 += __shfl_xor_sync(~0u, s0, 1); s0 += __shfl_xor_sync(~0u, s0, 2);
        s1 += __shfl_xor_sync(~0u, s1, 1); s1 += __shfl_xor_sync(~0u, s1, 2);
        lr0 = lr0*scl0 + s0; lr1 = lr1*scl1 + s1;
        #pragma unroll
        for (int j = 0; j < 8; j++) {
            O[j][0] *= scl0; O[j][1] *= scl0; O[j][2] *= scl1; O[j][3] *= scl1;
        }

        // PV immediately (no barrier): warps drift, MUFU overlaps tensor
        #pragma unroll
        for (int kk = 0; kk < 8; kk++) {
            #pragma unroll
            for (int jp = 0; jp < 4; jp++) {
                uint32_t bh4[4];
                uint32_t bo = (uint32_t)((jp*16 + (lane&7) + ((lane&16)>>1))*256
                             + (((kk*2 + ((lane&8)>>3)) ^ (lane&7)) << 4));
                ldsm_x4(bh4, sb + vOff + bo);
                mma_f16(O[jp*2],   phi[kk], bh4[0], bh4[1]);
                mma_f16(O[jp*2+1], phi[kk], bh4[2], bh4[3]);
            }
        }
        if (kt < 7) CP_WAIT0();
        __syncthreads();
    }

    const float i0 = 1.f/lr0, i1 = 1.f/lr1;
    __half* x0 = g_xh + ((size_t)(b*SEQ + q0 + r0))*DM + h*HD;
    __half* x1 = g_xh + ((size_t)(b*SEQ + q0 + r0 + 8))*DM + h*HD;
    #pragma unroll
    for (int j = 0; j < 8; j++) {
        const int col = j*8 + qid*2;
        __half2 o0 = __floats2half2_rn(O[j][0]*i0, O[j][1]*i0);
        __half2 o1 = __floats2half2_rn(O[j][2]*i1, O[j][3]*i1);
        *(__half2*)(x0 + col) = o0;
        *(__half2*)(x1 + col) = o1;
    }
}

// ---------------------------------------------------------------------------
extern "C" void kernel_launch(void* const* d_in, const int* in_sizes, int n_in,
                              void* d_out, int out_size) {
    const float* query  = (const float*)d_in[0];
    const float* key    = (const float*)d_in[1];
    const float* value  = (const float*)d_in[2];
    const float* Wq     = (const float*)d_in[4];
    const float* bq     = (const float*)d_in[5];
    const float* Wv     = (const float*)d_in[6];
    const float* bv     = (const float*)d_in[7];
    const float* Wo     = (const float*)d_in[8];
    const float* bo     = (const float*)d_in[9];
    const float* v_bias = (const float*)d_in[10];
    float* out = (float*)d_out;

    cudaFuncSetAttribute(qv_gemm512, cudaFuncAttributeMaxDynamicSharedMemorySize, HG_SMEM);
    cudaFuncSetAttribute(o_gemm512, cudaFuncAttributeMaxDynamicSharedMemorySize, OG_SMEM);
    cudaFuncSetAttribute(attn_mma, cudaFuncAttributeMaxDynamicSharedMemorySize, A_SMEM);

    front_prep<<<256, 512>>>(query, key, value, Wq, Wv, Wo, v_bias);

    dim3 qvgrid(DM/128, (NB*SEQ)/128, 2);
    qv_gemm512<<<qvgrid, 512, HG_SMEM>>>(bq, bv);

    dim3 agrid(SEQ/128, NH, NB);
    attn_mma<<<agrid, 256, A_SMEM>>>();

    dim3 ogrid(DM/128, (NB*SEQ)/128);
    o_gemm512<<<ogrid, 512, OG_SMEM>>>(bo, out);
}